// round 12
// baseline (speedup 1.0000x reference)
#include <cuda_runtime.h>
#include <cuda_bf16.h>
#include <math.h>
#include <cstdint>

#define Bn   4096
#define Mn   4
#define Hn   1024
#define Rn   10
#define MIDn 512
#define D3n  3072

// ---------------- scratch (__device__ globals: alloc-free) ----------------
__device__ float d_hidgo[3 * Bn * MIDn];
__device__ float d_ggo[3 * Bn];
__device__ float d_a2o[Bn * Hn];
__device__ float d_onew[Bn * 3 * Hn];
__device__ float d_omean[Bn * Hn];
__device__ float d_hidga[Bn * MIDn];
__device__ float d_gavec[Bn];
__device__ float d_o2a[Bn * Hn];
__device__ float d_zbuf[167772160];             // B*M*R*H fp32
__device__ float d_h2[Bn * Hn];
__device__ unsigned char d_mask[Bn * Mn];
__device__ int d_cidx[Mn * Bn];
__device__ int d_ccnt[Mn];
__device__ int d_pvidx[3 * Bn];
__device__ int d_pvcnt;
__device__ int d_aumidx[Bn];
__device__ int d_aumcnt;
// bf16-split operand pairs
__device__ __nv_bfloat16 d_ahi[Mn * Bn * Hn];      // mixed  [m][b][h]
__device__ __nv_bfloat16 d_alo[Mn * Bn * Hn];
__device__ __nv_bfloat16 d_fhi[Mn * Rn * Hn * Hn]; // factors [mr][h][d]
__device__ __nv_bfloat16 d_flo[Mn * Rn * Hn * Hn];
__device__ __nv_bfloat16 d_fgo_hi[3 * Bn * D3n];   // feat gate-others (compact rows)
__device__ __nv_bfloat16 d_fgo_lo[3 * Bn * D3n];
__device__ __nv_bfloat16 d_fga_hi[Bn * D3n];       // feat gate-audio (compact rows)
__device__ __nv_bfloat16 d_fga_lo[Bn * D3n];
__device__ __nv_bfloat16 d_om_hi[Bn * Hn];         // others_mean
__device__ __nv_bfloat16 d_om_lo[Bn * Hn];
__device__ __nv_bfloat16 d_aud_hi[Bn * Hn];        // audio tokens
__device__ __nv_bfloat16 d_aud_lo[Bn * Hn];
__device__ __nv_bfloat16 d_h1_hi[Bn * Hn];         // LN(fused)
__device__ __nv_bfloat16 d_h1_lo[Bn * Hn];
// weight pairs
__device__ __nv_bfloat16 d_w1go_hi[MIDn * D3n];
__device__ __nv_bfloat16 d_w1go_lo[MIDn * D3n];
__device__ __nv_bfloat16 d_w1ga_hi[MIDn * D3n];
__device__ __nv_bfloat16 d_w1ga_lo[MIDn * D3n];
__device__ __nv_bfloat16 d_a2ow_hi[Hn * Hn];
__device__ __nv_bfloat16 d_a2ow_lo[Hn * Hn];
__device__ __nv_bfloat16 d_o2aw_hi[Hn * Hn];
__device__ __nv_bfloat16 d_o2aw_lo[Hn * Hn];
__device__ __nv_bfloat16 d_outw_hi[Hn * Hn];
__device__ __nv_bfloat16 d_outw_lo[Hn * Hn];

// ---------------- generic helpers ----------------
__device__ __forceinline__ float gelu_f(float x) {
    return 0.5f * x * (1.0f + erff(x * 0.70710678118654752f));
}
__device__ __forceinline__ float2 blkSum2(float a, float b) {
    __shared__ float sa[32], sb[32];
    __shared__ float ra, rb;
    int lane = threadIdx.x & 31, w = threadIdx.x >> 5;
#pragma unroll
    for (int o = 16; o > 0; o >>= 1) {
        a += __shfl_xor_sync(0xffffffffu, a, o);
        b += __shfl_xor_sync(0xffffffffu, b, o);
    }
    if (lane == 0) { sa[w] = a; sb[w] = b; }
    __syncthreads();
    if (threadIdx.x == 0) {
        float x = 0.f, y = 0.f;
        int nw = blockDim.x >> 5;
        for (int i = 0; i < nw; i++) { x += sa[i]; y += sb[i]; }
        ra = x; rb = y;
    }
    __syncthreads();
    return make_float2(ra, rb);
}
__device__ __forceinline__ void split2(float v, __nv_bfloat16* hi, __nv_bfloat16* lo, size_t o) {
    __nv_bfloat16 h = __float2bfloat16(v);
    hi[o] = h;
    lo[o] = __float2bfloat16(v - __bfloat162float(h));
}

// ---------------- mma.sync helpers ----------------
__device__ __forceinline__ uint32_t smem_u32(const void* p) {
    uint32_t a;
    asm("{ .reg .u64 t; cvta.to.shared.u64 t, %1; cvt.u32.u64 %0, t; }" : "=r"(a) : "l"(p));
    return a;
}
__device__ __forceinline__ void ldm_x4(uint32_t& r0, uint32_t& r1, uint32_t& r2, uint32_t& r3,
                                       uint32_t addr) {
    asm volatile("ldmatrix.sync.aligned.m8n8.x4.shared.b16 {%0,%1,%2,%3}, [%4];"
                 : "=r"(r0), "=r"(r1), "=r"(r2), "=r"(r3) : "r"(addr));
}
__device__ __forceinline__ void mma_bf16(float* c, const uint32_t* a, const uint32_t* b) {
    asm volatile("mma.sync.aligned.m16n8k16.row.col.f32.bf16.bf16.f32 "
                 "{%0,%1,%2,%3}, {%4,%5,%6,%7}, {%8,%9}, {%0,%1,%2,%3};"
                 : "+f"(c[0]), "+f"(c[1]), "+f"(c[2]), "+f"(c[3])
                 : "r"(a[0]), "r"(a[1]), "r"(a[2]), "r"(a[3]), "r"(b[0]), "r"(b[1]));
}
__device__ __forceinline__ void cp16(uint32_t dst, const void* src) {
    asm volatile("cp.async.cg.shared.global [%0], [%1], 16;" :: "r"(dst), "l"(src));
}
#define CP_COMMIT() asm volatile("cp.async.commit_group;" ::: "memory")
#define CP_WAIT(n)  asm volatile("cp.async.wait_group %0;" :: "n"(n) : "memory")

// ---------------- fused mask sniff + all compactions (6 blocks) ----------------
__global__ void __launch_bounds__(1024) k_mask_compact(const void* raw) {
    __shared__ int ok32s, okfs;
    if (threadIdx.x == 0) { ok32s = 1; okfs = 1; }
    __syncthreads();
    const int* pi = (const int*)raw;
    const float* pf = (const float*)raw;
    const unsigned char* pb = (const unsigned char*)raw;
    int lok32 = 1, lokf = 1;
    for (int i = threadIdx.x; i < 4096; i += 1024) {
        int v = pi[i];
        if (v != 0 && v != 1) lok32 = 0;
        float f = pf[i];
        if (f != 0.0f && f != 1.0f) lokf = 0;
    }
    if (!lok32) ok32s = 0;
    if (!lokf)  okfs = 0;
    __syncthreads();
    const int ok32 = ok32s, okf = okfs;
    auto maskat = [&](int i) -> int {
        if (ok32) return pi[i] != 0;
        if (okf)  return pf[i] != 0.0f;
        return pb[i] != 0;
    };

    const int blk = blockIdx.x;
    if (blk == 0) {
        for (int i = threadIdx.x; i < Bn * Mn; i += 1024)
            d_mask[i] = (unsigned char)maskat(i);
    }

    int* out_idx;
    int* out_cnt;
    int nitems;
    if (blk < 4)      { out_idx = d_cidx + blk * Bn; out_cnt = d_ccnt + blk; nitems = Bn; }
    else if (blk == 4){ out_idx = d_pvidx;           out_cnt = &d_pvcnt;     nitems = 3 * Bn; }
    else              { out_idx = d_aumidx;          out_cnt = &d_aumcnt;    nitems = Bn; }

    __shared__ int warp_off[32];
    __shared__ int chunk_base;
    if (threadIdx.x == 0) chunk_base = 0;
    __syncthreads();
    int lane = threadIdx.x & 31, w = threadIdx.x >> 5;
    for (int c = 0; c < nitems; c += 1024) {
        int i = c + threadIdx.x;
        int v;
        if (blk < 4) {
            v = maskat(i * Mn + blk);
        } else if (blk == 4) {
            int b = i / 3, j = i - 3 * b;
            int oj = (j == 0) ? 0 : (j + 1);
            v = maskat(b * 4 + oj) && maskat(b * 4 + 1);
        } else {
            v = maskat(i * 4 + 1) && (maskat(i * 4) | maskat(i * 4 + 2) | maskat(i * 4 + 3));
        }
        unsigned bal = __ballot_sync(0xffffffffu, v);
        int pre = __popc(bal & ((1u << lane) - 1u));
        if (lane == 31) warp_off[w] = __popc(bal);
        __syncthreads();
        if (threadIdx.x < 32) {
            int val = warp_off[threadIdx.x];
#pragma unroll
            for (int o = 1; o < 32; o <<= 1) {
                int t = __shfl_up_sync(0xffffffffu, val, o);
                if ((int)threadIdx.x >= o) val += t;
            }
            warp_off[threadIdx.x] = val;
        }
        __syncthreads();
        int base = chunk_base + (w ? warp_off[w - 1] : 0) + pre;
        if (v) out_idx[base] = i;
        __syncthreads();
        if (threadIdx.x == 0) chunk_base += warp_off[31];
        __syncthreads();
    }
    if (threadIdx.x == 0) *out_cnt = chunk_base;
}

// ---------------- elementwise split kernels ----------------
// destination arrays selected in DEVICE code (device symbols must not cross
// the host launch boundary as pointer arguments)
__global__ void k_split_sel(const float* __restrict__ src, int sel, int n) {
    int i = blockIdx.x * 256 + threadIdx.x;
    if (i >= n) return;
    __nv_bfloat16 *hi, *lo;
    switch (sel) {
        case 0: hi = d_w1go_hi; lo = d_w1go_lo; break;
        case 1: hi = d_w1ga_hi; lo = d_w1ga_lo; break;
        case 2: hi = d_a2ow_hi; lo = d_a2ow_lo; break;
        case 3: hi = d_o2aw_hi; lo = d_o2aw_lo; break;
        default: hi = d_outw_hi; lo = d_outw_lo; break;
    }
    split2(src[i], hi, lo, i);
}
__global__ void k_tok_split(const float* __restrict__ tokens) {
    int i = blockIdx.x * 256 + threadIdx.x;     // over Bn*Hn
    int b = i >> 10, h = i & 1023;
    split2(tokens[(size_t)b * Mn * Hn + Hn + h], d_aud_hi, d_aud_lo, i);
}

// ---------------- generic bf16-pair GEMM: block 128x256, 16 warps, 3-stage ----------------
#define PPAD   40
#define PABUF  (128 * PPAD * 2)
#define PBBUF  (256 * PPAD * 2)
#define PSTAGE (2 * PABUF + 2 * PBBUF)        // 61440
#define PSM_TOTAL (3 * PSTAGE)                // 184320

__device__ __forceinline__ void gemm_pair_body(
    const __nv_bfloat16* __restrict__ Ahi, const __nv_bfloat16* __restrict__ Alo, int lda,
    const __nv_bfloat16* __restrict__ Bhi, const __nv_bfloat16* __restrict__ Blo, int ldb,
    float* __restrict__ C, int ldc, const float* __restrict__ bias, int K, int act,
    int cnt, const int* __restrict__ gidx)
{
    extern __shared__ char psm[];
    const uint32_t sbase = smem_u32(psm);
    const int tid = threadIdx.x;
    const int wid = tid >> 5, lane = tid & 31;
    const int n0 = blockIdx.x * 256, m0 = blockIdx.y * 128;
    if (m0 >= cnt) return;

    const int lrow = tid >> 2;
    const int lseg = tid & 3;

    int grow = m0 + lrow;
    if (grow >= cnt) grow = cnt - 1;
    const int arow = gidx ? gidx[grow] : grow;

    const __nv_bfloat16* pAhi = Ahi + (size_t)arow * lda + lseg * 8;
    const __nv_bfloat16* pAlo = Alo + (size_t)arow * lda + lseg * 8;
    const __nv_bfloat16* pB0hi = Bhi + (size_t)(n0 + lrow) * ldb + lseg * 8;
    const __nv_bfloat16* pB0lo = Blo + (size_t)(n0 + lrow) * ldb + lseg * 8;
    const __nv_bfloat16* pB1hi = pB0hi + (size_t)128 * ldb;
    const __nv_bfloat16* pB1lo = pB0lo + (size_t)128 * ldb;

    auto load_stage = [&](int st, int k0) {
        uint32_t base = sbase + st * PSTAGE;
        uint32_t offA = lrow * (PPAD * 2) + lseg * 16;
        cp16(base + offA, pAhi + k0);
        cp16(base + PABUF + offA, pAlo + k0);
        uint32_t offB1 = (lrow + 128) * (PPAD * 2) + lseg * 16;
        cp16(base + 2 * PABUF + offA, pB0hi + k0);
        cp16(base + 2 * PABUF + offB1, pB1hi + k0);
        cp16(base + 2 * PABUF + PBBUF + offA, pB0lo + k0);
        cp16(base + 2 * PABUF + PBBUF + offB1, pB1lo + k0);
    };

    float acc[2][8][4];
#pragma unroll
    for (int i = 0; i < 2; i++)
#pragma unroll
        for (int j = 0; j < 8; j++)
#pragma unroll
            for (int c = 0; c < 4; c++) acc[i][j][c] = 0.0f;

    const int wm0 = (wid >> 2) * 32;
    const int wn0 = (wid & 3) * 64;
    const int a_r = lane & 15;
    const int a_c8 = (lane >> 4) << 3;
    const int b_r = (lane & 7) + ((lane >> 4) << 3);
    const int b_c8 = ((lane >> 3) & 1) << 3;

    load_stage(0, 0);
    CP_COMMIT();
    load_stage(1, 32);
    CP_COMMIT();

    const int NIT = K / 32;
    for (int it = 0; it < NIT; it++) {
        CP_WAIT(1);
        __syncthreads();
        if (it + 2 < NIT) {
            load_stage((it + 2) % 3, (it + 2) * 32);
            CP_COMMIT();
        }
        const int st = it % 3;
        const uint32_t sAh = sbase + st * PSTAGE;
        const uint32_t sAl = sAh + PABUF;
        const uint32_t sBh = sAh + 2 * PABUF;
        const uint32_t sBl = sBh + PBBUF;

#pragma unroll
        for (int ks = 0; ks < 2; ks++) {
            const int kb = ks * 16;
            uint32_t aH[2][4], aL[2][4];
#pragma unroll
            for (int mi = 0; mi < 2; mi++) {
                uint32_t off = (uint32_t)(wm0 + mi * 16 + a_r) * (PPAD * 2) + (kb + a_c8) * 2;
                ldm_x4(aH[mi][0], aH[mi][1], aH[mi][2], aH[mi][3], sAh + off);
                ldm_x4(aL[mi][0], aL[mi][1], aL[mi][2], aL[mi][3], sAl + off);
            }
#pragma unroll
            for (int hf = 0; hf < 2; hf++) {
                uint32_t bH[4][2], bL[4][2];
#pragma unroll
                for (int p = 0; p < 2; p++) {
                    uint32_t off = (uint32_t)(wn0 + hf * 32 + p * 16 + b_r) * (PPAD * 2) + (kb + b_c8) * 2;
                    ldm_x4(bH[2 * p][0], bH[2 * p][1], bH[2 * p + 1][0], bH[2 * p + 1][1], sBh + off);
                    ldm_x4(bL[2 * p][0], bL[2 * p][1], bL[2 * p + 1][0], bL[2 * p + 1][1], sBl + off);
                }
#pragma unroll
                for (int mi = 0; mi < 2; mi++)
#pragma unroll
                    for (int ni = 0; ni < 4; ni++)
                        mma_bf16(acc[mi][hf * 4 + ni], aH[mi], bH[ni]);
#pragma unroll
                for (int mi = 0; mi < 2; mi++)
#pragma unroll
                    for (int ni = 0; ni < 4; ni++)
                        mma_bf16(acc[mi][hf * 4 + ni], aH[mi], bL[ni]);
#pragma unroll
                for (int mi = 0; mi < 2; mi++)
#pragma unroll
                    for (int ni = 0; ni < 4; ni++)
                        mma_bf16(acc[mi][hf * 4 + ni], aL[mi], bH[ni]);
            }
        }
    }

#pragma unroll
    for (int mi = 0; mi < 2; mi++) {
#pragma unroll
        for (int half = 0; half < 2; half++) {
            int r = m0 + wm0 + mi * 16 + (lane >> 2) + half * 8;
            if (r >= cnt) continue;
            int crow = gidx ? gidx[r] : r;
            float* dd = C + (size_t)crow * ldc + n0;
#pragma unroll
            for (int ni = 0; ni < 8; ni++) {
                int cc = wn0 + ni * 8 + (lane & 3) * 2;
                float v0 = acc[mi][ni][half * 2 + 0] + (bias ? bias[n0 + cc] : 0.f);
                float v1 = acc[mi][ni][half * 2 + 1] + (bias ? bias[n0 + cc + 1] : 0.f);
                if (act) { v0 = gelu_f(v0); v1 = gelu_f(v1); }
                *(float2*)(dd + cc) = make_float2(v0, v1);
            }
        }
    }
}

__global__ void __launch_bounds__(512) k_p_hidgo(const float* b1) {
    gemm_pair_body(d_fgo_hi, d_fgo_lo, D3n, d_w1go_hi, d_w1go_lo, D3n,
                   d_hidgo, MIDn, b1, D3n, 1, d_pvcnt, nullptr);
}
__global__ void __launch_bounds__(512) k_p_hidga(const float* b1) {
    gemm_pair_body(d_fga_hi, d_fga_lo, D3n, d_w1ga_hi, d_w1ga_lo, D3n,
                   d_hidga, MIDn, b1, D3n, 1, d_aumcnt, nullptr);
}
__global__ void __launch_bounds__(512) k_p_a2o() {
    gemm_pair_body(d_aud_hi, d_aud_lo, Hn, d_a2ow_hi, d_a2ow_lo, Hn,
                   d_a2o, Hn, (const float*)0, Hn, 0, d_aumcnt, d_aumidx);
}
__global__ void __launch_bounds__(512) k_p_o2a() {
    gemm_pair_body(d_om_hi, d_om_lo, Hn, d_o2aw_hi, d_o2aw_lo, Hn,
                   d_o2a, Hn, (const float*)0, Hn, 0, d_aumcnt, d_aumidx);
}
__global__ void __launch_bounds__(512) k_p_out(const float* bb) {
    gemm_pair_body(d_h1_hi, d_h1_lo, Hn, d_outw_hi, d_outw_lo, Hn,
                   d_h2, Hn, bb, Hn, 1, Bn, nullptr);
}

// ---------------- factor split/transpose prep ----------------
__global__ void __launch_bounds__(256) k_prep_factors(const float* __restrict__ f) {
    __shared__ float t[32][33];
    int mr = blockIdx.z;
    int d0 = blockIdx.x * 32, h0 = blockIdx.y * 32;
    int tx = threadIdx.x, ty = threadIdx.y;
#pragma unroll
    for (int i = ty; i < 32; i += 8)
        t[i][tx] = f[((size_t)mr * 1025 + 1 + d0 + i) * Hn + h0 + tx];
    __syncthreads();
#pragma unroll
    for (int i = ty; i < 32; i += 8) {
        float x = t[tx][i];
        size_t o = ((size_t)mr * Hn + h0 + i) * Hn + d0 + tx;
        split2(x, d_fhi, d_flo, o);
    }
}

// ---------------- LMF GEMM: block 128x256, 16 warps, warp 32x64, 3-stage ----------------
#define ZKC     32
#define ZPAD    40
#define ZABUF   (128 * ZPAD * 2)
#define ZBBUF   (256 * ZPAD * 2)
#define ZSTAGE  (2 * ZABUF + 2 * ZBBUF)
#define ZSM_TOTAL (3 * ZSTAGE)

__global__ void __launch_bounds__(512) k_gemm_z_mma() {
    extern __shared__ char zsm[];
    const uint32_t sbase = smem_u32(zsm);
    const int tid = threadIdx.x;
    const int wid = tid >> 5, lane = tid & 31;
    const int h0 = blockIdx.x * 256;
    const int b0 = blockIdx.y * 128;
    const int mr = blockIdx.z;
    const int m = mr / Rn;
    const int cnt = d_ccnt[m];
    if (b0 >= cnt) return;

    const int lrow = tid >> 2;
    const int lseg = tid & 3;

    int grow = b0 + lrow;
    int gidx = d_cidx[m * Bn + (grow < cnt ? grow : cnt - 1)];

    const __nv_bfloat16* pAhi = d_ahi + ((size_t)m * Bn + gidx) * Hn + lseg * 8;
    const __nv_bfloat16* pAlo = d_alo + ((size_t)m * Bn + gidx) * Hn + lseg * 8;
    const __nv_bfloat16* pB0hi = d_fhi + ((size_t)mr * Hn + h0 + lrow) * Hn + lseg * 8;
    const __nv_bfloat16* pB0lo = d_flo + ((size_t)mr * Hn + h0 + lrow) * Hn + lseg * 8;
    const __nv_bfloat16* pB1hi = pB0hi + (size_t)128 * Hn;
    const __nv_bfloat16* pB1lo = pB0lo + (size_t)128 * Hn;

    auto load_stage = [&](int st, int k0) {
        uint32_t base = sbase + st * ZSTAGE;
        uint32_t offA = lrow * (ZPAD * 2) + lseg * 16;
        cp16(base + offA, pAhi + k0);
        cp16(base + ZABUF + offA, pAlo + k0);
        uint32_t offB1 = (lrow + 128) * (ZPAD * 2) + lseg * 16;
        cp16(base + 2 * ZABUF + offA, pB0hi + k0);
        cp16(base + 2 * ZABUF + offB1, pB1hi + k0);
        cp16(base + 2 * ZABUF + ZBBUF + offA, pB0lo + k0);
        cp16(base + 2 * ZABUF + ZBBUF + offB1, pB1lo + k0);
    };

    float acc[2][8][4];
#pragma unroll
    for (int i = 0; i < 2; i++)
#pragma unroll
        for (int j = 0; j < 8; j++)
#pragma unroll
            for (int c = 0; c < 4; c++) acc[i][j][c] = 0.0f;

    const int wm0 = (wid >> 2) * 32;
    const int wn0 = (wid & 3) * 64;
    const int a_r = lane & 15;
    const int a_c8 = (lane >> 4) << 3;
    const int b_r = (lane & 7) + ((lane >> 4) << 3);
    const int b_c8 = ((lane >> 3) & 1) << 3;

    load_stage(0, 0);
    CP_COMMIT();
    load_stage(1, ZKC);
    CP_COMMIT();

    const int NIT = Hn / ZKC;
    for (int it = 0; it < NIT; it++) {
        CP_WAIT(1);
        __syncthreads();
        if (it + 2 < NIT) {
            load_stage((it + 2) % 3, (it + 2) * ZKC);
            CP_COMMIT();
        }
        const int st = it % 3;
        const uint32_t sAh = sbase + st * ZSTAGE;
        const uint32_t sAl = sAh + ZABUF;
        const uint32_t sBh = sAh + 2 * ZABUF;
        const uint32_t sBl = sBh + ZBBUF;

#pragma unroll
        for (int ks = 0; ks < 2; ks++) {
            const int kb = ks * 16;
            uint32_t aH[2][4], aL[2][4];
#pragma unroll
            for (int mi = 0; mi < 2; mi++) {
                uint32_t off = (uint32_t)(wm0 + mi * 16 + a_r) * (ZPAD * 2) + (kb + a_c8) * 2;
                ldm_x4(aH[mi][0], aH[mi][1], aH[mi][2], aH[mi][3], sAh + off);
                ldm_x4(aL[mi][0], aL[mi][1], aL[mi][2], aL[mi][3], sAl + off);
            }
#pragma unroll
            for (int hf = 0; hf < 2; hf++) {
                uint32_t bH[4][2], bL[4][2];
#pragma unroll
                for (int p = 0; p < 2; p++) {
                    uint32_t off = (uint32_t)(wn0 + hf * 32 + p * 16 + b_r) * (ZPAD * 2) + (kb + b_c8) * 2;
                    ldm_x4(bH[2 * p][0], bH[2 * p][1], bH[2 * p + 1][0], bH[2 * p + 1][1], sBh + off);
                    ldm_x4(bL[2 * p][0], bL[2 * p][1], bL[2 * p + 1][0], bL[2 * p + 1][1], sBl + off);
                }
#pragma unroll
                for (int mi = 0; mi < 2; mi++)
#pragma unroll
                    for (int ni = 0; ni < 4; ni++)
                        mma_bf16(acc[mi][hf * 4 + ni], aH[mi], bH[ni]);
#pragma unroll
                for (int mi = 0; mi < 2; mi++)
#pragma unroll
                    for (int ni = 0; ni < 4; ni++)
                        mma_bf16(acc[mi][hf * 4 + ni], aH[mi], bL[ni]);
#pragma unroll
                for (int mi = 0; mi < 2; mi++)
#pragma unroll
                    for (int ni = 0; ni < 4; ni++)
                        mma_bf16(acc[mi][hf * 4 + ni], aL[mi], bH[ni]);
            }
        }
    }

#pragma unroll
    for (int mi = 0; mi < 2; mi++) {
#pragma unroll
        for (int half = 0; half < 2; half++) {
            int r = b0 + wm0 + mi * 16 + (lane >> 2) + half * 8;
            if (r >= cnt) continue;
            int br = d_cidx[m * Bn + r];
            float* dd = d_zbuf + ((size_t)br * (Mn * Rn) + mr) * Hn + h0;
#pragma unroll
            for (int ni = 0; ni < 8; ni++) {
                int cc = wn0 + ni * 8 + (lane & 3) * 2;
                *(float2*)(dd + cc) = make_float2(acc[mi][ni][half * 2 + 0], acc[mi][ni][half * 2 + 1]);
            }
        }
    }
}

// ---------------- feat builders (compacted, write bf16 pairs) ----------------
__global__ void k_feat_go(const float* tokens, const float* lnw, const float* lnb) {
    int i = blockIdx.x;
    if (i >= d_pvcnt) return;
    int row = d_pvidx[i];
    int b = row / 3, j = row - 3 * b;
    int oj = (j == 0) ? 0 : (j + 1);
    const float* tok = tokens + (size_t)b * Mn * Hn;
    __shared__ float sf[D3n];
    float s = 0.f, q = 0.f;
    for (int k = threadIdx.x; k < Hn; k += blockDim.x) {
        float t = tok[oj * Hn + k];
        float sv = tok[Hn + k];
        float dv = fabsf(t - sv);
        sf[k] = t; sf[Hn + k] = sv; sf[2 * Hn + k] = dv;
        s += t + sv + dv; q += t * t + sv * sv + dv * dv;
    }
    float2 rr = blkSum2(s, q);
    float mean = rr.x / D3n;
    float var = rr.y / D3n - mean * mean;
    float rstd = rsqrtf(var + 1e-5f);
    size_t ob = (size_t)i * D3n;
    for (int k = threadIdx.x; k < D3n; k += blockDim.x)
        split2((sf[k] - mean) * rstd * lnw[k] + lnb[k], d_fgo_hi, d_fgo_lo, ob + k);
}

__global__ void k_feat_ga(const float* tokens, const float* lnw, const float* lnb) {
    int i = blockIdx.x;
    if (i >= d_aumcnt) return;
    int b = d_aumidx[i];
    const float* tok = tokens + (size_t)b * Mn * Hn;
    __shared__ float sf[D3n];
    float s = 0.f, q = 0.f;
    for (int k = threadIdx.x; k < Hn; k += blockDim.x) {
        float t = tok[Hn + k];
        float sv = d_omean[(size_t)b * Hn + k];
        float dv = fabsf(t - sv);
        sf[k] = t; sf[Hn + k] = sv; sf[2 * Hn + k] = dv;
        s += t + sv + dv; q += t * t + sv * sv + dv * dv;
    }
    float2 rr = blkSum2(s, q);
    float mean = rr.x / D3n;
    float var = rr.y / D3n - mean * mean;
    float rstd = rsqrtf(var + 1e-5f);
    size_t ob = (size_t)i * D3n;
    for (int k = threadIdx.x; k < D3n; k += blockDim.x)
        split2((sf[k] - mean) * rstd * lnw[k] + lnb[k], d_fga_hi, d_fga_lo, ob + k);
}

// ---------------- gate tails (compacted) ----------------
__global__ void k_gate_go(const float* w2, const float* b2) {
    int i = blockIdx.x;
    if (i >= d_pvcnt) return;
    const float* hr = d_hidgo + (size_t)i * MIDn;
    float v = 0.f;
    for (int k = threadIdx.x; k < MIDn; k += blockDim.x) v += hr[k] * w2[k];
    float2 rr = blkSum2(v, 0.f);
    if (threadIdx.x == 0) d_ggo[d_pvidx[i]] = 1.0f / (1.0f + expf(-(rr.x + b2[0])));
}
__global__ void k_gate_ga(const float* w2, const float* b2) {
    int i = blockIdx.x;
    if (i >= d_aumcnt) return;
    const float* hr = d_hidga + (size_t)i * MIDn;
    float v = 0.f;
    for (int k = threadIdx.x; k < MIDn; k += blockDim.x) v += hr[k] * w2[k];
    float2 rr = blkSum2(v, 0.f);
    if (threadIdx.x == 0) d_gavec[d_aumidx[i]] = 1.0f / (1.0f + expf(-(rr.x + b2[0])));
}

// ---------------- others_new + omean (fused, writes fp32 + omean pair) ----------------
__global__ void k_others_omean(const float* tokens, const float* lnw, const float* lnb) {
    int b = blockIdx.x;
    const float* tok = tokens + (size_t)b * Mn * Hn;
    int ma = d_mask[b * 4 + 1];
    __shared__ float srow[Hn];
    __shared__ float ssum[Hn];
    for (int k = threadIdx.x; k < Hn; k += blockDim.x) ssum[k] = 0.f;
    float denom = 0.f;
    for (int j = 0; j < 3; j++) {
        int oj = (j == 0) ? 0 : (j + 1);
        int moj = d_mask[b * 4 + oj];
        float* o = d_onew + ((size_t)b * 3 + j) * Hn;
        if (moj && ma) {
            float g = d_ggo[b * 3 + j];
            float s = 0.f, q = 0.f;
            for (int k = threadIdx.x; k < Hn; k += blockDim.x) {
                float x = tok[oj * Hn + k] + g * d_a2o[(size_t)b * Hn + k];
                srow[k] = x; s += x; q += x * x;
            }
            float2 rr = blkSum2(s, q);
            float mean = rr.x / Hn;
            float var = rr.y / Hn - mean * mean;
            float rstd = rsqrtf(var + 1e-5f);
            for (int k = threadIdx.x; k < Hn; k += blockDim.x) {
                float v = (srow[k] - mean) * rstd * lnw[k] + lnb[k];
                o[k] = v; ssum[k] += v;
            }
        } else if (moj) {
            for (int k = threadIdx.x; k < Hn; k += blockDim.x) {
                float v = tok[oj * Hn + k];
                o[k] = v; ssum[k] += v;
            }
        } else {
            for (int k = threadIdx.x; k < Hn; k += blockDim.x) o[k] = 0.f;
        }
        if (moj) denom += 1.f;
    }
    denom = fmaxf(denom, 1.f);
    for (int k = threadIdx.x; k < Hn; k += blockDim.x) {
        float v = ssum[k] / denom;
        d_omean[(size_t)b * Hn + k] = v;
        split2(v, d_om_hi, d_om_lo, (size_t)b * Hn + k);
    }
}

// ---------------- mixed assembly (writes bf16 hi/lo splits directly) ----------------
__global__ void k_mixed(const float* tokens, const float* lnw, const float* lnb) {
    int b = blockIdx.x;
    const float* tok = tokens + (size_t)b * Mn * Hn;
    int m0 = d_mask[b * 4], m1 = d_mask[b * 4 + 1], m2 = d_mask[b * 4 + 2], m3 = d_mask[b * 4 + 3];
    int aum = m1 && (m0 || m2 || m3);
    if (aum) {
        __shared__ float sx[Hn];
        float g = d_gavec[b];
        float s = 0.f, q = 0.f;
        for (int k = threadIdx.x; k < Hn; k += blockDim.x) {
            float x = tok[Hn + k] + g * d_o2a[(size_t)b * Hn + k];
            sx[k] = x; s += x; q += x * x;
        }
        float2 rr = blkSum2(s, q);
        float mean = rr.x / Hn;
        float var = rr.y / Hn - mean * mean;
        float rstd = rsqrtf(var + 1e-5f);
        for (int k = threadIdx.x; k < Hn; k += blockDim.x)
            split2((sx[k] - mean) * rstd * lnw[k] + lnb[k], d_ahi, d_alo, ((size_t)1 * Bn + b) * Hn + k);
    } else {
        float f = m1 ? 1.0f : 0.0f;
        for (int k = threadIdx.x; k < Hn; k += blockDim.x)
            split2(tok[Hn + k] * f, d_ahi, d_alo, ((size_t)1 * Bn + b) * Hn + k);
    }
    float f0 = m0 ? 1.f : 0.f, f2 = m2 ? 1.f : 0.f, f3 = m3 ? 1.f : 0.f;
    size_t ob = (size_t)b * 3 * Hn;
    for (int k = threadIdx.x; k < Hn; k += blockDim.x) {
        split2(d_onew[ob + k] * f0,          d_ahi, d_alo, ((size_t)0 * Bn + b) * Hn + k);
        split2(d_onew[ob + Hn + k] * f2,     d_ahi, d_alo, ((size_t)2 * Bn + b) * Hn + k);
        split2(d_onew[ob + 2 * Hn + k] * f3, d_ahi, d_alo, ((size_t)3 * Bn + b) * Hn + k);
    }
}

// ---------------- rank product + weighted sum + LN (fused, writes h1 pair) ----------------
__global__ void k_combine_ln(const float* rank_w, const float* lmf_bias,
                             const float* __restrict__ factors,
                             const float* lnw, const float* lnb) {
    int b = blockIdx.x;
    const unsigned char* mk = d_mask + b * 4;
    bool m0 = mk[0], m1 = mk[1], m2 = mk[2], m3 = mk[3];
    __shared__ float sx[Hn];
    float s = 0.f, q = 0.f;
    for (int h = threadIdx.x; h < Hn; h += blockDim.x) {
        const float* zb = d_zbuf + (size_t)b * (Mn * Rn * Hn) + h;
        float acc = 0.f;
#pragma unroll
        for (int r = 0; r < Rn; r++) {
            float p = rank_w[r];
            if (m0) p *= zb[(0 * Rn + r) * Hn] + factors[((size_t)(0 * Rn + r) * 1025) * Hn + h];
            if (m1) p *= zb[(1 * Rn + r) * Hn] + factors[((size_t)(1 * Rn + r) * 1025) * Hn + h];
            if (m2) p *= zb[(2 * Rn + r) * Hn] + factors[((size_t)(2 * Rn + r) * 1025) * Hn + h];
            if (m3) p *= zb[(3 * Rn + r) * Hn] + factors[((size_t)(3 * Rn + r) * 1025) * Hn + h];
            acc += p;
        }
        float v = acc + lmf_bias[h];
        sx[h] = v;
        s += v; q += v * v;
    }
    float2 rr = blkSum2(s, q);
    float mean = rr.x / Hn;
    float var = rr.y / Hn - mean * mean;
    float rstd = rsqrtf(var + 1e-5f);
    for (int h = threadIdx.x; h < Hn; h += blockDim.x)
        split2((sx[h] - mean) * rstd * lnw[h] + lnb[h], d_h1_hi, d_h1_lo, (size_t)b * Hn + h);
}

// ---------------- final LayerNorm ----------------
__global__ void k_ln_out(const float* w, const float* bb, float* out) {
    const float* x = d_h2 + (size_t)blockIdx.x * Hn;
    float* y = out + (size_t)blockIdx.x * Hn;
    float s = 0.f, q = 0.f;
    for (int k = threadIdx.x; k < Hn; k += blockDim.x) { float v = x[k]; s += v; q += v * v; }
    float2 rr = blkSum2(s, q);
    float mean = rr.x / Hn;
    float var = rr.y / Hn - mean * mean;
    float rstd = rsqrtf(var + 1e-5f);
    for (int k = threadIdx.x; k < Hn; k += blockDim.x)
        y[k] = (x[k] - mean) * rstd * w[k] + bb[k];
}

// ---------------- launch ----------------
extern "C" void kernel_launch(void* const* d_in, const int* in_sizes, int n_in,
                              void* d_out, int out_size) {
    const float* tokens   = (const float*)d_in[0];
    const void*  maskraw  = d_in[1];
    const float* ln_go_w  = (const float*)d_in[2];
    const float* ln_go_b  = (const float*)d_in[3];
    const float* go_w1    = (const float*)d_in[4];
    const float* go_b1    = (const float*)d_in[5];
    const float* go_w2    = (const float*)d_in[6];
    const float* go_b2    = (const float*)d_in[7];
    const float* ln_ga_w  = (const float*)d_in[8];
    const float* ln_ga_b  = (const float*)d_in[9];
    const float* ga_w1    = (const float*)d_in[10];
    const float* ga_b1    = (const float*)d_in[11];
    const float* ga_w2    = (const float*)d_in[12];
    const float* ga_b2    = (const float*)d_in[13];
    const float* a2o_w    = (const float*)d_in[14];
    const float* o2a_w    = (const float*)d_in[15];
    const float* ln_o_w   = (const float*)d_in[16];
    const float* ln_o_b   = (const float*)d_in[17];
    const float* ln_a_w   = (const float*)d_in[18];
    const float* ln_a_b   = (const float*)d_in[19];
    const float* factors  = (const float*)d_in[20];
    const float* rank_w   = (const float*)d_in[21];
    const float* lmf_bias = (const float*)d_in[22];
    const float* out_ln1w = (const float*)d_in[23];
    const float* out_ln1b = (const float*)d_in[24];
    const float* out_w    = (const float*)d_in[25];
    const float* out_b    = (const float*)d_in[26];
    const float* out_ln2w = (const float*)d_in[27];
    const float* out_ln2b = (const float*)d_in[28];
    float* out = (float*)d_out;

    static cudaStream_t s1 = nullptr, s2 = nullptr;
    static cudaEvent_t evStart, evPF, evW, evCmp, evA2O, evOM, evO2A;
    if (!s1) {
        cudaFuncSetAttribute(k_gemm_z_mma, cudaFuncAttributeMaxDynamicSharedMemorySize, ZSM_TOTAL);
        cudaFuncSetAttribute(k_p_hidgo, cudaFuncAttributeMaxDynamicSharedMemorySize, PSM_TOTAL);
        cudaFuncSetAttribute(k_p_hidga, cudaFuncAttributeMaxDynamicSharedMemorySize, PSM_TOTAL);
        cudaFuncSetAttribute(k_p_a2o,   cudaFuncAttributeMaxDynamicSharedMemorySize, PSM_TOTAL);
        cudaFuncSetAttribute(k_p_o2a,   cudaFuncAttributeMaxDynamicSharedMemorySize, PSM_TOTAL);
        cudaFuncSetAttribute(k_p_out,   cudaFuncAttributeMaxDynamicSharedMemorySize, PSM_TOTAL);
        cudaStreamCreateWithFlags(&s1, cudaStreamNonBlocking);
        cudaStreamCreateWithFlags(&s2, cudaStreamNonBlocking);
        cudaEventCreateWithFlags(&evStart, cudaEventDisableTiming);
        cudaEventCreateWithFlags(&evPF,    cudaEventDisableTiming);
        cudaEventCreateWithFlags(&evW,     cudaEventDisableTiming);
        cudaEventCreateWithFlags(&evCmp,   cudaEventDisableTiming);
        cudaEventCreateWithFlags(&evA2O,   cudaEventDisableTiming);
        cudaEventCreateWithFlags(&evOM,    cudaEventDisableTiming);
        cudaEventCreateWithFlags(&evO2A,   cudaEventDisableTiming);
    }

    cudaEventRecord(evStart, 0);
    cudaStreamWaitEvent(s1, evStart, 0);
    cudaStreamWaitEvent(s2, evStart, 0);

    // s1: weight splits then factor prep (off critical path)
    k_split_sel<<<(MIDn * D3n + 255) / 256, 256, 0, s1>>>(go_w1, 0, MIDn * D3n);
    k_split_sel<<<(MIDn * D3n + 255) / 256, 256, 0, s1>>>(ga_w1, 1, MIDn * D3n);
    k_split_sel<<<(Hn * Hn + 255) / 256, 256, 0, s1>>>(a2o_w, 2, Hn * Hn);
    k_split_sel<<<(Hn * Hn + 255) / 256, 256, 0, s1>>>(o2a_w, 3, Hn * Hn);
    k_split_sel<<<(Hn * Hn + 255) / 256, 256, 0, s1>>>(out_w, 4, Hn * Hn);
    cudaEventRecord(evW, s1);
    k_prep_factors<<<dim3(32, 32, Mn * Rn), dim3(32, 8), 0, s1>>>(factors);
    cudaEventRecord(evPF, s1);

    // s2: audio token split (depends only on tokens)
    k_tok_split<<<(Bn * Hn) / 256, 256, 0, s2>>>(tokens);

    k_mask_compact<<<6, 1024>>>(maskraw);
    cudaEventRecord(evCmp, 0);

    // s2: a2o after compaction + weight splits
    cudaStreamWaitEvent(s2, evCmp, 0);
    cudaStreamWaitEvent(s2, evW, 0);
    k_p_a2o<<<dim3(Hn / 256, Bn / 128), 512, PSM_TOTAL, s2>>>();
    cudaEventRecord(evA2O, s2);

    k_feat_go<<<3 * Bn, 256>>>(tokens, ln_go_w, ln_go_b);
    cudaStreamWaitEvent(0, evW, 0);
    k_p_hidgo<<<dim3(MIDn / 256, 3 * Bn / 128), 512, PSM_TOTAL>>>(go_b1);
    k_gate_go<<<3 * Bn, 256>>>(go_w2, go_b2);
    cudaStreamWaitEvent(0, evA2O, 0);
    k_others_omean<<<Bn, 256>>>(tokens, ln_o_w, ln_o_b);
    cudaEventRecord(evOM, 0);

    cudaStreamWaitEvent(s2, evOM, 0);
    k_p_o2a<<<dim3(Hn / 256, Bn / 128), 512, PSM_TOTAL, s2>>>();
    cudaEventRecord(evO2A, s2);

    k_feat_ga<<<Bn, 256>>>(tokens, ln_ga_w, ln_ga_b);
    k_p_hidga<<<dim3(MIDn / 256, Bn / 128), 512, PSM_TOTAL>>>(ga_b1);
    k_gate_ga<<<Bn, 256>>>(ga_w2, ga_b2);
    cudaStreamWaitEvent(0, evO2A, 0);
    k_mixed<<<Bn, 256>>>(tokens, ln_a_w, ln_a_b);

    cudaStreamWaitEvent(0, evPF, 0);
    k_gemm_z_mma<<<dim3(Hn / 256, Bn / 128, Mn * Rn), 512, ZSM_TOTAL>>>();
    k_combine_ln<<<Bn, 256>>>(rank_w, lmf_bias, factors, out_ln1w, out_ln1b);
    k_p_out<<<dim3(Hn / 256, Bn / 128), 512, PSM_TOTAL>>>(out_b);
    k_ln_out<<<Bn, 256>>>(out_ln2w, out_ln2b, out);
}

// round 13
// speedup vs baseline: 1.0871x; 1.0871x over previous
#include <cuda_runtime.h>
#include <cuda_bf16.h>
#include <math.h>
#include <cstdint>

#define Bn   4096
#define Mn   4
#define Hn   1024
#define Rn   10
#define MIDn 512
#define D3n  3072

// ---------------- scratch (__device__ globals: alloc-free) ----------------
__device__ float d_featgo[3 * Bn * D3n];
__device__ float d_hidgo[3 * Bn * MIDn];
__device__ float d_ggo[3 * Bn];
__device__ float d_a2o[Bn * Hn];
__device__ float d_onew[Bn * 3 * Hn];
__device__ float d_omean[Bn * Hn];
__device__ float d_featga[Bn * D3n];
__device__ float d_hidga[Bn * MIDn];
__device__ float d_gavec[Bn];
__device__ float d_o2a[Bn * Hn];
__device__ float d_zbuf[167772160];             // B*M*R*H fp32
__device__ float d_h1[Bn * Hn];
__device__ float d_h2[Bn * Hn];
__device__ unsigned char d_mask[Bn * Mn];
__device__ int d_cidx[Mn * Bn];
__device__ int d_ccnt[Mn];
__device__ int d_pvidx[3 * Bn];
__device__ int d_pvcnt;
__device__ int d_aumidx[Bn];
__device__ int d_aumcnt;
__device__ __nv_bfloat16 d_ahi[Mn * Bn * Hn];      // [m][b][h]
__device__ __nv_bfloat16 d_alo[Mn * Bn * Hn];
__device__ __nv_bfloat16 d_fhi[Mn * Rn * Hn * Hn]; // [mr][h][d]
__device__ __nv_bfloat16 d_flo[Mn * Rn * Hn * Hn];

// ---------------- generic helpers ----------------
__device__ __forceinline__ float gelu_f(float x) {
    return 0.5f * x * (1.0f + erff(x * 0.70710678118654752f));
}
__device__ __forceinline__ float2 blkSum2(float a, float b) {
    __shared__ float sa[32], sb[32];
    __shared__ float ra, rb;
    int lane = threadIdx.x & 31, w = threadIdx.x >> 5;
#pragma unroll
    for (int o = 16; o > 0; o >>= 1) {
        a += __shfl_xor_sync(0xffffffffu, a, o);
        b += __shfl_xor_sync(0xffffffffu, b, o);
    }
    if (lane == 0) { sa[w] = a; sb[w] = b; }
    __syncthreads();
    if (threadIdx.x == 0) {
        float x = 0.f, y = 0.f;
        int nw = blockDim.x >> 5;
        for (int i = 0; i < nw; i++) { x += sa[i]; y += sb[i]; }
        ra = x; rb = y;
    }
    __syncthreads();
    return make_float2(ra, rb);
}

// ---------------- mma.sync helpers ----------------
__device__ __forceinline__ uint32_t smem_u32(const void* p) {
    uint32_t a;
    asm("{ .reg .u64 t; cvta.to.shared.u64 t, %1; cvt.u32.u64 %0, t; }" : "=r"(a) : "l"(p));
    return a;
}
__device__ __forceinline__ void ldm_x4(uint32_t& r0, uint32_t& r1, uint32_t& r2, uint32_t& r3,
                                       uint32_t addr) {
    asm volatile("ldmatrix.sync.aligned.m8n8.x4.shared.b16 {%0,%1,%2,%3}, [%4];"
                 : "=r"(r0), "=r"(r1), "=r"(r2), "=r"(r3) : "r"(addr));
}
__device__ __forceinline__ void mma_bf16(float* c, const uint32_t* a, const uint32_t* b) {
    asm volatile("mma.sync.aligned.m16n8k16.row.col.f32.bf16.bf16.f32 "
                 "{%0,%1,%2,%3}, {%4,%5,%6,%7}, {%8,%9}, {%0,%1,%2,%3};"
                 : "+f"(c[0]), "+f"(c[1]), "+f"(c[2]), "+f"(c[3])
                 : "r"(a[0]), "r"(a[1]), "r"(a[2]), "r"(a[3]), "r"(b[0]), "r"(b[1]));
}
__device__ __forceinline__ void cp16(uint32_t dst, const void* src) {
    asm volatile("cp.async.cg.shared.global [%0], [%1], 16;" :: "r"(dst), "l"(src));
}
#define CP_COMMIT() asm volatile("cp.async.commit_group;" ::: "memory")
#define CP_WAIT(n)  asm volatile("cp.async.wait_group %0;" :: "n"(n) : "memory")

__device__ __forceinline__ uint32_t pack_hi_lo(float x, float y, uint32_t& lo) {
    __nv_bfloat16 hx = __float2bfloat16(x);
    __nv_bfloat16 hy = __float2bfloat16(y);
    float lxf = x - __bfloat162float(hx);
    float lyf = y - __bfloat162float(hy);
    __nv_bfloat162 hv = __halves2bfloat162(hx, hy);
    __nv_bfloat162 lv = __halves2bfloat162(__float2bfloat16(lxf), __float2bfloat16(lyf));
    lo = *reinterpret_cast<uint32_t*>(&lv);
    return *reinterpret_cast<uint32_t*>(&hv);
}

// ---------------- fused mask sniff + all compactions (6 blocks) ----------------
__global__ void __launch_bounds__(1024) k_mask_compact(const void* raw) {
    __shared__ int ok32s, okfs;
    if (threadIdx.x == 0) { ok32s = 1; okfs = 1; }
    __syncthreads();
    const int* pi = (const int*)raw;
    const float* pf = (const float*)raw;
    const unsigned char* pb = (const unsigned char*)raw;
    int lok32 = 1, lokf = 1;
    for (int i = threadIdx.x; i < 4096; i += 1024) {
        int v = pi[i];
        if (v != 0 && v != 1) lok32 = 0;
        float f = pf[i];
        if (f != 0.0f && f != 1.0f) lokf = 0;
    }
    if (!lok32) ok32s = 0;
    if (!lokf)  okfs = 0;
    __syncthreads();
    const int ok32 = ok32s, okf = okfs;
    auto maskat = [&](int i) -> int {
        if (ok32) return pi[i] != 0;
        if (okf)  return pf[i] != 0.0f;
        return pb[i] != 0;
    };

    const int blk = blockIdx.x;
    if (blk == 0) {
        for (int i = threadIdx.x; i < Bn * Mn; i += 1024)
            d_mask[i] = (unsigned char)maskat(i);
    }

    int* out_idx;
    int* out_cnt;
    int nitems;
    if (blk < 4)      { out_idx = d_cidx + blk * Bn; out_cnt = d_ccnt + blk; nitems = Bn; }
    else if (blk == 4){ out_idx = d_pvidx;           out_cnt = &d_pvcnt;     nitems = 3 * Bn; }
    else              { out_idx = d_aumidx;          out_cnt = &d_aumcnt;    nitems = Bn; }

    __shared__ int warp_off[32];
    __shared__ int chunk_base;
    if (threadIdx.x == 0) chunk_base = 0;
    __syncthreads();
    int lane = threadIdx.x & 31, w = threadIdx.x >> 5;
    for (int c = 0; c < nitems; c += 1024) {
        int i = c + threadIdx.x;
        int v;
        if (blk < 4) {
            v = maskat(i * Mn + blk);
        } else if (blk == 4) {
            int b = i / 3, j = i - 3 * b;
            int oj = (j == 0) ? 0 : (j + 1);
            v = maskat(b * 4 + oj) && maskat(b * 4 + 1);
        } else {
            v = maskat(i * 4 + 1) && (maskat(i * 4) | maskat(i * 4 + 2) | maskat(i * 4 + 3));
        }
        unsigned bal = __ballot_sync(0xffffffffu, v);
        int pre = __popc(bal & ((1u << lane) - 1u));
        if (lane == 31) warp_off[w] = __popc(bal);
        __syncthreads();
        if (threadIdx.x < 32) {
            int val = warp_off[threadIdx.x];
#pragma unroll
            for (int o = 1; o < 32; o <<= 1) {
                int t = __shfl_up_sync(0xffffffffu, val, o);
                if ((int)threadIdx.x >= o) val += t;
            }
            warp_off[threadIdx.x] = val;
        }
        __syncthreads();
        int base = chunk_base + (w ? warp_off[w - 1] : 0) + pre;
        if (v) out_idx[base] = i;
        __syncthreads();
        if (threadIdx.x == 0) chunk_base += warp_off[31];
        __syncthreads();
    }
    if (threadIdx.x == 0) *out_cnt = chunk_base;
}

// ---------------- generic fp32 -> bf16-split mma GEMM (512 thr, 16 warps) ----------------
#define GPAD   40
#define GBUF   (128 * GPAD * 2)
#define GSTAGE (4 * GBUF)
#define GSM_TOTAL (2 * GSTAGE)

template <int SEL>
__device__ __forceinline__ void gemm_sp_body(
    const float* __restrict__ A, int lda,
    const float* __restrict__ B, int ldb,
    float* __restrict__ C, int ldc,
    const float* __restrict__ bias, int K, int act)
{
    extern __shared__ char gsm[];
    int cnt = 1 << 30;
    const int* ridx = nullptr;
    if (SEL == 1) cnt = d_pvcnt;
    if (SEL == 2) cnt = d_aumcnt;
    if (SEL == 3) { cnt = d_aumcnt; ridx = d_aumidx; }
    const int n0 = blockIdx.x * 128, m0 = blockIdx.y * 128;
    if (SEL != 0 && m0 >= cnt) return;

    const uint32_t sbase = smem_u32(gsm);
    const int tid = threadIdx.x;
    const int wid = tid >> 5, lane = tid & 31;

    const int lrow = tid >> 2, lseg = tid & 3;
    int grow = m0 + lrow;
    if (SEL != 0 && grow >= cnt) grow = cnt - 1;
    const int arow = ridx ? ridx[grow] : grow;
    const float* Aref = A + (size_t)arow * lda + lseg * 8;
    const float* Bref = B + (size_t)(n0 + lrow) * ldb + lseg * 8;

    float4 ra[2], rb[2];
    auto gload = [&](int k0) {
        ra[0] = *(const float4*)(Aref + k0);
        ra[1] = *(const float4*)(Aref + k0 + 4);
        rb[0] = *(const float4*)(Bref + k0);
        rb[1] = *(const float4*)(Bref + k0 + 4);
    };
    auto sstore = [&](int st) {
        char* p = gsm + st * GSTAGE + lrow * (GPAD * 2) + lseg * 16;
        uint32_t l0, l1, l2, l3;
        uint32_t h0 = pack_hi_lo(ra[0].x, ra[0].y, l0);
        uint32_t h1 = pack_hi_lo(ra[0].z, ra[0].w, l1);
        uint32_t h2 = pack_hi_lo(ra[1].x, ra[1].y, l2);
        uint32_t h3 = pack_hi_lo(ra[1].z, ra[1].w, l3);
        *(uint4*)(p + 0 * GBUF) = make_uint4(h0, h1, h2, h3);
        *(uint4*)(p + 1 * GBUF) = make_uint4(l0, l1, l2, l3);
        h0 = pack_hi_lo(rb[0].x, rb[0].y, l0);
        h1 = pack_hi_lo(rb[0].z, rb[0].w, l1);
        h2 = pack_hi_lo(rb[1].x, rb[1].y, l2);
        h3 = pack_hi_lo(rb[1].z, rb[1].w, l3);
        *(uint4*)(p + 2 * GBUF) = make_uint4(h0, h1, h2, h3);
        *(uint4*)(p + 3 * GBUF) = make_uint4(l0, l1, l2, l3);
    };

    float acc[2][4][4];
#pragma unroll
    for (int i = 0; i < 2; i++)
#pragma unroll
        for (int j = 0; j < 4; j++)
#pragma unroll
            for (int c = 0; c < 4; c++) acc[i][j][c] = 0.0f;

    const int wm0 = (wid >> 2) * 32;
    const int wn0 = (wid & 3) * 32;
    const int a_r = lane & 15;
    const int a_c8 = (lane >> 4) << 3;
    const int b_r = (lane & 7) + ((lane >> 4) << 3);
    const int b_c8 = ((lane >> 3) & 1) << 3;

    gload(0);
    const int NIT = K / 32;
    for (int it = 0; it < NIT; it++) {
        const int st = it & 1;
        sstore(st);
        __syncthreads();
        if (it + 1 < NIT) gload((it + 1) * 32);

        const uint32_t sAh = sbase + st * GSTAGE + 0 * GBUF;
        const uint32_t sAl = sbase + st * GSTAGE + 1 * GBUF;
        const uint32_t sBh = sbase + st * GSTAGE + 2 * GBUF;
        const uint32_t sBl = sbase + st * GSTAGE + 3 * GBUF;
#pragma unroll
        for (int ks = 0; ks < 2; ks++) {
            const int kb = ks * 16;
            uint32_t aH[2][4], aL[2][4], bH[4][2], bL[4][2];
#pragma unroll
            for (int mi = 0; mi < 2; mi++) {
                uint32_t off = (uint32_t)(wm0 + mi * 16 + a_r) * (GPAD * 2) + (kb + a_c8) * 2;
                ldm_x4(aH[mi][0], aH[mi][1], aH[mi][2], aH[mi][3], sAh + off);
                ldm_x4(aL[mi][0], aL[mi][1], aL[mi][2], aL[mi][3], sAl + off);
            }
#pragma unroll
            for (int p2 = 0; p2 < 2; p2++) {
                uint32_t off = (uint32_t)(wn0 + p2 * 16 + b_r) * (GPAD * 2) + (kb + b_c8) * 2;
                ldm_x4(bH[2 * p2][0], bH[2 * p2][1], bH[2 * p2 + 1][0], bH[2 * p2 + 1][1], sBh + off);
                ldm_x4(bL[2 * p2][0], bL[2 * p2][1], bL[2 * p2 + 1][0], bL[2 * p2 + 1][1], sBl + off);
            }
#pragma unroll
            for (int mi = 0; mi < 2; mi++)
#pragma unroll
                for (int ni = 0; ni < 4; ni++)
                    mma_bf16(acc[mi][ni], aH[mi], bH[ni]);
#pragma unroll
            for (int mi = 0; mi < 2; mi++)
#pragma unroll
                for (int ni = 0; ni < 4; ni++)
                    mma_bf16(acc[mi][ni], aH[mi], bL[ni]);
#pragma unroll
            for (int mi = 0; mi < 2; mi++)
#pragma unroll
                for (int ni = 0; ni < 4; ni++)
                    mma_bf16(acc[mi][ni], aL[mi], bH[ni]);
        }
        __syncthreads();
    }

#pragma unroll
    for (int mi = 0; mi < 2; mi++) {
#pragma unroll
        for (int half = 0; half < 2; half++) {
            int r = m0 + wm0 + mi * 16 + (lane >> 2) + half * 8;
            if (SEL != 0 && r >= cnt) continue;
            int crow = ridx ? ridx[r] : r;
            float* dd = C + (size_t)crow * ldc;
#pragma unroll
            for (int ni = 0; ni < 4; ni++) {
                int cc = n0 + wn0 + ni * 8 + (lane & 3) * 2;
                float v0 = acc[mi][ni][half * 2 + 0] + (bias ? bias[cc] : 0.f);
                float v1 = acc[mi][ni][half * 2 + 1] + (bias ? bias[cc + 1] : 0.f);
                if (act) { v0 = gelu_f(v0); v1 = gelu_f(v1); }
                *(float2*)(dd + cc) = make_float2(v0, v1);
            }
        }
    }
}

__global__ void __launch_bounds__(512) k_sp_hidgo(const float* w1, const float* b1) {
    gemm_sp_body<1>(d_featgo, D3n, w1, D3n, d_hidgo, MIDn, b1, D3n, 1);
}
__global__ void __launch_bounds__(512) k_sp_hidga(const float* w1, const float* b1) {
    gemm_sp_body<2>(d_featga, D3n, w1, D3n, d_hidga, MIDn, b1, D3n, 1);
}
__global__ void __launch_bounds__(512) k_sp_a2o(const float* tokens, const float* w) {
    gemm_sp_body<3>(tokens + Hn, Mn * Hn, w, Hn, d_a2o, Hn, (const float*)0, Hn, 0);
}
__global__ void __launch_bounds__(512) k_sp_o2a(const float* w) {
    gemm_sp_body<3>(d_omean, Hn, w, Hn, d_o2a, Hn, (const float*)0, Hn, 0);
}
__global__ void __launch_bounds__(512) k_sp_out(const float* w, const float* bb) {
    gemm_sp_body<0>(d_h1, Hn, w, Hn, d_h2, Hn, bb, Hn, 1);
}

// ---------------- factor split/transpose prep ----------------
__global__ void __launch_bounds__(256) k_prep_factors(const float* __restrict__ f) {
    __shared__ float t[32][33];
    int mr = blockIdx.z;
    int d0 = blockIdx.x * 32, h0 = blockIdx.y * 32;
    int tx = threadIdx.x, ty = threadIdx.y;
#pragma unroll
    for (int i = ty; i < 32; i += 8)
        t[i][tx] = f[((size_t)mr * 1025 + 1 + d0 + i) * Hn + h0 + tx];
    __syncthreads();
#pragma unroll
    for (int i = ty; i < 32; i += 8) {
        float x = t[tx][i];
        __nv_bfloat16 hi = __float2bfloat16(x);
        float lo = x - __bfloat162float(hi);
        size_t o = ((size_t)mr * Hn + h0 + i) * Hn + d0 + tx;
        d_fhi[o] = hi;
        d_flo[o] = __float2bfloat16(lo);
    }
}

// ---------------- LMF GEMM: block 128x256, 16 warps, warp 32x64, 3-stage ----------------
#define ZKC     32
#define ZPAD    40
#define ZA_ROWS 128
#define ZB_ROWS 256
#define ZABUF   (ZA_ROWS * ZPAD * 2)          // 10240
#define ZBBUF   (ZB_ROWS * ZPAD * 2)          // 20480
#define ZSTAGE  (2 * ZABUF + 2 * ZBBUF)       // 61440
#define ZSM_TOTAL (3 * ZSTAGE)                // 184320

__global__ void __launch_bounds__(512) k_gemm_z_mma() {
    extern __shared__ char zsm[];
    const uint32_t sbase = smem_u32(zsm);
    const int tid = threadIdx.x;
    const int wid = tid >> 5, lane = tid & 31;
    const int h0 = blockIdx.x * 256;
    const int b0 = blockIdx.y * 128;
    const int mr = blockIdx.z;
    const int m = mr / Rn;
    const int cnt = d_ccnt[m];
    if (b0 >= cnt) return;

    const int lrow = tid >> 2;        // 0..127
    const int lseg = tid & 3;

    int grow = b0 + lrow;
    int gidx = d_cidx[m * Bn + (grow < cnt ? grow : cnt - 1)];

    const __nv_bfloat16* pAhi = d_ahi + ((size_t)m * Bn + gidx) * Hn + lseg * 8;
    const __nv_bfloat16* pAlo = d_alo + ((size_t)m * Bn + gidx) * Hn + lseg * 8;
    const __nv_bfloat16* pB0hi = d_fhi + ((size_t)mr * Hn + h0 + lrow) * Hn + lseg * 8;
    const __nv_bfloat16* pB0lo = d_flo + ((size_t)mr * Hn + h0 + lrow) * Hn + lseg * 8;
    const __nv_bfloat16* pB1hi = pB0hi + (size_t)128 * Hn;
    const __nv_bfloat16* pB1lo = pB0lo + (size_t)128 * Hn;

    auto load_stage = [&](int st, int k0) {
        uint32_t base = sbase + st * ZSTAGE;
        uint32_t offA = lrow * (ZPAD * 2) + lseg * 16;
        cp16(base + offA, pAhi + k0);
        cp16(base + ZABUF + offA, pAlo + k0);
        uint32_t offB0 = lrow * (ZPAD * 2) + lseg * 16;
        uint32_t offB1 = (lrow + 128) * (ZPAD * 2) + lseg * 16;
        cp16(base + 2 * ZABUF + offB0, pB0hi + k0);
        cp16(base + 2 * ZABUF + offB1, pB1hi + k0);
        cp16(base + 2 * ZABUF + ZBBUF + offB0, pB0lo + k0);
        cp16(base + 2 * ZABUF + ZBBUF + offB1, pB1lo + k0);
    };

    float acc[2][8][4];
#pragma unroll
    for (int i = 0; i < 2; i++)
#pragma unroll
        for (int j = 0; j < 8; j++)
#pragma unroll
            for (int c = 0; c < 4; c++) acc[i][j][c] = 0.0f;

    const int wm0 = (wid >> 2) * 32;  // 4 m-groups of 32 rows
    const int wn0 = (wid & 3) * 64;   // 4 n-groups of 64 cols
    const int a_r = lane & 15;
    const int a_c8 = (lane >> 4) << 3;
    const int b_r = (lane & 7) + ((lane >> 4) << 3);
    const int b_c8 = ((lane >> 3) & 1) << 3;

    load_stage(0, 0);
    CP_COMMIT();
    load_stage(1, ZKC);
    CP_COMMIT();

    const int NIT = Hn / ZKC;
    for (int it = 0; it < NIT; it++) {
        CP_WAIT(1);
        __syncthreads();
        if (it + 2 < NIT) {
            load_stage((it + 2) % 3, (it + 2) * ZKC);
            CP_COMMIT();
        }
        const int st = it % 3;
        const uint32_t sAh = sbase + st * ZSTAGE;
        const uint32_t sAl = sAh + ZABUF;
        const uint32_t sBh = sAh + 2 * ZABUF;
        const uint32_t sBl = sBh + ZBBUF;

#pragma unroll
        for (int ks = 0; ks < 2; ks++) {
            const int kb = ks * 16;
            uint32_t aH[2][4], aL[2][4];
#pragma unroll
            for (int mi = 0; mi < 2; mi++) {
                uint32_t off = (uint32_t)(wm0 + mi * 16 + a_r) * (ZPAD * 2) + (kb + a_c8) * 2;
                ldm_x4(aH[mi][0], aH[mi][1], aH[mi][2], aH[mi][3], sAh + off);
                ldm_x4(aL[mi][0], aL[mi][1], aL[mi][2], aL[mi][3], sAl + off);
            }
#pragma unroll
            for (int hf = 0; hf < 2; hf++) {         // two ni-halves of 32 cols
                uint32_t bH[4][2], bL[4][2];
#pragma unroll
                for (int p = 0; p < 2; p++) {
                    uint32_t off = (uint32_t)(wn0 + hf * 32 + p * 16 + b_r) * (ZPAD * 2) + (kb + b_c8) * 2;
                    ldm_x4(bH[2 * p][0], bH[2 * p][1], bH[2 * p + 1][0], bH[2 * p + 1][1], sBh + off);
                    ldm_x4(bL[2 * p][0], bL[2 * p][1], bL[2 * p + 1][0], bL[2 * p + 1][1], sBl + off);
                }
#pragma unroll
                for (int mi = 0; mi < 2; mi++)
#pragma unroll
                    for (int ni = 0; ni < 4; ni++)
                        mma_bf16(acc[mi][hf * 4 + ni], aH[mi], bH[ni]);
#pragma unroll
                for (int mi = 0; mi < 2; mi++)
#pragma unroll
                    for (int ni = 0; ni < 4; ni++)
                        mma_bf16(acc[mi][hf * 4 + ni], aH[mi], bL[ni]);
#pragma unroll
                for (int mi = 0; mi < 2; mi++)
#pragma unroll
                    for (int ni = 0; ni < 4; ni++)
                        mma_bf16(acc[mi][hf * 4 + ni], aL[mi], bH[ni]);
            }
        }
    }

#pragma unroll
    for (int mi = 0; mi < 2; mi++) {
#pragma unroll
        for (int half = 0; half < 2; half++) {
            int r = b0 + wm0 + mi * 16 + (lane >> 2) + half * 8;
            if (r >= cnt) continue;
            int br = d_cidx[m * Bn + r];
            float* dd = d_zbuf + ((size_t)br * (Mn * Rn) + mr) * Hn + h0;
#pragma unroll
            for (int ni = 0; ni < 8; ni++) {
                int cc = wn0 + ni * 8 + (lane & 3) * 2;
                *(float2*)(dd + cc) = make_float2(acc[mi][ni][half * 2 + 0], acc[mi][ni][half * 2 + 1]);
            }
        }
    }
}

// ---------------- feat builders (compacted) ----------------
__global__ void k_feat_go(const float* tokens, const float* lnw, const float* lnb) {
    int i = blockIdx.x;
    if (i >= d_pvcnt) return;
    int row = d_pvidx[i];
    int b = row / 3, j = row - 3 * b;
    int oj = (j == 0) ? 0 : (j + 1);
    const float* tok = tokens + (size_t)b * Mn * Hn;
    __shared__ float sf[D3n];
    float s = 0.f, q = 0.f;
    for (int k = threadIdx.x; k < Hn; k += blockDim.x) {
        float t = tok[oj * Hn + k];
        float sv = tok[Hn + k];
        float dv = fabsf(t - sv);
        sf[k] = t; sf[Hn + k] = sv; sf[2 * Hn + k] = dv;
        s += t + sv + dv; q += t * t + sv * sv + dv * dv;
    }
    float2 rr = blkSum2(s, q);
    float mean = rr.x / D3n;
    float var = rr.y / D3n - mean * mean;
    float rstd = rsqrtf(var + 1e-5f);
    float* o = d_featgo + (size_t)i * D3n;
    for (int k = threadIdx.x; k < D3n; k += blockDim.x)
        o[k] = (sf[k] - mean) * rstd * lnw[k] + lnb[k];
}

__global__ void k_feat_ga(const float* tokens, const float* lnw, const float* lnb) {
    int i = blockIdx.x;
    if (i >= d_aumcnt) return;
    int b = d_aumidx[i];
    const float* tok = tokens + (size_t)b * Mn * Hn;
    __shared__ float sf[D3n];
    float s = 0.f, q = 0.f;
    for (int k = threadIdx.x; k < Hn; k += blockDim.x) {
        float t = tok[Hn + k];
        float sv = d_omean[(size_t)b * Hn + k];
        float dv = fabsf(t - sv);
        sf[k] = t; sf[Hn + k] = sv; sf[2 * Hn + k] = dv;
        s += t + sv + dv; q += t * t + sv * sv + dv * dv;
    }
    float2 rr = blkSum2(s, q);
    float mean = rr.x / D3n;
    float var = rr.y / D3n - mean * mean;
    float rstd = rsqrtf(var + 1e-5f);
    float* o = d_featga + (size_t)i * D3n;
    for (int k = threadIdx.x; k < D3n; k += blockDim.x)
        o[k] = (sf[k] - mean) * rstd * lnw[k] + lnb[k];
}

// ---------------- gate tails (compacted) ----------------
__global__ void k_gate_go(const float* w2, const float* b2) {
    int i = blockIdx.x;
    if (i >= d_pvcnt) return;
    const float* hr = d_hidgo + (size_t)i * MIDn;
    float v = 0.f;
    for (int k = threadIdx.x; k < MIDn; k += blockDim.x) v += hr[k] * w2[k];
    float2 rr = blkSum2(v, 0.f);
    if (threadIdx.x == 0) d_ggo[d_pvidx[i]] = 1.0f / (1.0f + expf(-(rr.x + b2[0])));
}
__global__ void k_gate_ga(const float* w2, const float* b2) {
    int i = blockIdx.x;
    if (i >= d_aumcnt) return;
    const float* hr = d_hidga + (size_t)i * MIDn;
    float v = 0.f;
    for (int k = threadIdx.x; k < MIDn; k += blockDim.x) v += hr[k] * w2[k];
    float2 rr = blkSum2(v, 0.f);
    if (threadIdx.x == 0) d_gavec[d_aumidx[i]] = 1.0f / (1.0f + expf(-(rr.x + b2[0])));
}

// ---------------- others_new + omean (fused, block per b) ----------------
__global__ void k_others_omean(const float* tokens, const float* lnw, const float* lnb) {
    int b = blockIdx.x;
    const float* tok = tokens + (size_t)b * Mn * Hn;
    int ma = d_mask[b * 4 + 1];
    __shared__ float srow[Hn];
    __shared__ float ssum[Hn];
    for (int k = threadIdx.x; k < Hn; k += blockDim.x) ssum[k] = 0.f;
    float denom = 0.f;
    for (int j = 0; j < 3; j++) {
        int oj = (j == 0) ? 0 : (j + 1);
        int moj = d_mask[b * 4 + oj];
        float* o = d_onew + ((size_t)b * 3 + j) * Hn;
        if (moj && ma) {
            float g = d_ggo[b * 3 + j];
            float s = 0.f, q = 0.f;
            for (int k = threadIdx.x; k < Hn; k += blockDim.x) {
                float x = tok[oj * Hn + k] + g * d_a2o[(size_t)b * Hn + k];
                srow[k] = x; s += x; q += x * x;
            }
            float2 rr = blkSum2(s, q);
            float mean = rr.x / Hn;
            float var = rr.y / Hn - mean * mean;
            float rstd = rsqrtf(var + 1e-5f);
            for (int k = threadIdx.x; k < Hn; k += blockDim.x) {
                float v = (srow[k] - mean) * rstd * lnw[k] + lnb[k];
                o[k] = v; ssum[k] += v;
            }
        } else if (moj) {
            for (int k = threadIdx.x; k < Hn; k += blockDim.x) {
                float v = tok[oj * Hn + k];
                o[k] = v; ssum[k] += v;
            }
        } else {
            for (int k = threadIdx.x; k < Hn; k += blockDim.x) o[k] = 0.f;
        }
        if (moj) denom += 1.f;
    }
    denom = fmaxf(denom, 1.f);
    for (int k = threadIdx.x; k < Hn; k += blockDim.x)
        d_omean[(size_t)b * Hn + k] = ssum[k] / denom;
}

// ---------------- mixed assembly (writes bf16 hi/lo splits directly) ----------------
__device__ __forceinline__ void split_store(int m, int b, int k, float v) {
    __nv_bfloat16 hi = __float2bfloat16(v);
    float lo = v - __bfloat162float(hi);
    size_t o = ((size_t)m * Bn + b) * Hn + k;
    d_ahi[o] = hi;
    d_alo[o] = __float2bfloat16(lo);
}

__global__ void k_mixed(const float* tokens, const float* lnw, const float* lnb) {
    int b = blockIdx.x;
    const float* tok = tokens + (size_t)b * Mn * Hn;
    int m0 = d_mask[b * 4], m1 = d_mask[b * 4 + 1], m2 = d_mask[b * 4 + 2], m3 = d_mask[b * 4 + 3];
    int aum = m1 && (m0 || m2 || m3);
    if (aum) {
        __shared__ float sx[Hn];
        float g = d_gavec[b];
        float s = 0.f, q = 0.f;
        for (int k = threadIdx.x; k < Hn; k += blockDim.x) {
            float x = tok[Hn + k] + g * d_o2a[(size_t)b * Hn + k];
            sx[k] = x; s += x; q += x * x;
        }
        float2 rr = blkSum2(s, q);
        float mean = rr.x / Hn;
        float var = rr.y / Hn - mean * mean;
        float rstd = rsqrtf(var + 1e-5f);
        for (int k = threadIdx.x; k < Hn; k += blockDim.x)
            split_store(1, b, k, (sx[k] - mean) * rstd * lnw[k] + lnb[k]);
    } else {
        float f = m1 ? 1.0f : 0.0f;
        for (int k = threadIdx.x; k < Hn; k += blockDim.x)
            split_store(1, b, k, tok[Hn + k] * f);
    }
    float f0 = m0 ? 1.f : 0.f, f2 = m2 ? 1.f : 0.f, f3 = m3 ? 1.f : 0.f;
    size_t ob = (size_t)b * 3 * Hn;
    for (int k = threadIdx.x; k < Hn; k += blockDim.x) {
        split_store(0, b, k, d_onew[ob + k] * f0);
        split_store(2, b, k, d_onew[ob + Hn + k] * f2);
        split_store(3, b, k, d_onew[ob + 2 * Hn + k] * f3);
    }
}

// ---------------- rank product + weighted sum + LN (fused) ----------------
__global__ void k_combine_ln(const float* rank_w, const float* lmf_bias,
                             const float* __restrict__ factors,
                             const float* lnw, const float* lnb) {
    int b = blockIdx.x;
    const unsigned char* mk = d_mask + b * 4;
    bool m0 = mk[0], m1 = mk[1], m2 = mk[2], m3 = mk[3];
    __shared__ float sx[Hn];
    float s = 0.f, q = 0.f;
    for (int h = threadIdx.x; h < Hn; h += blockDim.x) {
        const float* zb = d_zbuf + (size_t)b * (Mn * Rn * Hn) + h;
        float acc = 0.f;
#pragma unroll
        for (int r = 0; r < Rn; r++) {
            float p = rank_w[r];
            if (m0) p *= zb[(0 * Rn + r) * Hn] + factors[((size_t)(0 * Rn + r) * 1025) * Hn + h];
            if (m1) p *= zb[(1 * Rn + r) * Hn] + factors[((size_t)(1 * Rn + r) * 1025) * Hn + h];
            if (m2) p *= zb[(2 * Rn + r) * Hn] + factors[((size_t)(2 * Rn + r) * 1025) * Hn + h];
            if (m3) p *= zb[(3 * Rn + r) * Hn] + factors[((size_t)(3 * Rn + r) * 1025) * Hn + h];
            acc += p;
        }
        float v = acc + lmf_bias[h];
        sx[h] = v;
        s += v; q += v * v;
    }
    float2 rr = blkSum2(s, q);
    float mean = rr.x / Hn;
    float var = rr.y / Hn - mean * mean;
    float rstd = rsqrtf(var + 1e-5f);
    float* o = d_h1 + (size_t)b * Hn;
    for (int h = threadIdx.x; h < Hn; h += blockDim.x)
        o[h] = (sx[h] - mean) * rstd * lnw[h] + lnb[h];
}

// ---------------- final LayerNorm ----------------
__global__ void k_ln_out(const float* w, const float* bb, float* out) {
    const float* x = d_h2 + (size_t)blockIdx.x * Hn;
    float* y = out + (size_t)blockIdx.x * Hn;
    float s = 0.f, q = 0.f;
    for (int k = threadIdx.x; k < Hn; k += blockDim.x) { float v = x[k]; s += v; q += v * v; }
    float2 rr = blkSum2(s, q);
    float mean = rr.x / Hn;
    float var = rr.y / Hn - mean * mean;
    float rstd = rsqrtf(var + 1e-5f);
    for (int k = threadIdx.x; k < Hn; k += blockDim.x)
        y[k] = (x[k] - mean) * rstd * w[k] + bb[k];
}

// ---------------- launch ----------------
extern "C" void kernel_launch(void* const* d_in, const int* in_sizes, int n_in,
                              void* d_out, int out_size) {
    const float* tokens   = (const float*)d_in[0];
    const void*  maskraw  = d_in[1];
    const float* ln_go_w  = (const float*)d_in[2];
    const float* ln_go_b  = (const float*)d_in[3];
    const float* go_w1    = (const float*)d_in[4];
    const float* go_b1    = (const float*)d_in[5];
    const float* go_w2    = (const float*)d_in[6];
    const float* go_b2    = (const float*)d_in[7];
    const float* ln_ga_w  = (const float*)d_in[8];
    const float* ln_ga_b  = (const float*)d_in[9];
    const float* ga_w1    = (const float*)d_in[10];
    const float* ga_b1    = (const float*)d_in[11];
    const float* ga_w2    = (const float*)d_in[12];
    const float* ga_b2    = (const float*)d_in[13];
    const float* a2o_w    = (const float*)d_in[14];
    const float* o2a_w    = (const float*)d_in[15];
    const float* ln_o_w   = (const float*)d_in[16];
    const float* ln_o_b   = (const float*)d_in[17];
    const float* ln_a_w   = (const float*)d_in[18];
    const float* ln_a_b   = (const float*)d_in[19];
    const float* factors  = (const float*)d_in[20];
    const float* rank_w   = (const float*)d_in[21];
    const float* lmf_bias = (const float*)d_in[22];
    const float* out_ln1w = (const float*)d_in[23];
    const float* out_ln1b = (const float*)d_in[24];
    const float* out_w    = (const float*)d_in[25];
    const float* out_b    = (const float*)d_in[26];
    const float* out_ln2w = (const float*)d_in[27];
    const float* out_ln2b = (const float*)d_in[28];
    float* out = (float*)d_out;

    static cudaStream_t s1 = nullptr, s2 = nullptr;
    static cudaEvent_t evStart, evPF, evCmp, evA2O, evOM, evO2A;
    if (!s1) {
        cudaFuncSetAttribute(k_gemm_z_mma, cudaFuncAttributeMaxDynamicSharedMemorySize, ZSM_TOTAL);
        cudaFuncSetAttribute(k_sp_hidgo, cudaFuncAttributeMaxDynamicSharedMemorySize, GSM_TOTAL);
        cudaFuncSetAttribute(k_sp_hidga, cudaFuncAttributeMaxDynamicSharedMemorySize, GSM_TOTAL);
        cudaFuncSetAttribute(k_sp_a2o,   cudaFuncAttributeMaxDynamicSharedMemorySize, GSM_TOTAL);
        cudaFuncSetAttribute(k_sp_o2a,   cudaFuncAttributeMaxDynamicSharedMemorySize, GSM_TOTAL);
        cudaFuncSetAttribute(k_sp_out,   cudaFuncAttributeMaxDynamicSharedMemorySize, GSM_TOTAL);
        cudaStreamCreateWithFlags(&s1, cudaStreamNonBlocking);
        cudaStreamCreateWithFlags(&s2, cudaStreamNonBlocking);
        cudaEventCreateWithFlags(&evStart, cudaEventDisableTiming);
        cudaEventCreateWithFlags(&evPF,    cudaEventDisableTiming);
        cudaEventCreateWithFlags(&evCmp,   cudaEventDisableTiming);
        cudaEventCreateWithFlags(&evA2O,   cudaEventDisableTiming);
        cudaEventCreateWithFlags(&evOM,    cudaEventDisableTiming);
        cudaEventCreateWithFlags(&evO2A,   cudaEventDisableTiming);
    }

    cudaEventRecord(evStart, 0);
    cudaStreamWaitEvent(s1, evStart, 0);
    k_prep_factors<<<dim3(32, 32, Mn * Rn), dim3(32, 8), 0, s1>>>(factors);
    cudaEventRecord(evPF, s1);

    k_mask_compact<<<6, 1024>>>(maskraw);
    cudaEventRecord(evCmp, 0);

    cudaStreamWaitEvent(s2, evCmp, 0);
    k_sp_a2o<<<dim3(Hn / 128, Bn / 128), 512, GSM_TOTAL, s2>>>(tokens, a2o_w);
    cudaEventRecord(evA2O, s2);

    k_feat_go<<<3 * Bn, 256>>>(tokens, ln_go_w, ln_go_b);
    k_sp_hidgo<<<dim3(MIDn / 128, 3 * Bn / 128), 512, GSM_TOTAL>>>(go_w1, go_b1);
    k_gate_go<<<3 * Bn, 256>>>(go_w2, go_b2);
    cudaStreamWaitEvent(0, evA2O, 0);
    k_others_omean<<<Bn, 256>>>(tokens, ln_o_w, ln_o_b);
    cudaEventRecord(evOM, 0);

    cudaStreamWaitEvent(s2, evOM, 0);
    k_sp_o2a<<<dim3(Hn / 128, Bn / 128), 512, GSM_TOTAL, s2>>>(o2a_w);
    cudaEventRecord(evO2A, s2);

    k_feat_ga<<<Bn, 256>>>(tokens, ln_ga_w, ln_ga_b);
    k_sp_hidga<<<dim3(MIDn / 128, Bn / 128), 512, GSM_TOTAL>>>(ga_w1, ga_b1);
    k_gate_ga<<<Bn, 256>>>(ga_w2, ga_b2);
    cudaStreamWaitEvent(0, evO2A, 0);
    k_mixed<<<Bn, 256>>>(tokens, ln_a_w, ln_a_b);

    cudaStreamWaitEvent(0, evPF, 0);
    k_gemm_z_mma<<<dim3(Hn / 256, Bn / 128, Mn * Rn), 512, ZSM_TOTAL>>>();
    k_combine_ln<<<Bn, 256>>>(rank_w, lmf_bias, factors, out_ln1w, out_ln1b);
    k_sp_out<<<dim3(Hn / 128, Bn / 128), 512, GSM_TOTAL>>>(out_w, out_b);
    k_ln_out<<<Bn, 256>>>(out_ln2w, out_ln2b, out);
}

// round 14
// speedup vs baseline: 1.0906x; 1.0033x over previous
#include <cuda_runtime.h>
#include <cuda_bf16.h>
#include <math.h>
#include <cstdint>

#define Bn   4096
#define Mn   4
#define Hn   1024
#define Rn   10
#define MIDn 512
#define D3n  3072

// ---------------- scratch (__device__ globals: alloc-free) ----------------
__device__ float d_featgo[3 * Bn * D3n];
__device__ float d_hidgo[3 * Bn * MIDn];
__device__ float d_ggo[3 * Bn];
__device__ float d_a2o[Bn * Hn];
__device__ float d_omean[Bn * Hn];
__device__ float d_featga[Bn * D3n];
__device__ float d_hidga[Bn * MIDn];
__device__ float d_gavec[Bn];
__device__ float d_o2a[Bn * Hn];
__device__ float d_zbuf[167772160];             // B*M*R*H fp32
__device__ float d_h1[Bn * Hn];
__device__ float d_h2[Bn * Hn];
__device__ unsigned char d_mask[Bn * Mn];
__device__ int d_cidx[Mn * Bn];
__device__ int d_ccnt[Mn];
__device__ int d_pvidx[3 * Bn];
__device__ int d_pvcnt;
__device__ int d_aumidx[Bn];
__device__ int d_aumcnt;
__device__ __nv_bfloat16 d_ahi[Mn * Bn * Hn];      // [m][b][h]
__device__ __nv_bfloat16 d_alo[Mn * Bn * Hn];
__device__ __nv_bfloat16 d_fhi[Mn * Rn * Hn * Hn]; // [mr][h][d]
__device__ __nv_bfloat16 d_flo[Mn * Rn * Hn * Hn];

// ---------------- generic helpers ----------------
__device__ __forceinline__ float gelu_f(float x) {
    return 0.5f * x * (1.0f + erff(x * 0.70710678118654752f));
}
__device__ __forceinline__ float2 blkSum2(float a, float b) {
    __shared__ float sa[32], sb[32];
    __shared__ float ra, rb;
    int lane = threadIdx.x & 31, w = threadIdx.x >> 5;
#pragma unroll
    for (int o = 16; o > 0; o >>= 1) {
        a += __shfl_xor_sync(0xffffffffu, a, o);
        b += __shfl_xor_sync(0xffffffffu, b, o);
    }
    if (lane == 0) { sa[w] = a; sb[w] = b; }
    __syncthreads();
    if (threadIdx.x == 0) {
        float x = 0.f, y = 0.f;
        int nw = blockDim.x >> 5;
        for (int i = 0; i < nw; i++) { x += sa[i]; y += sb[i]; }
        ra = x; rb = y;
    }
    __syncthreads();
    return make_float2(ra, rb);
}
__device__ __forceinline__ void split_store(int m, int b, int k, float v) {
    __nv_bfloat16 hi = __float2bfloat16(v);
    float lo = v - __bfloat162float(hi);
    size_t o = ((size_t)m * Bn + b) * Hn + k;
    d_ahi[o] = hi;
    d_alo[o] = __float2bfloat16(lo);
}

// ---------------- mma.sync helpers ----------------
__device__ __forceinline__ uint32_t smem_u32(const void* p) {
    uint32_t a;
    asm("{ .reg .u64 t; cvta.to.shared.u64 t, %1; cvt.u32.u64 %0, t; }" : "=r"(a) : "l"(p));
    return a;
}
__device__ __forceinline__ void ldm_x4(uint32_t& r0, uint32_t& r1, uint32_t& r2, uint32_t& r3,
                                       uint32_t addr) {
    asm volatile("ldmatrix.sync.aligned.m8n8.x4.shared.b16 {%0,%1,%2,%3}, [%4];"
                 : "=r"(r0), "=r"(r1), "=r"(r2), "=r"(r3) : "r"(addr));
}
__device__ __forceinline__ void mma_bf16(float* c, const uint32_t* a, const uint32_t* b) {
    asm volatile("mma.sync.aligned.m16n8k16.row.col.f32.bf16.bf16.f32 "
                 "{%0,%1,%2,%3}, {%4,%5,%6,%7}, {%8,%9}, {%0,%1,%2,%3};"
                 : "+f"(c[0]), "+f"(c[1]), "+f"(c[2]), "+f"(c[3])
                 : "r"(a[0]), "r"(a[1]), "r"(a[2]), "r"(a[3]), "r"(b[0]), "r"(b[1]));
}
__device__ __forceinline__ void cp16(uint32_t dst, const void* src) {
    asm volatile("cp.async.cg.shared.global [%0], [%1], 16;" :: "r"(dst), "l"(src));
}
#define CP_COMMIT() asm volatile("cp.async.commit_group;" ::: "memory")
#define CP_WAIT(n)  asm volatile("cp.async.wait_group %0;" :: "n"(n) : "memory")

__device__ __forceinline__ uint32_t pack_hi_lo(float x, float y, uint32_t& lo) {
    __nv_bfloat16 hx = __float2bfloat16(x);
    __nv_bfloat16 hy = __float2bfloat16(y);
    float lxf = x - __bfloat162float(hx);
    float lyf = y - __bfloat162float(hy);
    __nv_bfloat162 hv = __halves2bfloat162(hx, hy);
    __nv_bfloat162 lv = __halves2bfloat162(__float2bfloat16(lxf), __float2bfloat16(lyf));
    lo = *reinterpret_cast<uint32_t*>(&lv);
    return *reinterpret_cast<uint32_t*>(&hv);
}

// ---------------- fused mask sniff + all compactions (6 blocks) ----------------
__global__ void __launch_bounds__(1024) k_mask_compact(const void* raw) {
    __shared__ int ok32s, okfs;
    if (threadIdx.x == 0) { ok32s = 1; okfs = 1; }
    __syncthreads();
    const int* pi = (const int*)raw;
    const float* pf = (const float*)raw;
    const unsigned char* pb = (const unsigned char*)raw;
    int lok32 = 1, lokf = 1;
    for (int i = threadIdx.x; i < 4096; i += 1024) {
        int v = pi[i];
        if (v != 0 && v != 1) lok32 = 0;
        float f = pf[i];
        if (f != 0.0f && f != 1.0f) lokf = 0;
    }
    if (!lok32) ok32s = 0;
    if (!lokf)  okfs = 0;
    __syncthreads();
    const int ok32 = ok32s, okf = okfs;
    auto maskat = [&](int i) -> int {
        if (ok32) return pi[i] != 0;
        if (okf)  return pf[i] != 0.0f;
        return pb[i] != 0;
    };

    const int blk = blockIdx.x;
    if (blk == 0) {
        for (int i = threadIdx.x; i < Bn * Mn; i += 1024)
            d_mask[i] = (unsigned char)maskat(i);
    }

    int* out_idx;
    int* out_cnt;
    int nitems;
    if (blk < 4)      { out_idx = d_cidx + blk * Bn; out_cnt = d_ccnt + blk; nitems = Bn; }
    else if (blk == 4){ out_idx = d_pvidx;           out_cnt = &d_pvcnt;     nitems = 3 * Bn; }
    else              { out_idx = d_aumidx;          out_cnt = &d_aumcnt;    nitems = Bn; }

    __shared__ int warp_off[32];
    __shared__ int chunk_base;
    if (threadIdx.x == 0) chunk_base = 0;
    __syncthreads();
    int lane = threadIdx.x & 31, w = threadIdx.x >> 5;
    for (int c = 0; c < nitems; c += 1024) {
        int i = c + threadIdx.x;
        int v;
        if (blk < 4) {
            v = maskat(i * Mn + blk);
        } else if (blk == 4) {
            int b = i / 3, j = i - 3 * b;
            int oj = (j == 0) ? 0 : (j + 1);
            v = maskat(b * 4 + oj) && maskat(b * 4 + 1);
        } else {
            v = maskat(i * 4 + 1) && (maskat(i * 4) | maskat(i * 4 + 2) | maskat(i * 4 + 3));
        }
        unsigned bal = __ballot_sync(0xffffffffu, v);
        int pre = __popc(bal & ((1u << lane) - 1u));
        if (lane == 31) warp_off[w] = __popc(bal);
        __syncthreads();
        if (threadIdx.x < 32) {
            int val = warp_off[threadIdx.x];
#pragma unroll
            for (int o = 1; o < 32; o <<= 1) {
                int t = __shfl_up_sync(0xffffffffu, val, o);
                if ((int)threadIdx.x >= o) val += t;
            }
            warp_off[threadIdx.x] = val;
        }
        __syncthreads();
        int base = chunk_base + (w ? warp_off[w - 1] : 0) + pre;
        if (v) out_idx[base] = i;
        __syncthreads();
        if (threadIdx.x == 0) chunk_base += warp_off[31];
        __syncthreads();
    }
    if (threadIdx.x == 0) *out_cnt = chunk_base;
}

// ---------------- generic fp32 -> bf16-split mma GEMM (512 thr, 16 warps) ----------------
#define GPAD   40
#define GBUF   (128 * GPAD * 2)
#define GSTAGE (4 * GBUF)
#define GSM_TOTAL (2 * GSTAGE)

template <int SEL>
__device__ __forceinline__ void gemm_sp_body(
    const float* __restrict__ A, int lda,
    const float* __restrict__ B, int ldb,
    float* __restrict__ C, int ldc,
    const float* __restrict__ bias, int K, int act)
{
    extern __shared__ char gsm[];
    int cnt = 1 << 30;
    const int* ridx = nullptr;
    if (SEL == 1) cnt = d_pvcnt;
    if (SEL == 2) cnt = d_aumcnt;
    if (SEL == 3) { cnt = d_aumcnt; ridx = d_aumidx; }
    const int n0 = blockIdx.x * 128, m0 = blockIdx.y * 128;
    if (SEL != 0 && m0 >= cnt) return;

    const uint32_t sbase = smem_u32(gsm);
    const int tid = threadIdx.x;
    const int wid = tid >> 5, lane = tid & 31;

    const int lrow = tid >> 2, lseg = tid & 3;
    int grow = m0 + lrow;
    if (SEL != 0 && grow >= cnt) grow = cnt - 1;
    const int arow = ridx ? ridx[grow] : grow;
    const float* Aref = A + (size_t)arow * lda + lseg * 8;
    const float* Bref = B + (size_t)(n0 + lrow) * ldb + lseg * 8;

    float4 ra[2], rb[2];
    auto gload = [&](int k0) {
        ra[0] = *(const float4*)(Aref + k0);
        ra[1] = *(const float4*)(Aref + k0 + 4);
        rb[0] = *(const float4*)(Bref + k0);
        rb[1] = *(const float4*)(Bref + k0 + 4);
    };
    auto sstore = [&](int st) {
        char* p = gsm + st * GSTAGE + lrow * (GPAD * 2) + lseg * 16;
        uint32_t l0, l1, l2, l3;
        uint32_t h0 = pack_hi_lo(ra[0].x, ra[0].y, l0);
        uint32_t h1 = pack_hi_lo(ra[0].z, ra[0].w, l1);
        uint32_t h2 = pack_hi_lo(ra[1].x, ra[1].y, l2);
        uint32_t h3 = pack_hi_lo(ra[1].z, ra[1].w, l3);
        *(uint4*)(p + 0 * GBUF) = make_uint4(h0, h1, h2, h3);
        *(uint4*)(p + 1 * GBUF) = make_uint4(l0, l1, l2, l3);
        h0 = pack_hi_lo(rb[0].x, rb[0].y, l0);
        h1 = pack_hi_lo(rb[0].z, rb[0].w, l1);
        h2 = pack_hi_lo(rb[1].x, rb[1].y, l2);
        h3 = pack_hi_lo(rb[1].z, rb[1].w, l3);
        *(uint4*)(p + 2 * GBUF) = make_uint4(h0, h1, h2, h3);
        *(uint4*)(p + 3 * GBUF) = make_uint4(l0, l1, l2, l3);
    };

    float acc[2][4][4];
#pragma unroll
    for (int i = 0; i < 2; i++)
#pragma unroll
        for (int j = 0; j < 4; j++)
#pragma unroll
            for (int c = 0; c < 4; c++) acc[i][j][c] = 0.0f;

    const int wm0 = (wid >> 2) * 32;
    const int wn0 = (wid & 3) * 32;
    const int a_r = lane & 15;
    const int a_c8 = (lane >> 4) << 3;
    const int b_r = (lane & 7) + ((lane >> 4) << 3);
    const int b_c8 = ((lane >> 3) & 1) << 3;

    gload(0);
    const int NIT = K / 32;
    for (int it = 0; it < NIT; it++) {
        const int st = it & 1;
        sstore(st);
        __syncthreads();
        if (it + 1 < NIT) gload((it + 1) * 32);

        const uint32_t sAh = sbase + st * GSTAGE + 0 * GBUF;
        const uint32_t sAl = sbase + st * GSTAGE + 1 * GBUF;
        const uint32_t sBh = sbase + st * GSTAGE + 2 * GBUF;
        const uint32_t sBl = sbase + st * GSTAGE + 3 * GBUF;
#pragma unroll
        for (int ks = 0; ks < 2; ks++) {
            const int kb = ks * 16;
            uint32_t aH[2][4], aL[2][4], bH[4][2], bL[4][2];
#pragma unroll
            for (int mi = 0; mi < 2; mi++) {
                uint32_t off = (uint32_t)(wm0 + mi * 16 + a_r) * (GPAD * 2) + (kb + a_c8) * 2;
                ldm_x4(aH[mi][0], aH[mi][1], aH[mi][2], aH[mi][3], sAh + off);
                ldm_x4(aL[mi][0], aL[mi][1], aL[mi][2], aL[mi][3], sAl + off);
            }
#pragma unroll
            for (int p2 = 0; p2 < 2; p2++) {
                uint32_t off = (uint32_t)(wn0 + p2 * 16 + b_r) * (GPAD * 2) + (kb + b_c8) * 2;
                ldm_x4(bH[2 * p2][0], bH[2 * p2][1], bH[2 * p2 + 1][0], bH[2 * p2 + 1][1], sBh + off);
                ldm_x4(bL[2 * p2][0], bL[2 * p2][1], bL[2 * p2 + 1][0], bL[2 * p2 + 1][1], sBl + off);
            }
#pragma unroll
            for (int mi = 0; mi < 2; mi++)
#pragma unroll
                for (int ni = 0; ni < 4; ni++)
                    mma_bf16(acc[mi][ni], aH[mi], bH[ni]);
#pragma unroll
            for (int mi = 0; mi < 2; mi++)
#pragma unroll
                for (int ni = 0; ni < 4; ni++)
                    mma_bf16(acc[mi][ni], aH[mi], bL[ni]);
#pragma unroll
            for (int mi = 0; mi < 2; mi++)
#pragma unroll
                for (int ni = 0; ni < 4; ni++)
                    mma_bf16(acc[mi][ni], aL[mi], bH[ni]);
        }
        __syncthreads();
    }

#pragma unroll
    for (int mi = 0; mi < 2; mi++) {
#pragma unroll
        for (int half = 0; half < 2; half++) {
            int r = m0 + wm0 + mi * 16 + (lane >> 2) + half * 8;
            if (SEL != 0 && r >= cnt) continue;
            int crow = ridx ? ridx[r] : r;
            float* dd = C + (size_t)crow * ldc;
#pragma unroll
            for (int ni = 0; ni < 4; ni++) {
                int cc = n0 + wn0 + ni * 8 + (lane & 3) * 2;
                float v0 = acc[mi][ni][half * 2 + 0] + (bias ? bias[cc] : 0.f);
                float v1 = acc[mi][ni][half * 2 + 1] + (bias ? bias[cc + 1] : 0.f);
                if (act) { v0 = gelu_f(v0); v1 = gelu_f(v1); }
                *(float2*)(dd + cc) = make_float2(v0, v1);
            }
        }
    }
}

__global__ void __launch_bounds__(512) k_sp_hidgo(const float* w1, const float* b1) {
    gemm_sp_body<1>(d_featgo, D3n, w1, D3n, d_hidgo, MIDn, b1, D3n, 1);
}
__global__ void __launch_bounds__(512) k_sp_hidga(const float* w1, const float* b1) {
    gemm_sp_body<2>(d_featga, D3n, w1, D3n, d_hidga, MIDn, b1, D3n, 1);
}
__global__ void __launch_bounds__(512) k_sp_a2o(const float* tokens, const float* w) {
    gemm_sp_body<3>(tokens + Hn, Mn * Hn, w, Hn, d_a2o, Hn, (const float*)0, Hn, 0);
}
__global__ void __launch_bounds__(512) k_sp_o2a(const float* w) {
    gemm_sp_body<3>(d_omean, Hn, w, Hn, d_o2a, Hn, (const float*)0, Hn, 0);
}
__global__ void __launch_bounds__(512) k_sp_out(const float* w, const float* bb) {
    gemm_sp_body<0>(d_h1, Hn, w, Hn, d_h2, Hn, bb, Hn, 1);
}

// ---------------- factor split/transpose prep ----------------
__global__ void __launch_bounds__(256) k_prep_factors(const float* __restrict__ f) {
    __shared__ float t[32][33];
    int mr = blockIdx.z;
    int d0 = blockIdx.x * 32, h0 = blockIdx.y * 32;
    int tx = threadIdx.x, ty = threadIdx.y;
#pragma unroll
    for (int i = ty; i < 32; i += 8)
        t[i][tx] = f[((size_t)mr * 1025 + 1 + d0 + i) * Hn + h0 + tx];
    __syncthreads();
#pragma unroll
    for (int i = ty; i < 32; i += 8) {
        float x = t[tx][i];
        __nv_bfloat16 hi = __float2bfloat16(x);
        float lo = x - __bfloat162float(hi);
        size_t o = ((size_t)mr * Hn + h0 + i) * Hn + d0 + tx;
        d_fhi[o] = hi;
        d_flo[o] = __float2bfloat16(lo);
    }
}

// ---------------- LMF GEMM: block 128x256, 16 warps, warp 32x64, 3-stage ----------------
// mode 0: blockIdx.z in [0,30) -> mr in {0..9, 20..39} (m = 0,2,3)
// mode 1: blockIdx.z in [0,10) -> mr = 10 + z       (m = 1)
#define ZKC     32
#define ZPAD    40
#define ZA_ROWS 128
#define ZB_ROWS 256
#define ZABUF   (ZA_ROWS * ZPAD * 2)
#define ZBBUF   (ZB_ROWS * ZPAD * 2)
#define ZSTAGE  (2 * ZABUF + 2 * ZBBUF)
#define ZSM_TOTAL (3 * ZSTAGE)

__global__ void __launch_bounds__(512) k_gemm_z_mma(int mode) {
    extern __shared__ char zsm[];
    const uint32_t sbase = smem_u32(zsm);
    const int tid = threadIdx.x;
    const int wid = tid >> 5, lane = tid & 31;
    const int h0 = blockIdx.x * 256;
    const int b0 = blockIdx.y * 128;
    const int bz = blockIdx.z;
    const int mr = mode ? (10 + bz) : (bz < 10 ? bz : bz + 10);
    const int m = mr / Rn;
    const int cnt = d_ccnt[m];
    if (b0 >= cnt) return;

    const int lrow = tid >> 2;
    const int lseg = tid & 3;

    int grow = b0 + lrow;
    int gidx = d_cidx[m * Bn + (grow < cnt ? grow : cnt - 1)];

    const __nv_bfloat16* pAhi = d_ahi + ((size_t)m * Bn + gidx) * Hn + lseg * 8;
    const __nv_bfloat16* pAlo = d_alo + ((size_t)m * Bn + gidx) * Hn + lseg * 8;
    const __nv_bfloat16* pB0hi = d_fhi + ((size_t)mr * Hn + h0 + lrow) * Hn + lseg * 8;
    const __nv_bfloat16* pB0lo = d_flo + ((size_t)mr * Hn + h0 + lrow) * Hn + lseg * 8;
    const __nv_bfloat16* pB1hi = pB0hi + (size_t)128 * Hn;
    const __nv_bfloat16* pB1lo = pB0lo + (size_t)128 * Hn;

    auto load_stage = [&](int st, int k0) {
        uint32_t base = sbase + st * ZSTAGE;
        uint32_t offA = lrow * (ZPAD * 2) + lseg * 16;
        cp16(base + offA, pAhi + k0);
        cp16(base + ZABUF + offA, pAlo + k0);
        uint32_t offB0 = lrow * (ZPAD * 2) + lseg * 16;
        uint32_t offB1 = (lrow + 128) * (ZPAD * 2) + lseg * 16;
        cp16(base + 2 * ZABUF + offB0, pB0hi + k0);
        cp16(base + 2 * ZABUF + offB1, pB1hi + k0);
        cp16(base + 2 * ZABUF + ZBBUF + offB0, pB0lo + k0);
        cp16(base + 2 * ZABUF + ZBBUF + offB1, pB1lo + k0);
    };

    float acc[2][8][4];
#pragma unroll
    for (int i = 0; i < 2; i++)
#pragma unroll
        for (int j = 0; j < 8; j++)
#pragma unroll
            for (int c = 0; c < 4; c++) acc[i][j][c] = 0.0f;

    const int wm0 = (wid >> 2) * 32;
    const int wn0 = (wid & 3) * 64;
    const int a_r = lane & 15;
    const int a_c8 = (lane >> 4) << 3;
    const int b_r = (lane & 7) + ((lane >> 4) << 3);
    const int b_c8 = ((lane >> 3) & 1) << 3;

    load_stage(0, 0);
    CP_COMMIT();
    load_stage(1, ZKC);
    CP_COMMIT();

    const int NIT = Hn / ZKC;
    for (int it = 0; it < NIT; it++) {
        CP_WAIT(1);
        __syncthreads();
        if (it + 2 < NIT) {
            load_stage((it + 2) % 3, (it + 2) * ZKC);
            CP_COMMIT();
        }
        const int st = it % 3;
        const uint32_t sAh = sbase + st * ZSTAGE;
        const uint32_t sAl = sAh + ZABUF;
        const uint32_t sBh = sAh + 2 * ZABUF;
        const uint32_t sBl = sBh + ZBBUF;

#pragma unroll
        for (int ks = 0; ks < 2; ks++) {
            const int kb = ks * 16;
            uint32_t aH[2][4], aL[2][4];
#pragma unroll
            for (int mi = 0; mi < 2; mi++) {
                uint32_t off = (uint32_t)(wm0 + mi * 16 + a_r) * (ZPAD * 2) + (kb + a_c8) * 2;
                ldm_x4(aH[mi][0], aH[mi][1], aH[mi][2], aH[mi][3], sAh + off);
                ldm_x4(aL[mi][0], aL[mi][1], aL[mi][2], aL[mi][3], sAl + off);
            }
#pragma unroll
            for (int hf = 0; hf < 2; hf++) {
                uint32_t bH[4][2], bL[4][2];
#pragma unroll
                for (int p = 0; p < 2; p++) {
                    uint32_t off = (uint32_t)(wn0 + hf * 32 + p * 16 + b_r) * (ZPAD * 2) + (kb + b_c8) * 2;
                    ldm_x4(bH[2 * p][0], bH[2 * p][1], bH[2 * p + 1][0], bH[2 * p + 1][1], sBh + off);
                    ldm_x4(bL[2 * p][0], bL[2 * p][1], bL[2 * p + 1][0], bL[2 * p + 1][1], sBl + off);
                }
#pragma unroll
                for (int mi = 0; mi < 2; mi++)
#pragma unroll
                    for (int ni = 0; ni < 4; ni++)
                        mma_bf16(acc[mi][hf * 4 + ni], aH[mi], bH[ni]);
#pragma unroll
                for (int mi = 0; mi < 2; mi++)
#pragma unroll
                    for (int ni = 0; ni < 4; ni++)
                        mma_bf16(acc[mi][hf * 4 + ni], aH[mi], bL[ni]);
#pragma unroll
                for (int mi = 0; mi < 2; mi++)
#pragma unroll
                    for (int ni = 0; ni < 4; ni++)
                        mma_bf16(acc[mi][hf * 4 + ni], aL[mi], bH[ni]);
            }
        }
    }

#pragma unroll
    for (int mi = 0; mi < 2; mi++) {
#pragma unroll
        for (int half = 0; half < 2; half++) {
            int r = b0 + wm0 + mi * 16 + (lane >> 2) + half * 8;
            if (r >= cnt) continue;
            int br = d_cidx[m * Bn + r];
            float* dd = d_zbuf + ((size_t)br * (Mn * Rn) + mr) * Hn + h0;
#pragma unroll
            for (int ni = 0; ni < 8; ni++) {
                int cc = wn0 + ni * 8 + (lane & 3) * 2;
                *(float2*)(dd + cc) = make_float2(acc[mi][ni][half * 2 + 0], acc[mi][ni][half * 2 + 1]);
            }
        }
    }
}

// ---------------- feat builders (compacted) ----------------
__global__ void k_feat_go(const float* tokens, const float* lnw, const float* lnb) {
    int i = blockIdx.x;
    if (i >= d_pvcnt) return;
    int row = d_pvidx[i];
    int b = row / 3, j = row - 3 * b;
    int oj = (j == 0) ? 0 : (j + 1);
    const float* tok = tokens + (size_t)b * Mn * Hn;
    __shared__ float sf[D3n];
    float s = 0.f, q = 0.f;
    for (int k = threadIdx.x; k < Hn; k += blockDim.x) {
        float t = tok[oj * Hn + k];
        float sv = tok[Hn + k];
        float dv = fabsf(t - sv);
        sf[k] = t; sf[Hn + k] = sv; sf[2 * Hn + k] = dv;
        s += t + sv + dv; q += t * t + sv * sv + dv * dv;
    }
    float2 rr = blkSum2(s, q);
    float mean = rr.x / D3n;
    float var = rr.y / D3n - mean * mean;
    float rstd = rsqrtf(var + 1e-5f);
    float* o = d_featgo + (size_t)i * D3n;
    for (int k = threadIdx.x; k < D3n; k += blockDim.x)
        o[k] = (sf[k] - mean) * rstd * lnw[k] + lnb[k];
}

__global__ void k_feat_ga(const float* tokens, const float* lnw, const float* lnb) {
    int i = blockIdx.x;
    if (i >= d_aumcnt) return;
    int b = d_aumidx[i];
    const float* tok = tokens + (size_t)b * Mn * Hn;
    __shared__ float sf[D3n];
    float s = 0.f, q = 0.f;
    for (int k = threadIdx.x; k < Hn; k += blockDim.x) {
        float t = tok[Hn + k];
        float sv = d_omean[(size_t)b * Hn + k];
        float dv = fabsf(t - sv);
        sf[k] = t; sf[Hn + k] = sv; sf[2 * Hn + k] = dv;
        s += t + sv + dv; q += t * t + sv * sv + dv * dv;
    }
    float2 rr = blkSum2(s, q);
    float mean = rr.x / D3n;
    float var = rr.y / D3n - mean * mean;
    float rstd = rsqrtf(var + 1e-5f);
    float* o = d_featga + (size_t)i * D3n;
    for (int k = threadIdx.x; k < D3n; k += blockDim.x)
        o[k] = (sf[k] - mean) * rstd * lnw[k] + lnb[k];
}

// ---------------- gate tails (compacted) ----------------
__global__ void k_gate_go(const float* w2, const float* b2) {
    int i = blockIdx.x;
    if (i >= d_pvcnt) return;
    const float* hr = d_hidgo + (size_t)i * MIDn;
    float v = 0.f;
    for (int k = threadIdx.x; k < MIDn; k += blockDim.x) v += hr[k] * w2[k];
    float2 rr = blkSum2(v, 0.f);
    if (threadIdx.x == 0) d_ggo[d_pvidx[i]] = 1.0f / (1.0f + expf(-(rr.x + b2[0])));
}
__global__ void k_gate_ga(const float* w2, const float* b2) {
    int i = blockIdx.x;
    if (i >= d_aumcnt) return;
    const float* hr = d_hidga + (size_t)i * MIDn;
    float v = 0.f;
    for (int k = threadIdx.x; k < MIDn; k += blockDim.x) v += hr[k] * w2[k];
    float2 rr = blkSum2(v, 0.f);
    if (threadIdx.x == 0) d_gavec[d_aumidx[i]] = 1.0f / (1.0f + expf(-(rr.x + b2[0])));
}

// ---------------- others_new + omean + split of m=0,2,3 mixed slots (fused) ----------------
__global__ void k_others_omean(const float* tokens, const float* lnw, const float* lnb) {
    int b = blockIdx.x;
    const float* tok = tokens + (size_t)b * Mn * Hn;
    int ma = d_mask[b * 4 + 1];
    __shared__ float srow[Hn];
    __shared__ float ssum[Hn];
    for (int k = threadIdx.x; k < Hn; k += blockDim.x) ssum[k] = 0.f;
    float denom = 0.f;
    for (int j = 0; j < 3; j++) {
        int oj = (j == 0) ? 0 : (j + 1);     // mixed slot index == oj for others
        int moj = d_mask[b * 4 + oj];
        if (moj && ma) {
            float g = d_ggo[b * 3 + j];
            float s = 0.f, q = 0.f;
            for (int k = threadIdx.x; k < Hn; k += blockDim.x) {
                float x = tok[oj * Hn + k] + g * d_a2o[(size_t)b * Hn + k];
                srow[k] = x; s += x; q += x * x;
            }
            float2 rr = blkSum2(s, q);
            float mean = rr.x / Hn;
            float var = rr.y / Hn - mean * mean;
            float rstd = rsqrtf(var + 1e-5f);
            for (int k = threadIdx.x; k < Hn; k += blockDim.x) {
                float v = (srow[k] - mean) * rstd * lnw[k] + lnb[k];
                split_store(oj, b, k, v);
                ssum[k] += v;
            }
        } else if (moj) {
            for (int k = threadIdx.x; k < Hn; k += blockDim.x) {
                float v = tok[oj * Hn + k];
                split_store(oj, b, k, v);
                ssum[k] += v;
            }
        } else {
            for (int k = threadIdx.x; k < Hn; k += blockDim.x)
                split_store(oj, b, k, 0.0f);
        }
        if (moj) denom += 1.f;
    }
    denom = fmaxf(denom, 1.f);
    for (int k = threadIdx.x; k < Hn; k += blockDim.x)
        d_omean[(size_t)b * Hn + k] = ssum[k] / denom;
}

// ---------------- mixed audio slot only (m=1) ----------------
__global__ void k_mixed_audio(const float* tokens, const float* lnw, const float* lnb) {
    int b = blockIdx.x;
    const float* tok = tokens + (size_t)b * Mn * Hn;
    int m0 = d_mask[b * 4], m1 = d_mask[b * 4 + 1], m2 = d_mask[b * 4 + 2], m3 = d_mask[b * 4 + 3];
    int aum = m1 && (m0 || m2 || m3);
    if (aum) {
        __shared__ float sx[Hn];
        float g = d_gavec[b];
        float s = 0.f, q = 0.f;
        for (int k = threadIdx.x; k < Hn; k += blockDim.x) {
            float x = tok[Hn + k] + g * d_o2a[(size_t)b * Hn + k];
            sx[k] = x; s += x; q += x * x;
        }
        float2 rr = blkSum2(s, q);
        float mean = rr.x / Hn;
        float var = rr.y / Hn - mean * mean;
        float rstd = rsqrtf(var + 1e-5f);
        for (int k = threadIdx.x; k < Hn; k += blockDim.x)
            split_store(1, b, k, (sx[k] - mean) * rstd * lnw[k] + lnb[k]);
    } else {
        float f = m1 ? 1.0f : 0.0f;
        for (int k = threadIdx.x; k < Hn; k += blockDim.x)
            split_store(1, b, k, tok[Hn + k] * f);
    }
}

// ---------------- rank product + weighted sum + LN (fused) ----------------
__global__ void k_combine_ln(const float* rank_w, const float* lmf_bias,
                             const float* __restrict__ factors,
                             const float* lnw, const float* lnb) {
    int b = blockIdx.x;
    const unsigned char* mk = d_mask + b * 4;
    bool m0 = mk[0], m1 = mk[1], m2 = mk[2], m3 = mk[3];
    __shared__ float sx[Hn];
    float s = 0.f, q = 0.f;
    for (int h = threadIdx.x; h < Hn; h += blockDim.x) {
        const float* zb = d_zbuf + (size_t)b * (Mn * Rn * Hn) + h;
        float acc = 0.f;
#pragma unroll
        for (int r = 0; r < Rn; r++) {
            float p = rank_w[r];
            if (m0) p *= zb[(0 * Rn + r) * Hn] + factors[((size_t)(0 * Rn + r) * 1025) * Hn + h];
            if (m1) p *= zb[(1 * Rn + r) * Hn] + factors[((size_t)(1 * Rn + r) * 1025) * Hn + h];
            if (m2) p *= zb[(2 * Rn + r) * Hn] + factors[((size_t)(2 * Rn + r) * 1025) * Hn + h];
            if (m3) p *= zb[(3 * Rn + r) * Hn] + factors[((size_t)(3 * Rn + r) * 1025) * Hn + h];
            acc += p;
        }
        float v = acc + lmf_bias[h];
        sx[h] = v;
        s += v; q += v * v;
    }
    float2 rr = blkSum2(s, q);
    float mean = rr.x / Hn;
    float var = rr.y / Hn - mean * mean;
    float rstd = rsqrtf(var + 1e-5f);
    float* o = d_h1 + (size_t)b * Hn;
    for (int h = threadIdx.x; h < Hn; h += blockDim.x)
        o[h] = (sx[h] - mean) * rstd * lnw[h] + lnb[h];
}

// ---------------- final LayerNorm ----------------
__global__ void k_ln_out(const float* w, const float* bb, float* out) {
    const float* x = d_h2 + (size_t)blockIdx.x * Hn;
    float* y = out + (size_t)blockIdx.x * Hn;
    float s = 0.f, q = 0.f;
    for (int k = threadIdx.x; k < Hn; k += blockDim.x) { float v = x[k]; s += v; q += v * v; }
    float2 rr = blkSum2(s, q);
    float mean = rr.x / Hn;
    float var = rr.y / Hn - mean * mean;
    float rstd = rsqrtf(var + 1e-5f);
    for (int k = threadIdx.x; k < Hn; k += blockDim.x)
        y[k] = (x[k] - mean) * rstd * w[k] + bb[k];
}

// ---------------- launch ----------------
extern "C" void kernel_launch(void* const* d_in, const int* in_sizes, int n_in,
                              void* d_out, int out_size) {
    const float* tokens   = (const float*)d_in[0];
    const void*  maskraw  = d_in[1];
    const float* ln_go_w  = (const float*)d_in[2];
    const float* ln_go_b  = (const float*)d_in[3];
    const float* go_w1    = (const float*)d_in[4];
    const float* go_b1    = (const float*)d_in[5];
    const float* go_w2    = (const float*)d_in[6];
    const float* go_b2    = (const float*)d_in[7];
    const float* ln_ga_w  = (const float*)d_in[8];
    const float* ln_ga_b  = (const float*)d_in[9];
    const float* ga_w1    = (const float*)d_in[10];
    const float* ga_b1    = (const float*)d_in[11];
    const float* ga_w2    = (const float*)d_in[12];
    const float* ga_b2    = (const float*)d_in[13];
    const float* a2o_w    = (const float*)d_in[14];
    const float* o2a_w    = (const float*)d_in[15];
    const float* ln_o_w   = (const float*)d_in[16];
    const float* ln_o_b   = (const float*)d_in[17];
    const float* ln_a_w   = (const float*)d_in[18];
    const float* ln_a_b   = (const float*)d_in[19];
    const float* factors  = (const float*)d_in[20];
    const float* rank_w   = (const float*)d_in[21];
    const float* lmf_bias = (const float*)d_in[22];
    const float* out_ln1w = (const float*)d_in[23];
    const float* out_ln1b = (const float*)d_in[24];
    const float* out_w    = (const float*)d_in[25];
    const float* out_b    = (const float*)d_in[26];
    const float* out_ln2w = (const float*)d_in[27];
    const float* out_ln2b = (const float*)d_in[28];
    float* out = (float*)d_out;

    static cudaStream_t s1 = nullptr, s2 = nullptr;
    static cudaEvent_t evStart, evPF, evCmp, evA2O, evOM, evO2A, evZ1;
    if (!s1) {
        cudaFuncSetAttribute(k_gemm_z_mma, cudaFuncAttributeMaxDynamicSharedMemorySize, ZSM_TOTAL);
        cudaFuncSetAttribute(k_sp_hidgo, cudaFuncAttributeMaxDynamicSharedMemorySize, GSM_TOTAL);
        cudaFuncSetAttribute(k_sp_hidga, cudaFuncAttributeMaxDynamicSharedMemorySize, GSM_TOTAL);
        cudaFuncSetAttribute(k_sp_a2o,   cudaFuncAttributeMaxDynamicSharedMemorySize, GSM_TOTAL);
        cudaFuncSetAttribute(k_sp_o2a,   cudaFuncAttributeMaxDynamicSharedMemorySize, GSM_TOTAL);
        cudaFuncSetAttribute(k_sp_out,   cudaFuncAttributeMaxDynamicSharedMemorySize, GSM_TOTAL);
        cudaStreamCreateWithFlags(&s1, cudaStreamNonBlocking);
        cudaStreamCreateWithFlags(&s2, cudaStreamNonBlocking);
        cudaEventCreateWithFlags(&evStart, cudaEventDisableTiming);
        cudaEventCreateWithFlags(&evPF,    cudaEventDisableTiming);
        cudaEventCreateWithFlags(&evCmp,   cudaEventDisableTiming);
        cudaEventCreateWithFlags(&evA2O,   cudaEventDisableTiming);
        cudaEventCreateWithFlags(&evOM,    cudaEventDisableTiming);
        cudaEventCreateWithFlags(&evO2A,   cudaEventDisableTiming);
        cudaEventCreateWithFlags(&evZ1,    cudaEventDisableTiming);
    }

    cudaEventRecord(evStart, 0);
    cudaStreamWaitEvent(s1, evStart, 0);
    k_prep_factors<<<dim3(32, 32, Mn * Rn), dim3(32, 8), 0, s1>>>(factors);
    cudaEventRecord(evPF, s1);

    k_mask_compact<<<6, 1024>>>(maskraw);
    cudaEventRecord(evCmp, 0);

    cudaStreamWaitEvent(s2, evCmp, 0);
    k_sp_a2o<<<dim3(Hn / 128, Bn / 128), 512, GSM_TOTAL, s2>>>(tokens, a2o_w);
    cudaEventRecord(evA2O, s2);

    k_feat_go<<<3 * Bn, 256>>>(tokens, ln_go_w, ln_go_b);
    k_sp_hidgo<<<dim3(MIDn / 128, 3 * Bn / 128), 512, GSM_TOTAL>>>(go_w1, go_b1);
    k_gate_go<<<3 * Bn, 256>>>(go_w2, go_b2);
    cudaStreamWaitEvent(0, evA2O, 0);
    k_others_omean<<<Bn, 256>>>(tokens, ln_o_w, ln_o_b);
    cudaEventRecord(evOM, 0);

    // s2: z for m in {0,2,3} overlaps the entire gate-audio chain
    cudaStreamWaitEvent(s2, evOM, 0);
    cudaStreamWaitEvent(s2, evPF, 0);
    k_gemm_z_mma<<<dim3(Hn / 256, Bn / 128, 30), 512, ZSM_TOTAL, s2>>>(0);
    cudaEventRecord(evZ1, s2);

    // s1: o2a after omean (concurrent with feat_ga/hidga on stream 0)
    cudaStreamWaitEvent(s1, evOM, 0);
    k_sp_o2a<<<dim3(Hn / 128, Bn / 128), 512, GSM_TOTAL, s1>>>(o2a_w);
    cudaEventRecord(evO2A, s1);

    k_feat_ga<<<Bn, 256>>>(tokens, ln_ga_w, ln_ga_b);
    k_sp_hidga<<<dim3(MIDn / 128, Bn / 128), 512, GSM_TOTAL>>>(ga_w1, ga_b1);
    k_gate_ga<<<Bn, 256>>>(ga_w2, ga_b2);
    cudaStreamWaitEvent(0, evO2A, 0);
    k_mixed_audio<<<Bn, 256>>>(tokens, ln_a_w, ln_a_b);

    k_gemm_z_mma<<<dim3(Hn / 256, Bn / 128, 10), 512, ZSM_TOTAL>>>(1);
    cudaStreamWaitEvent(0, evZ1, 0);
    k_combine_ln<<<Bn, 256>>>(rank_w, lmf_bias, factors, out_ln1w, out_ln1b);
    k_sp_out<<<dim3(Hn / 128, Bn / 128), 512, GSM_TOTAL>>>(out_w, out_b);
    k_ln_out<<<Bn, 256>>>(out_ln2w, out_ln2b, out);
}

// round 15
// speedup vs baseline: 1.1030x; 1.0114x over previous
#include <cuda_runtime.h>
#include <cuda_bf16.h>
#include <math.h>
#include <cstdint>

#define Bn   4096
#define Mn   4
#define Hn   1024
#define Rn   10
#define MIDn 512
#define D3n  3072

// ---------------- scratch (__device__ globals: alloc-free) ----------------
__device__ float d_featgo[3 * Bn * D3n];
__device__ float d_hidgo[3 * Bn * MIDn];
__device__ float d_ggo[3 * Bn];
__device__ float d_a2o[Bn * Hn];
__device__ float d_omean[Bn * Hn];
__device__ float d_featga[Bn * D3n];
__device__ float d_hidga[Bn * MIDn];
__device__ float d_gavec[Bn];
__device__ float d_o2a[Bn * Hn];
__device__ float d_zbuf[167772160];             // B*M*R*H fp32
__device__ float d_h1[Bn * Hn];
__device__ float d_h2[Bn * Hn];
__device__ unsigned char d_mask[Bn * Mn];
__device__ int d_cidx[Mn * Bn];
__device__ int d_ccnt[Mn];
__device__ int d_pvidx[3 * Bn];
__device__ int d_pvcnt;
__device__ int d_aumidx[Bn];
__device__ int d_aumcnt;
__device__ __nv_bfloat16 d_ahi[Mn * Bn * Hn];      // [m][b][h]
__device__ __nv_bfloat16 d_alo[Mn * Bn * Hn];
__device__ __nv_bfloat16 d_fhi[Mn * Rn * Hn * Hn]; // [mr][h][d]
__device__ __nv_bfloat16 d_flo[Mn * Rn * Hn * Hn];

// ---------------- generic helpers ----------------
__device__ __forceinline__ float gelu_f(float x) {
    return 0.5f * x * (1.0f + erff(x * 0.70710678118654752f));
}
__device__ __forceinline__ float2 blkSum2(float a, float b) {
    __shared__ float sa[32], sb[32];
    __shared__ float ra, rb;
    int lane = threadIdx.x & 31, w = threadIdx.x >> 5;
#pragma unroll
    for (int o = 16; o > 0; o >>= 1) {
        a += __shfl_xor_sync(0xffffffffu, a, o);
        b += __shfl_xor_sync(0xffffffffu, b, o);
    }
    if (lane == 0) { sa[w] = a; sb[w] = b; }
    __syncthreads();
    if (threadIdx.x == 0) {
        float x = 0.f, y = 0.f;
        int nw = blockDim.x >> 5;
        for (int i = 0; i < nw; i++) { x += sa[i]; y += sb[i]; }
        ra = x; rb = y;
    }
    __syncthreads();
    return make_float2(ra, rb);
}
__device__ __forceinline__ void split_store(int m, int b, int k, float v) {
    __nv_bfloat16 hi = __float2bfloat16(v);
    float lo = v - __bfloat162float(hi);
    size_t o = ((size_t)m * Bn + b) * Hn + k;
    d_ahi[o] = hi;
    d_alo[o] = __float2bfloat16(lo);
}

// ---------------- mma.sync helpers ----------------
__device__ __forceinline__ uint32_t smem_u32(const void* p) {
    uint32_t a;
    asm("{ .reg .u64 t; cvta.to.shared.u64 t, %1; cvt.u32.u64 %0, t; }" : "=r"(a) : "l"(p));
    return a;
}
__device__ __forceinline__ void ldm_x4(uint32_t& r0, uint32_t& r1, uint32_t& r2, uint32_t& r3,
                                       uint32_t addr) {
    asm volatile("ldmatrix.sync.aligned.m8n8.x4.shared.b16 {%0,%1,%2,%3}, [%4];"
                 : "=r"(r0), "=r"(r1), "=r"(r2), "=r"(r3) : "r"(addr));
}
__device__ __forceinline__ void mma_bf16(float* c, const uint32_t* a, const uint32_t* b) {
    asm volatile("mma.sync.aligned.m16n8k16.row.col.f32.bf16.bf16.f32 "
                 "{%0,%1,%2,%3}, {%4,%5,%6,%7}, {%8,%9}, {%0,%1,%2,%3};"
                 : "+f"(c[0]), "+f"(c[1]), "+f"(c[2]), "+f"(c[3])
                 : "r"(a[0]), "r"(a[1]), "r"(a[2]), "r"(a[3]), "r"(b[0]), "r"(b[1]));
}
__device__ __forceinline__ void cp16(uint32_t dst, const void* src) {
    asm volatile("cp.async.cg.shared.global [%0], [%1], 16;" :: "r"(dst), "l"(src));
}
#define CP_COMMIT() asm volatile("cp.async.commit_group;" ::: "memory")
#define CP_WAIT(n)  asm volatile("cp.async.wait_group %0;" :: "n"(n) : "memory")

__device__ __forceinline__ uint32_t pack_hi_lo(float x, float y, uint32_t& lo) {
    __nv_bfloat16 hx = __float2bfloat16(x);
    __nv_bfloat16 hy = __float2bfloat16(y);
    float lxf = x - __bfloat162float(hx);
    float lyf = y - __bfloat162float(hy);
    __nv_bfloat162 hv = __halves2bfloat162(hx, hy);
    __nv_bfloat162 lv = __halves2bfloat162(__float2bfloat16(lxf), __float2bfloat16(lyf));
    lo = *reinterpret_cast<uint32_t*>(&lv);
    return *reinterpret_cast<uint32_t*>(&hv);
}

// ---------------- fused mask sniff + all compactions (6 blocks) ----------------
__global__ void __launch_bounds__(1024) k_mask_compact(const void* raw) {
    __shared__ int ok32s, okfs;
    if (threadIdx.x == 0) { ok32s = 1; okfs = 1; }
    __syncthreads();
    const int* pi = (const int*)raw;
    const float* pf = (const float*)raw;
    const unsigned char* pb = (const unsigned char*)raw;
    int lok32 = 1, lokf = 1;
    for (int i = threadIdx.x; i < 4096; i += 1024) {
        int v = pi[i];
        if (v != 0 && v != 1) lok32 = 0;
        float f = pf[i];
        if (f != 0.0f && f != 1.0f) lokf = 0;
    }
    if (!lok32) ok32s = 0;
    if (!lokf)  okfs = 0;
    __syncthreads();
    const int ok32 = ok32s, okf = okfs;
    auto maskat = [&](int i) -> int {
        if (ok32) return pi[i] != 0;
        if (okf)  return pf[i] != 0.0f;
        return pb[i] != 0;
    };

    const int blk = blockIdx.x;
    if (blk == 0) {
        for (int i = threadIdx.x; i < Bn * Mn; i += 1024)
            d_mask[i] = (unsigned char)maskat(i);
    }

    int* out_idx;
    int* out_cnt;
    int nitems;
    if (blk < 4)      { out_idx = d_cidx + blk * Bn; out_cnt = d_ccnt + blk; nitems = Bn; }
    else if (blk == 4){ out_idx = d_pvidx;           out_cnt = &d_pvcnt;     nitems = 3 * Bn; }
    else              { out_idx = d_aumidx;          out_cnt = &d_aumcnt;    nitems = Bn; }

    __shared__ int warp_off[32];
    __shared__ int chunk_base;
    if (threadIdx.x == 0) chunk_base = 0;
    __syncthreads();
    int lane = threadIdx.x & 31, w = threadIdx.x >> 5;
    for (int c = 0; c < nitems; c += 1024) {
        int i = c + threadIdx.x;
        int v;
        if (blk < 4) {
            v = maskat(i * Mn + blk);
        } else if (blk == 4) {
            int b = i / 3, j = i - 3 * b;
            int oj = (j == 0) ? 0 : (j + 1);
            v = maskat(b * 4 + oj) && maskat(b * 4 + 1);
        } else {
            v = maskat(i * 4 + 1) && (maskat(i * 4) | maskat(i * 4 + 2) | maskat(i * 4 + 3));
        }
        unsigned bal = __ballot_sync(0xffffffffu, v);
        int pre = __popc(bal & ((1u << lane) - 1u));
        if (lane == 31) warp_off[w] = __popc(bal);
        __syncthreads();
        if (threadIdx.x < 32) {
            int val = warp_off[threadIdx.x];
#pragma unroll
            for (int o = 1; o < 32; o <<= 1) {
                int t = __shfl_up_sync(0xffffffffu, val, o);
                if ((int)threadIdx.x >= o) val += t;
            }
            warp_off[threadIdx.x] = val;
        }
        __syncthreads();
        int base = chunk_base + (w ? warp_off[w - 1] : 0) + pre;
        if (v) out_idx[base] = i;
        __syncthreads();
        if (threadIdx.x == 0) chunk_base += warp_off[31];
        __syncthreads();
    }
    if (threadIdx.x == 0) *out_cnt = chunk_base;
}

// ---------------- generic fp32 -> bf16-split mma GEMM (512 thr, 16 warps) ----------------
#define GPAD   40
#define GBUF   (128 * GPAD * 2)
#define GSTAGE (4 * GBUF)
#define GSM_TOTAL (2 * GSTAGE)

template <int SEL>
__device__ __forceinline__ void gemm_sp_body(
    const float* __restrict__ A, int lda,
    const float* __restrict__ B, int ldb,
    float* __restrict__ C, int ldc,
    const float* __restrict__ bias, int K, int act)
{
    extern __shared__ char gsm[];
    int cnt = 1 << 30;
    const int* ridx = nullptr;
    if (SEL == 1) cnt = d_pvcnt;
    if (SEL == 2) cnt = d_aumcnt;
    if (SEL == 3) { cnt = d_aumcnt; ridx = d_aumidx; }
    const int n0 = blockIdx.x * 128, m0 = blockIdx.y * 128;
    if (SEL != 0 && m0 >= cnt) return;

    const uint32_t sbase = smem_u32(gsm);
    const int tid = threadIdx.x;
    const int wid = tid >> 5, lane = tid & 31;

    const int lrow = tid >> 2, lseg = tid & 3;
    int grow = m0 + lrow;
    if (SEL != 0 && grow >= cnt) grow = cnt - 1;
    const int arow = ridx ? ridx[grow] : grow;
    const float* Aref = A + (size_t)arow * lda + lseg * 8;
    const float* Bref = B + (size_t)(n0 + lrow) * ldb + lseg * 8;

    float4 ra[2], rb[2];
    auto gload = [&](int k0) {
        ra[0] = *(const float4*)(Aref + k0);
        ra[1] = *(const float4*)(Aref + k0 + 4);
        rb[0] = *(const float4*)(Bref + k0);
        rb[1] = *(const float4*)(Bref + k0 + 4);
    };
    auto sstore = [&](int st) {
        char* p = gsm + st * GSTAGE + lrow * (GPAD * 2) + lseg * 16;
        uint32_t l0, l1, l2, l3;
        uint32_t h0 = pack_hi_lo(ra[0].x, ra[0].y, l0);
        uint32_t h1 = pack_hi_lo(ra[0].z, ra[0].w, l1);
        uint32_t h2 = pack_hi_lo(ra[1].x, ra[1].y, l2);
        uint32_t h3 = pack_hi_lo(ra[1].z, ra[1].w, l3);
        *(uint4*)(p + 0 * GBUF) = make_uint4(h0, h1, h2, h3);
        *(uint4*)(p + 1 * GBUF) = make_uint4(l0, l1, l2, l3);
        h0 = pack_hi_lo(rb[0].x, rb[0].y, l0);
        h1 = pack_hi_lo(rb[0].z, rb[0].w, l1);
        h2 = pack_hi_lo(rb[1].x, rb[1].y, l2);
        h3 = pack_hi_lo(rb[1].z, rb[1].w, l3);
        *(uint4*)(p + 2 * GBUF) = make_uint4(h0, h1, h2, h3);
        *(uint4*)(p + 3 * GBUF) = make_uint4(l0, l1, l2, l3);
    };

    float acc[2][4][4];
#pragma unroll
    for (int i = 0; i < 2; i++)
#pragma unroll
        for (int j = 0; j < 4; j++)
#pragma unroll
            for (int c = 0; c < 4; c++) acc[i][j][c] = 0.0f;

    const int wm0 = (wid >> 2) * 32;
    const int wn0 = (wid & 3) * 32;
    const int a_r = lane & 15;
    const int a_c8 = (lane >> 4) << 3;
    const int b_r = (lane & 7) + ((lane >> 4) << 3);
    const int b_c8 = ((lane >> 3) & 1) << 3;

    gload(0);
    const int NIT = K / 32;
    for (int it = 0; it < NIT; it++) {
        const int st = it & 1;
        sstore(st);
        __syncthreads();
        if (it + 1 < NIT) gload((it + 1) * 32);

        const uint32_t sAh = sbase + st * GSTAGE + 0 * GBUF;
        const uint32_t sAl = sbase + st * GSTAGE + 1 * GBUF;
        const uint32_t sBh = sbase + st * GSTAGE + 2 * GBUF;
        const uint32_t sBl = sbase + st * GSTAGE + 3 * GBUF;
#pragma unroll
        for (int ks = 0; ks < 2; ks++) {
            const int kb = ks * 16;
            uint32_t aH[2][4], aL[2][4], bH[4][2], bL[4][2];
#pragma unroll
            for (int mi = 0; mi < 2; mi++) {
                uint32_t off = (uint32_t)(wm0 + mi * 16 + a_r) * (GPAD * 2) + (kb + a_c8) * 2;
                ldm_x4(aH[mi][0], aH[mi][1], aH[mi][2], aH[mi][3], sAh + off);
                ldm_x4(aL[mi][0], aL[mi][1], aL[mi][2], aL[mi][3], sAl + off);
            }
#pragma unroll
            for (int p2 = 0; p2 < 2; p2++) {
                uint32_t off = (uint32_t)(wn0 + p2 * 16 + b_r) * (GPAD * 2) + (kb + b_c8) * 2;
                ldm_x4(bH[2 * p2][0], bH[2 * p2][1], bH[2 * p2 + 1][0], bH[2 * p2 + 1][1], sBh + off);
                ldm_x4(bL[2 * p2][0], bL[2 * p2][1], bL[2 * p2 + 1][0], bL[2 * p2 + 1][1], sBl + off);
            }
#pragma unroll
            for (int mi = 0; mi < 2; mi++)
#pragma unroll
                for (int ni = 0; ni < 4; ni++)
                    mma_bf16(acc[mi][ni], aH[mi], bH[ni]);
#pragma unroll
            for (int mi = 0; mi < 2; mi++)
#pragma unroll
                for (int ni = 0; ni < 4; ni++)
                    mma_bf16(acc[mi][ni], aH[mi], bL[ni]);
#pragma unroll
            for (int mi = 0; mi < 2; mi++)
#pragma unroll
                for (int ni = 0; ni < 4; ni++)
                    mma_bf16(acc[mi][ni], aL[mi], bH[ni]);
        }
        __syncthreads();
    }

#pragma unroll
    for (int mi = 0; mi < 2; mi++) {
#pragma unroll
        for (int half = 0; half < 2; half++) {
            int r = m0 + wm0 + mi * 16 + (lane >> 2) + half * 8;
            if (SEL != 0 && r >= cnt) continue;
            int crow = ridx ? ridx[r] : r;
            float* dd = C + (size_t)crow * ldc;
#pragma unroll
            for (int ni = 0; ni < 4; ni++) {
                int cc = n0 + wn0 + ni * 8 + (lane & 3) * 2;
                float v0 = acc[mi][ni][half * 2 + 0] + (bias ? bias[cc] : 0.f);
                float v1 = acc[mi][ni][half * 2 + 1] + (bias ? bias[cc + 1] : 0.f);
                if (act) { v0 = gelu_f(v0); v1 = gelu_f(v1); }
                *(float2*)(dd + cc) = make_float2(v0, v1);
            }
        }
    }
}

__global__ void __launch_bounds__(512) k_sp_hidgo(const float* w1, const float* b1) {
    gemm_sp_body<1>(d_featgo, D3n, w1, D3n, d_hidgo, MIDn, b1, D3n, 1);
}
__global__ void __launch_bounds__(512) k_sp_hidga(const float* w1, const float* b1) {
    gemm_sp_body<2>(d_featga, D3n, w1, D3n, d_hidga, MIDn, b1, D3n, 1);
}
__global__ void __launch_bounds__(512) k_sp_a2o(const float* tokens, const float* w) {
    gemm_sp_body<3>(tokens + Hn, Mn * Hn, w, Hn, d_a2o, Hn, (const float*)0, Hn, 0);
}
__global__ void __launch_bounds__(512) k_sp_o2a(const float* w) {
    gemm_sp_body<3>(d_omean, Hn, w, Hn, d_o2a, Hn, (const float*)0, Hn, 0);
}
__global__ void __launch_bounds__(512) k_sp_out(const float* w, const float* bb) {
    gemm_sp_body<0>(d_h1, Hn, w, Hn, d_h2, Hn, bb, Hn, 1);
}

// ---------------- factor split/transpose prep ----------------
__global__ void __launch_bounds__(256) k_prep_factors(const float* __restrict__ f) {
    __shared__ float t[32][33];
    int mr = blockIdx.z;
    int d0 = blockIdx.x * 32, h0 = blockIdx.y * 32;
    int tx = threadIdx.x, ty = threadIdx.y;
#pragma unroll
    for (int i = ty; i < 32; i += 8)
        t[i][tx] = f[((size_t)mr * 1025 + 1 + d0 + i) * Hn + h0 + tx];
    __syncthreads();
#pragma unroll
    for (int i = ty; i < 32; i += 8) {
        float x = t[tx][i];
        __nv_bfloat16 hi = __float2bfloat16(x);
        float lo = x - __bfloat162float(hi);
        size_t o = ((size_t)mr * Hn + h0 + i) * Hn + d0 + tx;
        d_fhi[o] = hi;
        d_flo[o] = __float2bfloat16(lo);
    }
}

// ---------------- LMF GEMM: block 128x256, 16 warps, warp 32x64, 3-stage ----------------
#define ZKC     32
#define ZPAD    40
#define ZA_ROWS 128
#define ZB_ROWS 256
#define ZABUF   (ZA_ROWS * ZPAD * 2)
#define ZBBUF   (ZB_ROWS * ZPAD * 2)
#define ZSTAGE  (2 * ZABUF + 2 * ZBBUF)
#define ZSM_TOTAL (3 * ZSTAGE)

__global__ void __launch_bounds__(512) k_gemm_z_mma() {
    extern __shared__ char zsm[];
    const uint32_t sbase = smem_u32(zsm);
    const int tid = threadIdx.x;
    const int wid = tid >> 5, lane = tid & 31;
    const int h0 = blockIdx.x * 256;
    const int b0 = blockIdx.y * 128;
    const int mr = blockIdx.z;
    const int m = mr / Rn;
    const int cnt = d_ccnt[m];
    if (b0 >= cnt) return;

    const int lrow = tid >> 2;
    const int lseg = tid & 3;

    int grow = b0 + lrow;
    int gidx = d_cidx[m * Bn + (grow < cnt ? grow : cnt - 1)];

    const __nv_bfloat16* pAhi = d_ahi + ((size_t)m * Bn + gidx) * Hn + lseg * 8;
    const __nv_bfloat16* pAlo = d_alo + ((size_t)m * Bn + gidx) * Hn + lseg * 8;
    const __nv_bfloat16* pB0hi = d_fhi + ((size_t)mr * Hn + h0 + lrow) * Hn + lseg * 8;
    const __nv_bfloat16* pB0lo = d_flo + ((size_t)mr * Hn + h0 + lrow) * Hn + lseg * 8;
    const __nv_bfloat16* pB1hi = pB0hi + (size_t)128 * Hn;
    const __nv_bfloat16* pB1lo = pB0lo + (size_t)128 * Hn;

    auto load_stage = [&](int st, int k0) {
        uint32_t base = sbase + st * ZSTAGE;
        uint32_t offA = lrow * (ZPAD * 2) + lseg * 16;
        cp16(base + offA, pAhi + k0);
        cp16(base + ZABUF + offA, pAlo + k0);
        uint32_t offB0 = lrow * (ZPAD * 2) + lseg * 16;
        uint32_t offB1 = (lrow + 128) * (ZPAD * 2) + lseg * 16;
        cp16(base + 2 * ZABUF + offB0, pB0hi + k0);
        cp16(base + 2 * ZABUF + offB1, pB1hi + k0);
        cp16(base + 2 * ZABUF + ZBBUF + offB0, pB0lo + k0);
        cp16(base + 2 * ZABUF + ZBBUF + offB1, pB1lo + k0);
    };

    float acc[2][8][4];
#pragma unroll
    for (int i = 0; i < 2; i++)
#pragma unroll
        for (int j = 0; j < 8; j++)
#pragma unroll
            for (int c = 0; c < 4; c++) acc[i][j][c] = 0.0f;

    const int wm0 = (wid >> 2) * 32;
    const int wn0 = (wid & 3) * 64;
    const int a_r = lane & 15;
    const int a_c8 = (lane >> 4) << 3;
    const int b_r = (lane & 7) + ((lane >> 4) << 3);
    const int b_c8 = ((lane >> 3) & 1) << 3;

    load_stage(0, 0);
    CP_COMMIT();
    load_stage(1, ZKC);
    CP_COMMIT();

    const int NIT = Hn / ZKC;
    for (int it = 0; it < NIT; it++) {
        CP_WAIT(1);
        __syncthreads();
        if (it + 2 < NIT) {
            load_stage((it + 2) % 3, (it + 2) * ZKC);
            CP_COMMIT();
        }
        const int st = it % 3;
        const uint32_t sAh = sbase + st * ZSTAGE;
        const uint32_t sAl = sAh + ZABUF;
        const uint32_t sBh = sAh + 2 * ZABUF;
        const uint32_t sBl = sBh + ZBBUF;

#pragma unroll
        for (int ks = 0; ks < 2; ks++) {
            const int kb = ks * 16;
            uint32_t aH[2][4], aL[2][4];
#pragma unroll
            for (int mi = 0; mi < 2; mi++) {
                uint32_t off = (uint32_t)(wm0 + mi * 16 + a_r) * (ZPAD * 2) + (kb + a_c8) * 2;
                ldm_x4(aH[mi][0], aH[mi][1], aH[mi][2], aH[mi][3], sAh + off);
                ldm_x4(aL[mi][0], aL[mi][1], aL[mi][2], aL[mi][3], sAl + off);
            }
#pragma unroll
            for (int hf = 0; hf < 2; hf++) {
                uint32_t bH[4][2], bL[4][2];
#pragma unroll
                for (int p = 0; p < 2; p++) {
                    uint32_t off = (uint32_t)(wn0 + hf * 32 + p * 16 + b_r) * (ZPAD * 2) + (kb + b_c8) * 2;
                    ldm_x4(bH[2 * p][0], bH[2 * p][1], bH[2 * p + 1][0], bH[2 * p + 1][1], sBh + off);
                    ldm_x4(bL[2 * p][0], bL[2 * p][1], bL[2 * p + 1][0], bL[2 * p + 1][1], sBl + off);
                }
#pragma unroll
                for (int mi = 0; mi < 2; mi++)
#pragma unroll
                    for (int ni = 0; ni < 4; ni++)
                        mma_bf16(acc[mi][hf * 4 + ni], aH[mi], bH[ni]);
#pragma unroll
                for (int mi = 0; mi < 2; mi++)
#pragma unroll
                    for (int ni = 0; ni < 4; ni++)
                        mma_bf16(acc[mi][hf * 4 + ni], aH[mi], bL[ni]);
#pragma unroll
                for (int mi = 0; mi < 2; mi++)
#pragma unroll
                    for (int ni = 0; ni < 4; ni++)
                        mma_bf16(acc[mi][hf * 4 + ni], aL[mi], bH[ni]);
            }
        }
    }

#pragma unroll
    for (int mi = 0; mi < 2; mi++) {
#pragma unroll
        for (int half = 0; half < 2; half++) {
            int r = b0 + wm0 + mi * 16 + (lane >> 2) + half * 8;
            if (r >= cnt) continue;
            int br = d_cidx[m * Bn + r];
            float* dd = d_zbuf + ((size_t)br * (Mn * Rn) + mr) * Hn + h0;
#pragma unroll
            for (int ni = 0; ni < 8; ni++) {
                int cc = wn0 + ni * 8 + (lane & 3) * 2;
                *(float2*)(dd + cc) = make_float2(acc[mi][ni][half * 2 + 0], acc[mi][ni][half * 2 + 1]);
            }
        }
    }
}

// ---------------- feat builders (compacted) ----------------
__global__ void k_feat_go(const float* tokens, const float* lnw, const float* lnb) {
    int i = blockIdx.x;
    if (i >= d_pvcnt) return;
    int row = d_pvidx[i];
    int b = row / 3, j = row - 3 * b;
    int oj = (j == 0) ? 0 : (j + 1);
    const float* tok = tokens + (size_t)b * Mn * Hn;
    __shared__ float sf[D3n];
    float s = 0.f, q = 0.f;
    for (int k = threadIdx.x; k < Hn; k += blockDim.x) {
        float t = tok[oj * Hn + k];
        float sv = tok[Hn + k];
        float dv = fabsf(t - sv);
        sf[k] = t; sf[Hn + k] = sv; sf[2 * Hn + k] = dv;
        s += t + sv + dv; q += t * t + sv * sv + dv * dv;
    }
    float2 rr = blkSum2(s, q);
    float mean = rr.x / D3n;
    float var = rr.y / D3n - mean * mean;
    float rstd = rsqrtf(var + 1e-5f);
    float* o = d_featgo + (size_t)i * D3n;
    for (int k = threadIdx.x; k < D3n; k += blockDim.x)
        o[k] = (sf[k] - mean) * rstd * lnw[k] + lnb[k];
}

__global__ void k_feat_ga(const float* tokens, const float* lnw, const float* lnb) {
    int i = blockIdx.x;
    if (i >= d_aumcnt) return;
    int b = d_aumidx[i];
    const float* tok = tokens + (size_t)b * Mn * Hn;
    __shared__ float sf[D3n];
    float s = 0.f, q = 0.f;
    for (int k = threadIdx.x; k < Hn; k += blockDim.x) {
        float t = tok[Hn + k];
        float sv = d_omean[(size_t)b * Hn + k];
        float dv = fabsf(t - sv);
        sf[k] = t; sf[Hn + k] = sv; sf[2 * Hn + k] = dv;
        s += t + sv + dv; q += t * t + sv * sv + dv * dv;
    }
    float2 rr = blkSum2(s, q);
    float mean = rr.x / D3n;
    float var = rr.y / D3n - mean * mean;
    float rstd = rsqrtf(var + 1e-5f);
    float* o = d_featga + (size_t)i * D3n;
    for (int k = threadIdx.x; k < D3n; k += blockDim.x)
        o[k] = (sf[k] - mean) * rstd * lnw[k] + lnb[k];
}

// ---------------- gate tails (compacted) ----------------
__global__ void k_gate_go(const float* w2, const float* b2) {
    int i = blockIdx.x;
    if (i >= d_pvcnt) return;
    const float* hr = d_hidgo + (size_t)i * MIDn;
    float v = 0.f;
    for (int k = threadIdx.x; k < MIDn; k += blockDim.x) v += hr[k] * w2[k];
    float2 rr = blkSum2(v, 0.f);
    if (threadIdx.x == 0) d_ggo[d_pvidx[i]] = 1.0f / (1.0f + expf(-(rr.x + b2[0])));
}
__global__ void k_gate_ga(const float* w2, const float* b2) {
    int i = blockIdx.x;
    if (i >= d_aumcnt) return;
    const float* hr = d_hidga + (size_t)i * MIDn;
    float v = 0.f;
    for (int k = threadIdx.x; k < MIDn; k += blockDim.x) v += hr[k] * w2[k];
    float2 rr = blkSum2(v, 0.f);
    if (threadIdx.x == 0) d_gavec[d_aumidx[i]] = 1.0f / (1.0f + expf(-(rr.x + b2[0])));
}

// ---------------- others_new + omean + split of m=0,2,3 mixed slots (fused) ----------------
__global__ void k_others_omean(const float* tokens, const float* lnw, const float* lnb) {
    int b = blockIdx.x;
    const float* tok = tokens + (size_t)b * Mn * Hn;
    int ma = d_mask[b * 4 + 1];
    __shared__ float srow[Hn];
    __shared__ float ssum[Hn];
    for (int k = threadIdx.x; k < Hn; k += blockDim.x) ssum[k] = 0.f;
    float denom = 0.f;
    for (int j = 0; j < 3; j++) {
        int oj = (j == 0) ? 0 : (j + 1);
        int moj = d_mask[b * 4 + oj];
        if (moj && ma) {
            float g = d_ggo[b * 3 + j];
            float s = 0.f, q = 0.f;
            for (int k = threadIdx.x; k < Hn; k += blockDim.x) {
                float x = tok[oj * Hn + k] + g * d_a2o[(size_t)b * Hn + k];
                srow[k] = x; s += x; q += x * x;
            }
            float2 rr = blkSum2(s, q);
            float mean = rr.x / Hn;
            float var = rr.y / Hn - mean * mean;
            float rstd = rsqrtf(var + 1e-5f);
            for (int k = threadIdx.x; k < Hn; k += blockDim.x) {
                float v = (srow[k] - mean) * rstd * lnw[k] + lnb[k];
                split_store(oj, b, k, v);
                ssum[k] += v;
            }
        } else if (moj) {
            for (int k = threadIdx.x; k < Hn; k += blockDim.x) {
                float v = tok[oj * Hn + k];
                split_store(oj, b, k, v);
                ssum[k] += v;
            }
        } else {
            for (int k = threadIdx.x; k < Hn; k += blockDim.x)
                split_store(oj, b, k, 0.0f);
        }
        if (moj) denom += 1.f;
    }
    denom = fmaxf(denom, 1.f);
    for (int k = threadIdx.x; k < Hn; k += blockDim.x)
        d_omean[(size_t)b * Hn + k] = ssum[k] / denom;
}

// ---------------- mixed audio slot only (m=1) ----------------
__global__ void k_mixed_audio(const float* tokens, const float* lnw, const float* lnb) {
    int b = blockIdx.x;
    const float* tok = tokens + (size_t)b * Mn * Hn;
    int m0 = d_mask[b * 4], m1 = d_mask[b * 4 + 1], m2 = d_mask[b * 4 + 2], m3 = d_mask[b * 4 + 3];
    int aum = m1 && (m0 || m2 || m3);
    if (aum) {
        __shared__ float sx[Hn];
        float g = d_gavec[b];
        float s = 0.f, q = 0.f;
        for (int k = threadIdx.x; k < Hn; k += blockDim.x) {
            float x = tok[Hn + k] + g * d_o2a[(size_t)b * Hn + k];
            sx[k] = x; s += x; q += x * x;
        }
        float2 rr = blkSum2(s, q);
        float mean = rr.x / Hn;
        float var = rr.y / Hn - mean * mean;
        float rstd = rsqrtf(var + 1e-5f);
        for (int k = threadIdx.x; k < Hn; k += blockDim.x)
            split_store(1, b, k, (sx[k] - mean) * rstd * lnw[k] + lnb[k]);
    } else {
        float f = m1 ? 1.0f : 0.0f;
        for (int k = threadIdx.x; k < Hn; k += blockDim.x)
            split_store(1, b, k, tok[Hn + k] * f);
    }
}

// ---------------- rank product + weighted sum + LN (fused) ----------------
__global__ void k_combine_ln(const float* rank_w, const float* lmf_bias,
                             const float* __restrict__ factors,
                             const float* lnw, const float* lnb) {
    int b = blockIdx.x;
    const unsigned char* mk = d_mask + b * 4;
    bool m0 = mk[0], m1 = mk[1], m2 = mk[2], m3 = mk[3];
    __shared__ float sx[Hn];
    float s = 0.f, q = 0.f;
    for (int h = threadIdx.x; h < Hn; h += blockDim.x) {
        const float* zb = d_zbuf + (size_t)b * (Mn * Rn * Hn) + h;
        float acc = 0.f;
#pragma unroll
        for (int r = 0; r < Rn; r++) {
            float p = rank_w[r];
            if (m0) p *= zb[(0 * Rn + r) * Hn] + factors[((size_t)(0 * Rn + r) * 1025) * Hn + h];
            if (m1) p *= zb[(1 * Rn + r) * Hn] + factors[((size_t)(1 * Rn + r) * 1025) * Hn + h];
            if (m2) p *= zb[(2 * Rn + r) * Hn] + factors[((size_t)(2 * Rn + r) * 1025) * Hn + h];
            if (m3) p *= zb[(3 * Rn + r) * Hn] + factors[((size_t)(3 * Rn + r) * 1025) * Hn + h];
            acc += p;
        }
        float v = acc + lmf_bias[h];
        sx[h] = v;
        s += v; q += v * v;
    }
    float2 rr = blkSum2(s, q);
    float mean = rr.x / Hn;
    float var = rr.y / Hn - mean * mean;
    float rstd = rsqrtf(var + 1e-5f);
    float* o = d_h1 + (size_t)b * Hn;
    for (int h = threadIdx.x; h < Hn; h += blockDim.x)
        o[h] = (sx[h] - mean) * rstd * lnw[h] + lnb[h];
}

// ---------------- final LayerNorm ----------------
__global__ void k_ln_out(const float* w, const float* bb, float* out) {
    const float* x = d_h2 + (size_t)blockIdx.x * Hn;
    float* y = out + (size_t)blockIdx.x * Hn;
    float s = 0.f, q = 0.f;
    for (int k = threadIdx.x; k < Hn; k += blockDim.x) { float v = x[k]; s += v; q += v * v; }
    float2 rr = blkSum2(s, q);
    float mean = rr.x / Hn;
    float var = rr.y / Hn - mean * mean;
    float rstd = rsqrtf(var + 1e-5f);
    for (int k = threadIdx.x; k < Hn; k += blockDim.x)
        y[k] = (x[k] - mean) * rstd * w[k] + bb[k];
}

// ---------------- launch ----------------
extern "C" void kernel_launch(void* const* d_in, const int* in_sizes, int n_in,
                              void* d_out, int out_size) {
    const float* tokens   = (const float*)d_in[0];
    const void*  maskraw  = d_in[1];
    const float* ln_go_w  = (const float*)d_in[2];
    const float* ln_go_b  = (const float*)d_in[3];
    const float* go_w1    = (const float*)d_in[4];
    const float* go_b1    = (const float*)d_in[5];
    const float* go_w2    = (const float*)d_in[6];
    const float* go_b2    = (const float*)d_in[7];
    const float* ln_ga_w  = (const float*)d_in[8];
    const float* ln_ga_b  = (const float*)d_in[9];
    const float* ga_w1    = (const float*)d_in[10];
    const float* ga_b1    = (const float*)d_in[11];
    const float* ga_w2    = (const float*)d_in[12];
    const float* ga_b2    = (const float*)d_in[13];
    const float* a2o_w    = (const float*)d_in[14];
    const float* o2a_w    = (const float*)d_in[15];
    const float* ln_o_w   = (const float*)d_in[16];
    const float* ln_o_b   = (const float*)d_in[17];
    const float* ln_a_w   = (const float*)d_in[18];
    const float* ln_a_b   = (const float*)d_in[19];
    const float* factors  = (const float*)d_in[20];
    const float* rank_w   = (const float*)d_in[21];
    const float* lmf_bias = (const float*)d_in[22];
    const float* out_ln1w = (const float*)d_in[23];
    const float* out_ln1b = (const float*)d_in[24];
    const float* out_w    = (const float*)d_in[25];
    const float* out_b    = (const float*)d_in[26];
    const float* out_ln2w = (const float*)d_in[27];
    const float* out_ln2b = (const float*)d_in[28];
    float* out = (float*)d_out;

    static cudaStream_t s1 = nullptr, s2 = nullptr;
    static cudaEvent_t evStart, evPF, evCmp, evA2O, evOM, evO2A;
    if (!s1) {
        cudaFuncSetAttribute(k_gemm_z_mma, cudaFuncAttributeMaxDynamicSharedMemorySize, ZSM_TOTAL);
        cudaFuncSetAttribute(k_sp_hidgo, cudaFuncAttributeMaxDynamicSharedMemorySize, GSM_TOTAL);
        cudaFuncSetAttribute(k_sp_hidga, cudaFuncAttributeMaxDynamicSharedMemorySize, GSM_TOTAL);
        cudaFuncSetAttribute(k_sp_a2o,   cudaFuncAttributeMaxDynamicSharedMemorySize, GSM_TOTAL);
        cudaFuncSetAttribute(k_sp_o2a,   cudaFuncAttributeMaxDynamicSharedMemorySize, GSM_TOTAL);
        cudaFuncSetAttribute(k_sp_out,   cudaFuncAttributeMaxDynamicSharedMemorySize, GSM_TOTAL);
        cudaStreamCreateWithFlags(&s1, cudaStreamNonBlocking);
        cudaStreamCreateWithFlags(&s2, cudaStreamNonBlocking);
        cudaEventCreateWithFlags(&evStart, cudaEventDisableTiming);
        cudaEventCreateWithFlags(&evPF,    cudaEventDisableTiming);
        cudaEventCreateWithFlags(&evCmp,   cudaEventDisableTiming);
        cudaEventCreateWithFlags(&evA2O,   cudaEventDisableTiming);
        cudaEventCreateWithFlags(&evOM,    cudaEventDisableTiming);
        cudaEventCreateWithFlags(&evO2A,   cudaEventDisableTiming);
    }

    cudaEventRecord(evStart, 0);
    cudaStreamWaitEvent(s1, evStart, 0);
    k_prep_factors<<<dim3(32, 32, Mn * Rn), dim3(32, 8), 0, s1>>>(factors);
    cudaEventRecord(evPF, s1);

    k_mask_compact<<<6, 1024>>>(maskraw);
    cudaEventRecord(evCmp, 0);

    cudaStreamWaitEvent(s2, evCmp, 0);
    k_sp_a2o<<<dim3(Hn / 128, Bn / 128), 512, GSM_TOTAL, s2>>>(tokens, a2o_w);
    cudaEventRecord(evA2O, s2);

    k_feat_go<<<3 * Bn, 256>>>(tokens, ln_go_w, ln_go_b);
    k_sp_hidgo<<<dim3(MIDn / 128, 3 * Bn / 128), 512, GSM_TOTAL>>>(go_w1, go_b1);
    k_gate_go<<<3 * Bn, 256>>>(go_w2, go_b2);
    cudaStreamWaitEvent(0, evA2O, 0);
    k_others_omean<<<Bn, 256>>>(tokens, ln_o_w, ln_o_b);
    cudaEventRecord(evOM, 0);

    // s1: o2a after omean (concurrent with feat_ga/hidga on stream 0)
    cudaStreamWaitEvent(s1, evOM, 0);
    k_sp_o2a<<<dim3(Hn / 128, Bn / 128), 512, GSM_TOTAL, s1>>>(o2a_w);
    cudaEventRecord(evO2A, s1);

    k_feat_ga<<<Bn, 256>>>(tokens, ln_ga_w, ln_ga_b);
    k_sp_hidga<<<dim3(MIDn / 128, Bn / 128), 512, GSM_TOTAL>>>(ga_w1, ga_b1);
    k_gate_ga<<<Bn, 256>>>(ga_w2, ga_b2);
    cudaStreamWaitEvent(0, evO2A, 0);
    k_mixed_audio<<<Bn, 256>>>(tokens, ln_a_w, ln_a_b);

    cudaStreamWaitEvent(0, evPF, 0);
    k_gemm_z_mma<<<dim3(Hn / 256, Bn / 128, Mn * Rn), 512, ZSM_TOTAL>>>();
    k_combine_ln<<<Bn, 256>>>(rank_w, lmf_bias, factors, out_ln1w, out_ln1b);
    k_sp_out<<<dim3(Hn / 128, Bn / 128), 512, GSM_TOTAL>>>(out_w, out_b);
    k_ln_out<<<Bn, 256>>>(out_ln2w, out_ln2b, out);
}

// round 16
// speedup vs baseline: 1.1106x; 1.0069x over previous
#include <cuda_runtime.h>
#include <cuda_bf16.h>
#include <math.h>
#include <cstdint>

#define Bn   4096
#define Mn   4
#define Hn   1024
#define Rn   10
#define MIDn 512
#define D3n  3072

// ---------------- scratch (__device__ globals: alloc-free) ----------------
__device__ float d_featgo[3 * Bn * D3n];
__device__ float d_gdot_go[3 * Bn];
__device__ float d_gdot_ga[Bn];
__device__ float d_ggo[3 * Bn];
__device__ float d_a2o[Bn * Hn];
__device__ float d_omean[Bn * Hn];
__device__ float d_featga[Bn * D3n];
__device__ float d_gavec[Bn];
__device__ float d_o2a[Bn * Hn];
__device__ float d_zbuf[167772160];             // B*M*R*H fp32
__device__ float d_h1[Bn * Hn];
__device__ float d_h2[Bn * Hn];
__device__ unsigned char d_mask[Bn * Mn];
__device__ int d_cidx[Mn * Bn];
__device__ int d_ccnt[Mn];
__device__ int d_pvidx[3 * Bn];
__device__ int d_pvcnt;
__device__ int d_aumidx[Bn];
__device__ int d_aumcnt;
__device__ __nv_bfloat16 d_ahi[Mn * Bn * Hn];      // [m][b][h]
__device__ __nv_bfloat16 d_alo[Mn * Bn * Hn];
__device__ __nv_bfloat16 d_fhi[Mn * Rn * Hn * Hn]; // [mr][h][d]
__device__ __nv_bfloat16 d_flo[Mn * Rn * Hn * Hn];

// ---------------- generic helpers ----------------
__device__ __forceinline__ float gelu_f(float x) {
    return 0.5f * x * (1.0f + erff(x * 0.70710678118654752f));
}
__device__ __forceinline__ float2 blkSum2(float a, float b) {
    __shared__ float sa[32], sb[32];
    __shared__ float ra, rb;
    int lane = threadIdx.x & 31, w = threadIdx.x >> 5;
#pragma unroll
    for (int o = 16; o > 0; o >>= 1) {
        a += __shfl_xor_sync(0xffffffffu, a, o);
        b += __shfl_xor_sync(0xffffffffu, b, o);
    }
    if (lane == 0) { sa[w] = a; sb[w] = b; }
    __syncthreads();
    if (threadIdx.x == 0) {
        float x = 0.f, y = 0.f;
        int nw = blockDim.x >> 5;
        for (int i = 0; i < nw; i++) { x += sa[i]; y += sb[i]; }
        ra = x; rb = y;
    }
    __syncthreads();
    return make_float2(ra, rb);
}
__device__ __forceinline__ void split_store(int m, int b, int k, float v) {
    __nv_bfloat16 hi = __float2bfloat16(v);
    float lo = v - __bfloat162float(hi);
    size_t o = ((size_t)m * Bn + b) * Hn + k;
    d_ahi[o] = hi;
    d_alo[o] = __float2bfloat16(lo);
}

// ---------------- mma.sync helpers ----------------
__device__ __forceinline__ uint32_t smem_u32(const void* p) {
    uint32_t a;
    asm("{ .reg .u64 t; cvta.to.shared.u64 t, %1; cvt.u32.u64 %0, t; }" : "=r"(a) : "l"(p));
    return a;
}
__device__ __forceinline__ void ldm_x4(uint32_t& r0, uint32_t& r1, uint32_t& r2, uint32_t& r3,
                                       uint32_t addr) {
    asm volatile("ldmatrix.sync.aligned.m8n8.x4.shared.b16 {%0,%1,%2,%3}, [%4];"
                 : "=r"(r0), "=r"(r1), "=r"(r2), "=r"(r3) : "r"(addr));
}
__device__ __forceinline__ void mma_bf16(float* c, const uint32_t* a, const uint32_t* b) {
    asm volatile("mma.sync.aligned.m16n8k16.row.col.f32.bf16.bf16.f32 "
                 "{%0,%1,%2,%3}, {%4,%5,%6,%7}, {%8,%9}, {%0,%1,%2,%3};"
                 : "+f"(c[0]), "+f"(c[1]), "+f"(c[2]), "+f"(c[3])
                 : "r"(a[0]), "r"(a[1]), "r"(a[2]), "r"(a[3]), "r"(b[0]), "r"(b[1]));
}
__device__ __forceinline__ void cp16(uint32_t dst, const void* src) {
    asm volatile("cp.async.cg.shared.global [%0], [%1], 16;" :: "r"(dst), "l"(src));
}
#define CP_COMMIT() asm volatile("cp.async.commit_group;" ::: "memory")
#define CP_WAIT(n)  asm volatile("cp.async.wait_group %0;" :: "n"(n) : "memory")

__device__ __forceinline__ uint32_t pack_hi_lo(float x, float y, uint32_t& lo) {
    __nv_bfloat16 hx = __float2bfloat16(x);
    __nv_bfloat16 hy = __float2bfloat16(y);
    float lxf = x - __bfloat162float(hx);
    float lyf = y - __bfloat162float(hy);
    __nv_bfloat162 hv = __halves2bfloat162(hx, hy);
    __nv_bfloat162 lv = __halves2bfloat162(__float2bfloat16(lxf), __float2bfloat16(lyf));
    lo = *reinterpret_cast<uint32_t*>(&lv);
    return *reinterpret_cast<uint32_t*>(&hv);
}

// ---------------- fused mask sniff + all compactions (6 blocks) ----------------
__global__ void __launch_bounds__(1024) k_mask_compact(const void* raw) {
    __shared__ int ok32s, okfs;
    if (threadIdx.x == 0) { ok32s = 1; okfs = 1; }
    __syncthreads();
    const int* pi = (const int*)raw;
    const float* pf = (const float*)raw;
    const unsigned char* pb = (const unsigned char*)raw;
    int lok32 = 1, lokf = 1;
    for (int i = threadIdx.x; i < 4096; i += 1024) {
        int v = pi[i];
        if (v != 0 && v != 1) lok32 = 0;
        float f = pf[i];
        if (f != 0.0f && f != 1.0f) lokf = 0;
    }
    if (!lok32) ok32s = 0;
    if (!lokf)  okfs = 0;
    __syncthreads();
    const int ok32 = ok32s, okf = okfs;
    auto maskat = [&](int i) -> int {
        if (ok32) return pi[i] != 0;
        if (okf)  return pf[i] != 0.0f;
        return pb[i] != 0;
    };

    const int blk = blockIdx.x;
    if (blk == 0) {
        for (int i = threadIdx.x; i < Bn * Mn; i += 1024)
            d_mask[i] = (unsigned char)maskat(i);
        for (int i = threadIdx.x; i < 3 * Bn; i += 1024) d_gdot_go[i] = 0.0f;
        for (int i = threadIdx.x; i < Bn; i += 1024)     d_gdot_ga[i] = 0.0f;
    }

    int* out_idx;
    int* out_cnt;
    int nitems;
    if (blk < 4)      { out_idx = d_cidx + blk * Bn; out_cnt = d_ccnt + blk; nitems = Bn; }
    else if (blk == 4){ out_idx = d_pvidx;           out_cnt = &d_pvcnt;     nitems = 3 * Bn; }
    else              { out_idx = d_aumidx;          out_cnt = &d_aumcnt;    nitems = Bn; }

    __shared__ int warp_off[32];
    __shared__ int chunk_base;
    if (threadIdx.x == 0) chunk_base = 0;
    __syncthreads();
    int lane = threadIdx.x & 31, w = threadIdx.x >> 5;
    for (int c = 0; c < nitems; c += 1024) {
        int i = c + threadIdx.x;
        int v;
        if (blk < 4) {
            v = maskat(i * Mn + blk);
        } else if (blk == 4) {
            int b = i / 3, j = i - 3 * b;
            int oj = (j == 0) ? 0 : (j + 1);
            v = maskat(b * 4 + oj) && maskat(b * 4 + 1);
        } else {
            v = maskat(i * 4 + 1) && (maskat(i * 4) | maskat(i * 4 + 2) | maskat(i * 4 + 3));
        }
        unsigned bal = __ballot_sync(0xffffffffu, v);
        int pre = __popc(bal & ((1u << lane) - 1u));
        if (lane == 31) warp_off[w] = __popc(bal);
        __syncthreads();
        if (threadIdx.x < 32) {
            int val = warp_off[threadIdx.x];
#pragma unroll
            for (int o = 1; o < 32; o <<= 1) {
                int t = __shfl_up_sync(0xffffffffu, val, o);
                if ((int)threadIdx.x >= o) val += t;
            }
            warp_off[threadIdx.x] = val;
        }
        __syncthreads();
        int base = chunk_base + (w ? warp_off[w - 1] : 0) + pre;
        if (v) out_idx[base] = i;
        __syncthreads();
        if (threadIdx.x == 0) chunk_base += warp_off[31];
        __syncthreads();
    }
    if (threadIdx.x == 0) *out_cnt = chunk_base;
}

// ---------------- generic fp32 -> bf16-split mma GEMM (512 thr, 16 warps) ----------------
// GATE != 0: instead of storing C, dot gelu(acc+bias) with w2 and atomicAdd into gdot[row].
#define GPAD   40
#define GBUF   (128 * GPAD * 2)
#define GSTAGE (4 * GBUF)
#define GSM_TOTAL (2 * GSTAGE)

template <int SEL, int GATE>
__device__ __forceinline__ void gemm_sp_body(
    const float* __restrict__ A, int lda,
    const float* __restrict__ B, int ldb,
    float* __restrict__ C, int ldc,
    const float* __restrict__ bias, int K, int act,
    const float* __restrict__ w2gate, float* __restrict__ gdot)
{
    extern __shared__ char gsm[];
    int cnt = 1 << 30;
    const int* ridx = nullptr;
    if (SEL == 1) cnt = d_pvcnt;
    if (SEL == 2) cnt = d_aumcnt;
    if (SEL == 3) { cnt = d_aumcnt; ridx = d_aumidx; }
    const int n0 = blockIdx.x * 128, m0 = blockIdx.y * 128;
    if (SEL != 0 && m0 >= cnt) return;

    const uint32_t sbase = smem_u32(gsm);
    const int tid = threadIdx.x;
    const int wid = tid >> 5, lane = tid & 31;

    const int lrow = tid >> 2, lseg = tid & 3;
    int grow = m0 + lrow;
    if (SEL != 0 && grow >= cnt) grow = cnt - 1;
    const int arow = ridx ? ridx[grow] : grow;
    const float* Aref = A + (size_t)arow * lda + lseg * 8;
    const float* Bref = B + (size_t)(n0 + lrow) * ldb + lseg * 8;

    float4 ra[2], rb[2];
    auto gload = [&](int k0) {
        ra[0] = *(const float4*)(Aref + k0);
        ra[1] = *(const float4*)(Aref + k0 + 4);
        rb[0] = *(const float4*)(Bref + k0);
        rb[1] = *(const float4*)(Bref + k0 + 4);
    };
    auto sstore = [&](int st) {
        char* p = gsm + st * GSTAGE + lrow * (GPAD * 2) + lseg * 16;
        uint32_t l0, l1, l2, l3;
        uint32_t h0 = pack_hi_lo(ra[0].x, ra[0].y, l0);
        uint32_t h1 = pack_hi_lo(ra[0].z, ra[0].w, l1);
        uint32_t h2 = pack_hi_lo(ra[1].x, ra[1].y, l2);
        uint32_t h3 = pack_hi_lo(ra[1].z, ra[1].w, l3);
        *(uint4*)(p + 0 * GBUF) = make_uint4(h0, h1, h2, h3);
        *(uint4*)(p + 1 * GBUF) = make_uint4(l0, l1, l2, l3);
        h0 = pack_hi_lo(rb[0].x, rb[0].y, l0);
        h1 = pack_hi_lo(rb[0].z, rb[0].w, l1);
        h2 = pack_hi_lo(rb[1].x, rb[1].y, l2);
        h3 = pack_hi_lo(rb[1].z, rb[1].w, l3);
        *(uint4*)(p + 2 * GBUF) = make_uint4(h0, h1, h2, h3);
        *(uint4*)(p + 3 * GBUF) = make_uint4(l0, l1, l2, l3);
    };

    float acc[2][4][4];
#pragma unroll
    for (int i = 0; i < 2; i++)
#pragma unroll
        for (int j = 0; j < 4; j++)
#pragma unroll
            for (int c = 0; c < 4; c++) acc[i][j][c] = 0.0f;

    const int wm0 = (wid >> 2) * 32;
    const int wn0 = (wid & 3) * 32;
    const int a_r = lane & 15;
    const int a_c8 = (lane >> 4) << 3;
    const int b_r = (lane & 7) + ((lane >> 4) << 3);
    const int b_c8 = ((lane >> 3) & 1) << 3;

    gload(0);
    const int NIT = K / 32;
    for (int it = 0; it < NIT; it++) {
        const int st = it & 1;
        sstore(st);
        __syncthreads();
        if (it + 1 < NIT) gload((it + 1) * 32);

        const uint32_t sAh = sbase + st * GSTAGE + 0 * GBUF;
        const uint32_t sAl = sbase + st * GSTAGE + 1 * GBUF;
        const uint32_t sBh = sbase + st * GSTAGE + 2 * GBUF;
        const uint32_t sBl = sbase + st * GSTAGE + 3 * GBUF;
#pragma unroll
        for (int ks = 0; ks < 2; ks++) {
            const int kb = ks * 16;
            uint32_t aH[2][4], aL[2][4], bH[4][2], bL[4][2];
#pragma unroll
            for (int mi = 0; mi < 2; mi++) {
                uint32_t off = (uint32_t)(wm0 + mi * 16 + a_r) * (GPAD * 2) + (kb + a_c8) * 2;
                ldm_x4(aH[mi][0], aH[mi][1], aH[mi][2], aH[mi][3], sAh + off);
                ldm_x4(aL[mi][0], aL[mi][1], aL[mi][2], aL[mi][3], sAl + off);
            }
#pragma unroll
            for (int p2 = 0; p2 < 2; p2++) {
                uint32_t off = (uint32_t)(wn0 + p2 * 16 + b_r) * (GPAD * 2) + (kb + b_c8) * 2;
                ldm_x4(bH[2 * p2][0], bH[2 * p2][1], bH[2 * p2 + 1][0], bH[2 * p2 + 1][1], sBh + off);
                ldm_x4(bL[2 * p2][0], bL[2 * p2][1], bL[2 * p2 + 1][0], bL[2 * p2 + 1][1], sBl + off);
            }
#pragma unroll
            for (int mi = 0; mi < 2; mi++)
#pragma unroll
                for (int ni = 0; ni < 4; ni++)
                    mma_bf16(acc[mi][ni], aH[mi], bH[ni]);
#pragma unroll
            for (int mi = 0; mi < 2; mi++)
#pragma unroll
                for (int ni = 0; ni < 4; ni++)
                    mma_bf16(acc[mi][ni], aH[mi], bL[ni]);
#pragma unroll
            for (int mi = 0; mi < 2; mi++)
#pragma unroll
                for (int ni = 0; ni < 4; ni++)
                    mma_bf16(acc[mi][ni], aL[mi], bH[ni]);
        }
        __syncthreads();
    }

#pragma unroll
    for (int mi = 0; mi < 2; mi++) {
#pragma unroll
        for (int half = 0; half < 2; half++) {
            int r = m0 + wm0 + mi * 16 + (lane >> 2) + half * 8;
            bool valid = !(SEL != 0 && r >= cnt);
            if (GATE) {
                float part = 0.f;
#pragma unroll
                for (int ni = 0; ni < 4; ni++) {
                    int cc = n0 + wn0 + ni * 8 + (lane & 3) * 2;
                    float v0 = gelu_f(acc[mi][ni][half * 2 + 0] + bias[cc]);
                    float v1 = gelu_f(acc[mi][ni][half * 2 + 1] + bias[cc + 1]);
                    part += v0 * w2gate[cc] + v1 * w2gate[cc + 1];
                }
                part += __shfl_xor_sync(0xffffffffu, part, 1);
                part += __shfl_xor_sync(0xffffffffu, part, 2);
                if ((lane & 3) == 0 && valid) atomicAdd(&gdot[r], part);
            } else {
                if (!valid) continue;
                int crow = ridx ? ridx[r] : r;
                float* dd = C + (size_t)crow * ldc;
#pragma unroll
                for (int ni = 0; ni < 4; ni++) {
                    int cc = n0 + wn0 + ni * 8 + (lane & 3) * 2;
                    float v0 = acc[mi][ni][half * 2 + 0] + (bias ? bias[cc] : 0.f);
                    float v1 = acc[mi][ni][half * 2 + 1] + (bias ? bias[cc + 1] : 0.f);
                    if (act) { v0 = gelu_f(v0); v1 = gelu_f(v1); }
                    *(float2*)(dd + cc) = make_float2(v0, v1);
                }
            }
        }
    }
}

__global__ void __launch_bounds__(512) k_sp_hidgo(const float* w1, const float* b1, const float* w2) {
    gemm_sp_body<1, 1>(d_featgo, D3n, w1, D3n, nullptr, 0, b1, D3n, 1, w2, d_gdot_go);
}
__global__ void __launch_bounds__(512) k_sp_hidga(const float* w1, const float* b1, const float* w2) {
    gemm_sp_body<2, 1>(d_featga, D3n, w1, D3n, nullptr, 0, b1, D3n, 1, w2, d_gdot_ga);
}
__global__ void __launch_bounds__(512) k_sp_a2o(const float* tokens, const float* w) {
    gemm_sp_body<3, 0>(tokens + Hn, Mn * Hn, w, Hn, d_a2o, Hn, (const float*)0, Hn, 0, nullptr, nullptr);
}
__global__ void __launch_bounds__(512) k_sp_o2a(const float* w) {
    gemm_sp_body<3, 0>(d_omean, Hn, w, Hn, d_o2a, Hn, (const float*)0, Hn, 0, nullptr, nullptr);
}
__global__ void __launch_bounds__(512) k_sp_out(const float* w, const float* bb) {
    gemm_sp_body<0, 0>(d_h1, Hn, w, Hn, d_h2, Hn, bb, Hn, 1, nullptr, nullptr);
}

// ---------------- gate sigmoid finishers ----------------
__global__ void k_gate_fin_go(const float* b2) {
    int i = blockIdx.x * 256 + threadIdx.x;
    if (i >= d_pvcnt) return;
    d_ggo[d_pvidx[i]] = 1.0f / (1.0f + expf(-(d_gdot_go[i] + b2[0])));
}
__global__ void k_gate_fin_ga(const float* b2) {
    int i = blockIdx.x * 256 + threadIdx.x;
    if (i >= d_aumcnt) return;
    d_gavec[d_aumidx[i]] = 1.0f / (1.0f + expf(-(d_gdot_ga[i] + b2[0])));
}

// ---------------- factor split/transpose prep ----------------
__global__ void __launch_bounds__(256) k_prep_factors(const float* __restrict__ f) {
    __shared__ float t[32][33];
    int mr = blockIdx.z;
    int d0 = blockIdx.x * 32, h0 = blockIdx.y * 32;
    int tx = threadIdx.x, ty = threadIdx.y;
#pragma unroll
    for (int i = ty; i < 32; i += 8)
        t[i][tx] = f[((size_t)mr * 1025 + 1 + d0 + i) * Hn + h0 + tx];
    __syncthreads();
#pragma unroll
    for (int i = ty; i < 32; i += 8) {
        float x = t[tx][i];
        __nv_bfloat16 hi = __float2bfloat16(x);
        float lo = x - __bfloat162float(hi);
        size_t o = ((size_t)mr * Hn + h0 + i) * Hn + d0 + tx;
        d_fhi[o] = hi;
        d_flo[o] = __float2bfloat16(lo);
    }
}

// ---------------- LMF GEMM: block 128x256, 16 warps, warp 32x64, 3-stage ----------------
#define ZKC     32
#define ZPAD    40
#define ZA_ROWS 128
#define ZB_ROWS 256
#define ZABUF   (ZA_ROWS * ZPAD * 2)
#define ZBBUF   (ZB_ROWS * ZPAD * 2)
#define ZSTAGE  (2 * ZABUF + 2 * ZBBUF)
#define ZSM_TOTAL (3 * ZSTAGE)

__global__ void __launch_bounds__(512) k_gemm_z_mma() {
    extern __shared__ char zsm[];
    const uint32_t sbase = smem_u32(zsm);
    const int tid = threadIdx.x;
    const int wid = tid >> 5, lane = tid & 31;
    const int h0 = blockIdx.x * 256;
    const int b0 = blockIdx.y * 128;
    const int mr = blockIdx.z;
    const int m = mr / Rn;
    const int cnt = d_ccnt[m];
    if (b0 >= cnt) return;

    const int lrow = tid >> 2;
    const int lseg = tid & 3;

    int grow = b0 + lrow;
    int gidx = d_cidx[m * Bn + (grow < cnt ? grow : cnt - 1)];

    const __nv_bfloat16* pAhi = d_ahi + ((size_t)m * Bn + gidx) * Hn + lseg * 8;
    const __nv_bfloat16* pAlo = d_alo + ((size_t)m * Bn + gidx) * Hn + lseg * 8;
    const __nv_bfloat16* pB0hi = d_fhi + ((size_t)mr * Hn + h0 + lrow) * Hn + lseg * 8;
    const __nv_bfloat16* pB0lo = d_flo + ((size_t)mr * Hn + h0 + lrow) * Hn + lseg * 8;
    const __nv_bfloat16* pB1hi = pB0hi + (size_t)128 * Hn;
    const __nv_bfloat16* pB1lo = pB0lo + (size_t)128 * Hn;

    auto load_stage = [&](int st, int k0) {
        uint32_t base = sbase + st * ZSTAGE;
        uint32_t offA = lrow * (ZPAD * 2) + lseg * 16;
        cp16(base + offA, pAhi + k0);
        cp16(base + ZABUF + offA, pAlo + k0);
        uint32_t offB0 = lrow * (ZPAD * 2) + lseg * 16;
        uint32_t offB1 = (lrow + 128) * (ZPAD * 2) + lseg * 16;
        cp16(base + 2 * ZABUF + offB0, pB0hi + k0);
        cp16(base + 2 * ZABUF + offB1, pB1hi + k0);
        cp16(base + 2 * ZABUF + ZBBUF + offB0, pB0lo + k0);
        cp16(base + 2 * ZABUF + ZBBUF + offB1, pB1lo + k0);
    };

    float acc[2][8][4];
#pragma unroll
    for (int i = 0; i < 2; i++)
#pragma unroll
        for (int j = 0; j < 8; j++)
#pragma unroll
            for (int c = 0; c < 4; c++) acc[i][j][c] = 0.0f;

    const int wm0 = (wid >> 2) * 32;
    const int wn0 = (wid & 3) * 64;
    const int a_r = lane & 15;
    const int a_c8 = (lane >> 4) << 3;
    const int b_r = (lane & 7) + ((lane >> 4) << 3);
    const int b_c8 = ((lane >> 3) & 1) << 3;

    load_stage(0, 0);
    CP_COMMIT();
    load_stage(1, ZKC);
    CP_COMMIT();

    const int NIT = Hn / ZKC;
    for (int it = 0; it < NIT; it++) {
        CP_WAIT(1);
        __syncthreads();
        if (it + 2 < NIT) {
            load_stage((it + 2) % 3, (it + 2) * ZKC);
            CP_COMMIT();
        }
        const int st = it % 3;
        const uint32_t sAh = sbase + st * ZSTAGE;
        const uint32_t sAl = sAh + ZABUF;
        const uint32_t sBh = sAh + 2 * ZABUF;
        const uint32_t sBl = sBh + ZBBUF;

#pragma unroll
        for (int ks = 0; ks < 2; ks++) {
            const int kb = ks * 16;
            uint32_t aH[2][4], aL[2][4];
#pragma unroll
            for (int mi = 0; mi < 2; mi++) {
                uint32_t off = (uint32_t)(wm0 + mi * 16 + a_r) * (ZPAD * 2) + (kb + a_c8) * 2;
                ldm_x4(aH[mi][0], aH[mi][1], aH[mi][2], aH[mi][3], sAh + off);
                ldm_x4(aL[mi][0], aL[mi][1], aL[mi][2], aL[mi][3], sAl + off);
            }
#pragma unroll
            for (int hf = 0; hf < 2; hf++) {
                uint32_t bH[4][2], bL[4][2];
#pragma unroll
                for (int p = 0; p < 2; p++) {
                    uint32_t off = (uint32_t)(wn0 + hf * 32 + p * 16 + b_r) * (ZPAD * 2) + (kb + b_c8) * 2;
                    ldm_x4(bH[2 * p][0], bH[2 * p][1], bH[2 * p + 1][0], bH[2 * p + 1][1], sBh + off);
                    ldm_x4(bL[2 * p][0], bL[2 * p][1], bL[2 * p + 1][0], bL[2 * p + 1][1], sBl + off);
                }
#pragma unroll
                for (int mi = 0; mi < 2; mi++)
#pragma unroll
                    for (int ni = 0; ni < 4; ni++)
                        mma_bf16(acc[mi][hf * 4 + ni], aH[mi], bH[ni]);
#pragma unroll
                for (int mi = 0; mi < 2; mi++)
#pragma unroll
                    for (int ni = 0; ni < 4; ni++)
                        mma_bf16(acc[mi][hf * 4 + ni], aH[mi], bL[ni]);
#pragma unroll
                for (int mi = 0; mi < 2; mi++)
#pragma unroll
                    for (int ni = 0; ni < 4; ni++)
                        mma_bf16(acc[mi][hf * 4 + ni], aL[mi], bH[ni]);
            }
        }
    }

#pragma unroll
    for (int mi = 0; mi < 2; mi++) {
#pragma unroll
        for (int half = 0; half < 2; half++) {
            int r = b0 + wm0 + mi * 16 + (lane >> 2) + half * 8;
            if (r >= cnt) continue;
            int br = d_cidx[m * Bn + r];
            float* dd = d_zbuf + ((size_t)br * (Mn * Rn) + mr) * Hn + h0;
#pragma unroll
            for (int ni = 0; ni < 8; ni++) {
                int cc = wn0 + ni * 8 + (lane & 3) * 2;
                *(float2*)(dd + cc) = make_float2(acc[mi][ni][half * 2 + 0], acc[mi][ni][half * 2 + 1]);
            }
        }
    }
}

// ---------------- feat builders (compacted) ----------------
__global__ void k_feat_go(const float* tokens, const float* lnw, const float* lnb) {
    int i = blockIdx.x;
    if (i >= d_pvcnt) return;
    int row = d_pvidx[i];
    int b = row / 3, j = row - 3 * b;
    int oj = (j == 0) ? 0 : (j + 1);
    const float* tok = tokens + (size_t)b * Mn * Hn;
    __shared__ float sf[D3n];
    float s = 0.f, q = 0.f;
    for (int k = threadIdx.x; k < Hn; k += blockDim.x) {
        float t = tok[oj * Hn + k];
        float sv = tok[Hn + k];
        float dv = fabsf(t - sv);
        sf[k] = t; sf[Hn + k] = sv; sf[2 * Hn + k] = dv;
        s += t + sv + dv; q += t * t + sv * sv + dv * dv;
    }
    float2 rr = blkSum2(s, q);
    float mean = rr.x / D3n;
    float var = rr.y / D3n - mean * mean;
    float rstd = rsqrtf(var + 1e-5f);
    float* o = d_featgo + (size_t)i * D3n;
    for (int k = threadIdx.x; k < D3n; k += blockDim.x)
        o[k] = (sf[k] - mean) * rstd * lnw[k] + lnb[k];
}

__global__ void k_feat_ga(const float* tokens, const float* lnw, const float* lnb) {
    int i = blockIdx.x;
    if (i >= d_aumcnt) return;
    int b = d_aumidx[i];
    const float* tok = tokens + (size_t)b * Mn * Hn;
    __shared__ float sf[D3n];
    float s = 0.f, q = 0.f;
    for (int k = threadIdx.x; k < Hn; k += blockDim.x) {
        float t = tok[Hn + k];
        float sv = d_omean[(size_t)b * Hn + k];
        float dv = fabsf(t - sv);
        sf[k] = t; sf[Hn + k] = sv; sf[2 * Hn + k] = dv;
        s += t + sv + dv; q += t * t + sv * sv + dv * dv;
    }
    float2 rr = blkSum2(s, q);
    float mean = rr.x / D3n;
    float var = rr.y / D3n - mean * mean;
    float rstd = rsqrtf(var + 1e-5f);
    float* o = d_featga + (size_t)i * D3n;
    for (int k = threadIdx.x; k < D3n; k += blockDim.x)
        o[k] = (sf[k] - mean) * rstd * lnw[k] + lnb[k];
}

// ---------------- others_new + omean + split of m=0,2,3 mixed slots (fused) ----------------
__global__ void k_others_omean(const float* tokens, const float* lnw, const float* lnb) {
    int b = blockIdx.x;
    const float* tok = tokens + (size_t)b * Mn * Hn;
    int ma = d_mask[b * 4 + 1];
    __shared__ float srow[Hn];
    __shared__ float ssum[Hn];
    for (int k = threadIdx.x; k < Hn; k += blockDim.x) ssum[k] = 0.f;
    float denom = 0.f;
    for (int j = 0; j < 3; j++) {
        int oj = (j == 0) ? 0 : (j + 1);
        int moj = d_mask[b * 4 + oj];
        if (moj && ma) {
            float g = d_ggo[b * 3 + j];
            float s = 0.f, q = 0.f;
            for (int k = threadIdx.x; k < Hn; k += blockDim.x) {
                float x = tok[oj * Hn + k] + g * d_a2o[(size_t)b * Hn + k];
                srow[k] = x; s += x; q += x * x;
            }
            float2 rr = blkSum2(s, q);
            float mean = rr.x / Hn;
            float var = rr.y / Hn - mean * mean;
            float rstd = rsqrtf(var + 1e-5f);
            for (int k = threadIdx.x; k < Hn; k += blockDim.x) {
                float v = (srow[k] - mean) * rstd * lnw[k] + lnb[k];
                split_store(oj, b, k, v);
                ssum[k] += v;
            }
        } else if (moj) {
            for (int k = threadIdx.x; k < Hn; k += blockDim.x) {
                float v = tok[oj * Hn + k];
                split_store(oj, b, k, v);
                ssum[k] += v;
            }
        } else {
            for (int k = threadIdx.x; k < Hn; k += blockDim.x)
                split_store(oj, b, k, 0.0f);
        }
        if (moj) denom += 1.f;
    }
    denom = fmaxf(denom, 1.f);
    for (int k = threadIdx.x; k < Hn; k += blockDim.x)
        d_omean[(size_t)b * Hn + k] = ssum[k] / denom;
}

// ---------------- mixed audio slot only (m=1) ----------------
__global__ void k_mixed_audio(const float* tokens, const float* lnw, const float* lnb) {
    int b = blockIdx.x;
    const float* tok = tokens + (size_t)b * Mn * Hn;
    int m0 = d_mask[b * 4], m1 = d_mask[b * 4 + 1], m2 = d_mask[b * 4 + 2], m3 = d_mask[b * 4 + 3];
    int aum = m1 && (m0 || m2 || m3);
    if (aum) {
        __shared__ float sx[Hn];
        float g = d_gavec[b];
        float s = 0.f, q = 0.f;
        for (int k = threadIdx.x; k < Hn; k += blockDim.x) {
            float x = tok[Hn + k] + g * d_o2a[(size_t)b * Hn + k];
            sx[k] = x; s += x; q += x * x;
        }
        float2 rr = blkSum2(s, q);
        float mean = rr.x / Hn;
        float var = rr.y / Hn - mean * mean;
        float rstd = rsqrtf(var + 1e-5f);
        for (int k = threadIdx.x; k < Hn; k += blockDim.x)
            split_store(1, b, k, (sx[k] - mean) * rstd * lnw[k] + lnb[k]);
    } else {
        float f = m1 ? 1.0f : 0.0f;
        for (int k = threadIdx.x; k < Hn; k += blockDim.x)
            split_store(1, b, k, tok[Hn + k] * f);
    }
}

// ---------------- rank product + weighted sum + LN (fused) ----------------
__global__ void k_combine_ln(const float* rank_w, const float* lmf_bias,
                             const float* __restrict__ factors,
                             const float* lnw, const float* lnb) {
    int b = blockIdx.x;
    const unsigned char* mk = d_mask + b * 4;
    bool m0 = mk[0], m1 = mk[1], m2 = mk[2], m3 = mk[3];
    __shared__ float sx[Hn];
    float s = 0.f, q = 0.f;
    for (int h = threadIdx.x; h < Hn; h += blockDim.x) {
        const float* zb = d_zbuf + (size_t)b * (Mn * Rn * Hn) + h;
        float acc = 0.f;
#pragma unroll
        for (int r = 0; r < Rn; r++) {
            float p = rank_w[r];
            if (m0) p *= zb[(0 * Rn + r) * Hn] + factors[((size_t)(0 * Rn + r) * 1025) * Hn + h];
            if (m1) p *= zb[(1 * Rn + r) * Hn] + factors[((size_t)(1 * Rn + r) * 1025) * Hn + h];
            if (m2) p *= zb[(2 * Rn + r) * Hn] + factors[((size_t)(2 * Rn + r) * 1025) * Hn + h];
            if (m3) p *= zb[(3 * Rn + r) * Hn] + factors[((size_t)(3 * Rn + r) * 1025) * Hn + h];
            acc += p;
        }
        float v = acc + lmf_bias[h];
        sx[h] = v;
        s += v; q += v * v;
    }
    float2 rr = blkSum2(s, q);
    float mean = rr.x / Hn;
    float var = rr.y / Hn - mean * mean;
    float rstd = rsqrtf(var + 1e-5f);
    float* o = d_h1 + (size_t)b * Hn;
    for (int h = threadIdx.x; h < Hn; h += blockDim.x)
        o[h] = (sx[h] - mean) * rstd * lnw[h] + lnb[h];
}

// ---------------- final LayerNorm ----------------
__global__ void k_ln_out(const float* w, const float* bb, float* out) {
    const float* x = d_h2 + (size_t)blockIdx.x * Hn;
    float* y = out + (size_t)blockIdx.x * Hn;
    float s = 0.f, q = 0.f;
    for (int k = threadIdx.x; k < Hn; k += blockDim.x) { float v = x[k]; s += v; q += v * v; }
    float2 rr = blkSum2(s, q);
    float mean = rr.x / Hn;
    float var = rr.y / Hn - mean * mean;
    float rstd = rsqrtf(var + 1e-5f);
    for (int k = threadIdx.x; k < Hn; k += blockDim.x)
        y[k] = (x[k] - mean) * rstd * w[k] + bb[k];
}

// ---------------- launch ----------------
extern "C" void kernel_launch(void* const* d_in, const int* in_sizes, int n_in,
                              void* d_out, int out_size) {
    const float* tokens   = (const float*)d_in[0];
    const void*  maskraw  = d_in[1];
    const float* ln_go_w  = (const float*)d_in[2];
    const float* ln_go_b  = (const float*)d_in[3];
    const float* go_w1    = (const float*)d_in[4];
    const float* go_b1    = (const float*)d_in[5];
    const float* go_w2    = (const float*)d_in[6];
    const float* go_b2    = (const float*)d_in[7];
    const float* ln_ga_w  = (const float*)d_in[8];
    const float* ln_ga_b  = (const float*)d_in[9];
    const float* ga_w1    = (const float*)d_in[10];
    const float* ga_b1    = (const float*)d_in[11];
    const float* ga_w2    = (const float*)d_in[12];
    const float* ga_b2    = (const float*)d_in[13];
    const float* a2o_w    = (const float*)d_in[14];
    const float* o2a_w    = (const float*)d_in[15];
    const float* ln_o_w   = (const float*)d_in[16];
    const float* ln_o_b   = (const float*)d_in[17];
    const float* ln_a_w   = (const float*)d_in[18];
    const float* ln_a_b   = (const float*)d_in[19];
    const float* factors  = (const float*)d_in[20];
    const float* rank_w   = (const float*)d_in[21];
    const float* lmf_bias = (const float*)d_in[22];
    const float* out_ln1w = (const float*)d_in[23];
    const float* out_ln1b = (const float*)d_in[24];
    const float* out_w    = (const float*)d_in[25];
    const float* out_b    = (const float*)d_in[26];
    const float* out_ln2w = (const float*)d_in[27];
    const float* out_ln2b = (const float*)d_in[28];
    float* out = (float*)d_out;

    static cudaStream_t s1 = nullptr, s2 = nullptr;
    static cudaEvent_t evStart, evPF, evCmp, evA2O, evOM, evO2A;
    if (!s1) {
        cudaFuncSetAttribute(k_gemm_z_mma, cudaFuncAttributeMaxDynamicSharedMemorySize, ZSM_TOTAL);
        cudaFuncSetAttribute(k_sp_hidgo, cudaFuncAttributeMaxDynamicSharedMemorySize, GSM_TOTAL);
        cudaFuncSetAttribute(k_sp_hidga, cudaFuncAttributeMaxDynamicSharedMemorySize, GSM_TOTAL);
        cudaFuncSetAttribute(k_sp_a2o,   cudaFuncAttributeMaxDynamicSharedMemorySize, GSM_TOTAL);
        cudaFuncSetAttribute(k_sp_o2a,   cudaFuncAttributeMaxDynamicSharedMemorySize, GSM_TOTAL);
        cudaFuncSetAttribute(k_sp_out,   cudaFuncAttributeMaxDynamicSharedMemorySize, GSM_TOTAL);
        cudaStreamCreateWithFlags(&s1, cudaStreamNonBlocking);
        cudaStreamCreateWithFlags(&s2, cudaStreamNonBlocking);
        cudaEventCreateWithFlags(&evStart, cudaEventDisableTiming);
        cudaEventCreateWithFlags(&evPF,    cudaEventDisableTiming);
        cudaEventCreateWithFlags(&evCmp,   cudaEventDisableTiming);
        cudaEventCreateWithFlags(&evA2O,   cudaEventDisableTiming);
        cudaEventCreateWithFlags(&evOM,    cudaEventDisableTiming);
        cudaEventCreateWithFlags(&evO2A,   cudaEventDisableTiming);
    }

    cudaEventRecord(evStart, 0);
    cudaStreamWaitEvent(s1, evStart, 0);
    k_prep_factors<<<dim3(32, 32, Mn * Rn), dim3(32, 8), 0, s1>>>(factors);
    cudaEventRecord(evPF, s1);

    k_mask_compact<<<6, 1024>>>(maskraw);
    cudaEventRecord(evCmp, 0);

    cudaStreamWaitEvent(s2, evCmp, 0);
    k_sp_a2o<<<dim3(Hn / 128, Bn / 128), 512, GSM_TOTAL, s2>>>(tokens, a2o_w);
    cudaEventRecord(evA2O, s2);

    k_feat_go<<<3 * Bn, 256>>>(tokens, ln_go_w, ln_go_b);
    k_sp_hidgo<<<dim3(MIDn / 128, 3 * Bn / 128), 512, GSM_TOTAL>>>(go_w1, go_b1, go_w2);
    k_gate_fin_go<<<(3 * Bn + 255) / 256, 256>>>(go_b2);
    cudaStreamWaitEvent(0, evA2O, 0);
    k_others_omean<<<Bn, 256>>>(tokens, ln_o_w, ln_o_b);
    cudaEventRecord(evOM, 0);

    // s1: o2a after omean (concurrent with feat_ga/hidga on stream 0)
    cudaStreamWaitEvent(s1, evOM, 0);
    k_sp_o2a<<<dim3(Hn / 128, Bn / 128), 512, GSM_TOTAL, s1>>>(o2a_w);
    cudaEventRecord(evO2A, s1);

    k_feat_ga<<<Bn, 256>>>(tokens, ln_ga_w, ln_ga_b);
    k_sp_hidga<<<dim3(MIDn / 128, Bn / 128), 512, GSM_TOTAL>>>(ga_w1, ga_b1, ga_w2);
    k_gate_fin_ga<<<(Bn + 255) / 256, 256>>>(ga_b2);
    cudaStreamWaitEvent(0, evO2A, 0);
    k_mixed_audio<<<Bn, 256>>>(tokens, ln_a_w, ln_a_b);

    cudaStreamWaitEvent(0, evPF, 0);
    k_gemm_z_mma<<<dim3(Hn / 256, Bn / 128, Mn * Rn), 512, ZSM_TOTAL>>>();
    k_combine_ln<<<Bn, 256>>>(rank_w, lmf_bias, factors, out_ln1w, out_ln1b);
    k_sp_out<<<dim3(Hn / 128, Bn / 128), 512, GSM_TOTAL>>>(out_w, out_b);
    k_ln_out<<<Bn, 256>>>(out_ln2w, out_ln2b, out);
}